// round 3
// baseline (speedup 1.0000x reference)
#include <cuda_runtime.h>
#include <math.h>

// Problem constants
#define NLAYERS 12
#define BATCH   8
#define SEQ     512
#define HID     768
#define NHEAD   12
#define HDIM    64
#define MROWS   (BATCH * SEQ)      // 4096
#define MH      (MROWS * HID)      // 3,145,728 floats
#define SCELEMS (BATCH * NHEAD * SEQ * SEQ)

// Scratch
__device__ float g_X[MH];
__device__ float g_Q[MH];
__device__ float g_K[MH];
__device__ float g_V[MH];
__device__ float g_CTX[MH];
__device__ float g_T1[MH];
__device__ float g_T2[MH];
__device__ float g_SC[SCELEMS];

// ---------------------------------------------------------------------------
// Packed fp32x2 helpers (sm_100+): 2 FMAs per issue slot via fma.rn.f32x2.
// ---------------------------------------------------------------------------
__device__ __forceinline__ unsigned long long pack_dup(float a) {
    unsigned long long r;
    asm("mov.b64 %0, {%1, %1};" : "=l"(r) : "f"(a));
    return r;
}
__device__ __forceinline__ void ffma2(unsigned long long& d,
                                      unsigned long long a,
                                      unsigned long long b) {
    asm("fma.rn.f32x2 %0, %1, %2, %0;" : "+l"(d) : "l"(a), "l"(b));
}
__device__ __forceinline__ float2 unpack2(unsigned long long v) {
    float2 f;
    asm("mov.b64 {%0, %1}, %2;" : "=f"(f.x), "=f"(f.y) : "l"(v));
    return f;
}

// ---------------------------------------------------------------------------
// GEMM: C[M,N] = A[M,K] @ W[K,N] + bias[N] (optional ReLU)
// BM=BN=128, BK=16, 256 threads, 8x8 per thread, double-buffered smem,
// register prefetch, packed f32x2 FMA inner loop.
// ---------------------------------------------------------------------------
template <bool RELU>
__global__ __launch_bounds__(256)
void gemm_bias_kernel(const float* __restrict__ A,
                      const float* __restrict__ W,
                      const float* __restrict__ bias,
                      float* __restrict__ C,
                      int M, int N, int K) {
    __shared__ float As[2][16][132];
    __shared__ float Bs[2][16][128];

    const int tid = threadIdx.x;
    const int blockRow = blockIdx.y * 128;
    const int blockCol = blockIdx.x * 128;

    const int aRow = tid >> 1;          // 0..127
    const int aK   = (tid & 1) * 8;     // 0 or 8
    const int bRow = tid >> 4;          // 0..15
    const int bCol = (tid & 15) * 8;    // 0..120

    const int tRow = (tid >> 4) * 8;
    const int tCol = (tid & 15) * 8;

    const float* Aptr = A + (size_t)(blockRow + aRow) * K + aK;
    const float* Wptr = W + (size_t)bRow * N + blockCol + bCol;

    unsigned long long acc[8][4];
#pragma unroll
    for (int i = 0; i < 8; i++)
#pragma unroll
        for (int j = 0; j < 4; j++) acc[i][j] = 0ULL;

    // preload tile 0 into registers
    float4 a0 = *reinterpret_cast<const float4*>(Aptr);
    float4 a1 = *reinterpret_cast<const float4*>(Aptr + 4);
    float4 b0 = *reinterpret_cast<const float4*>(Wptr);
    float4 b1 = *reinterpret_cast<const float4*>(Wptr + 4);

    const int ntiles = K / 16;
    int buf = 0;

    for (int t = 0; t < ntiles; t++) {
        // commit registers -> smem[buf]
        As[buf][aK + 0][aRow] = a0.x;
        As[buf][aK + 1][aRow] = a0.y;
        As[buf][aK + 2][aRow] = a0.z;
        As[buf][aK + 3][aRow] = a0.w;
        As[buf][aK + 4][aRow] = a1.x;
        As[buf][aK + 5][aRow] = a1.y;
        As[buf][aK + 6][aRow] = a1.z;
        As[buf][aK + 7][aRow] = a1.w;
        *reinterpret_cast<float4*>(&Bs[buf][bRow][bCol])     = b0;
        *reinterpret_cast<float4*>(&Bs[buf][bRow][bCol + 4]) = b1;
        __syncthreads();

        // prefetch next tile into registers (overlaps with compute)
        if (t + 1 < ntiles) {
            const float* An = Aptr + (t + 1) * 16;
            a0 = *reinterpret_cast<const float4*>(An);
            a1 = *reinterpret_cast<const float4*>(An + 4);
            const float* Wn = Wptr + (size_t)(t + 1) * 16 * N;
            b0 = *reinterpret_cast<const float4*>(Wn);
            b1 = *reinterpret_cast<const float4*>(Wn + 4);
        }

#pragma unroll
        for (int k = 0; k < 16; k++) {
            float4 x0 = *reinterpret_cast<const float4*>(&As[buf][k][tRow]);
            float4 x1 = *reinterpret_cast<const float4*>(&As[buf][k][tRow + 4]);
            ulonglong2 p01 = *reinterpret_cast<const ulonglong2*>(&Bs[buf][k][tCol]);
            ulonglong2 p23 = *reinterpret_cast<const ulonglong2*>(&Bs[buf][k][tCol + 4]);
            float ar[8] = {x0.x, x0.y, x0.z, x0.w, x1.x, x1.y, x1.z, x1.w};
#pragma unroll
            for (int i = 0; i < 8; i++) {
                unsigned long long ap = pack_dup(ar[i]);
                ffma2(acc[i][0], ap, p01.x);
                ffma2(acc[i][1], ap, p01.y);
                ffma2(acc[i][2], ap, p23.x);
                ffma2(acc[i][3], ap, p23.y);
            }
        }
        buf ^= 1;
    }

    const float4 bv0 = *reinterpret_cast<const float4*>(bias + blockCol + tCol);
    const float4 bv1 = *reinterpret_cast<const float4*>(bias + blockCol + tCol + 4);
    const float bb[8] = {bv0.x, bv0.y, bv0.z, bv0.w, bv1.x, bv1.y, bv1.z, bv1.w};

#pragma unroll
    for (int i = 0; i < 8; i++) {
        float* Crow = C + (size_t)(blockRow + tRow + i) * N + blockCol + tCol;
        float2 c0 = unpack2(acc[i][0]);
        float2 c1 = unpack2(acc[i][1]);
        float2 c2 = unpack2(acc[i][2]);
        float2 c3 = unpack2(acc[i][3]);
        float o[8] = {c0.x + bb[0], c0.y + bb[1], c1.x + bb[2], c1.y + bb[3],
                      c2.x + bb[4], c2.y + bb[5], c3.x + bb[6], c3.y + bb[7]};
        if (RELU) {
#pragma unroll
            for (int j = 0; j < 8; j++) o[j] = fmaxf(o[j], 0.0f);
        }
        float4 w0 = {o[0], o[1], o[2], o[3]};
        float4 w1 = {o[4], o[5], o[6], o[7]};
        *reinterpret_cast<float4*>(Crow)     = w0;
        *reinterpret_cast<float4*>(Crow + 4) = w1;
    }
}

// ---------------------------------------------------------------------------
// Scores: S[bh,q,k] = dot(Q[bh,q,:], K[bh,k,:]) * 0.125
// 128x128 tile per block, 8x8 per thread, d chunked by 32, packed FMA.
// ---------------------------------------------------------------------------
__global__ __launch_bounds__(256)
void scores_kernel(const float* __restrict__ Q,
                   const float* __restrict__ K,
                   float* __restrict__ SC) {
    const int bh = blockIdx.z;
    const int b = bh / NHEAD, h = bh % NHEAD;
    const int q0 = blockIdx.y * 128;
    const int k0 = blockIdx.x * 128;

    const float* Qh = Q + (size_t)(b * SEQ) * HID + h * HDIM;
    const float* Kh = K + (size_t)(b * SEQ) * HID + h * HDIM;
    float* S = SC + (size_t)bh * SEQ * SEQ;

    __shared__ float Qs[32][132];  // [d][q]
    __shared__ float Ks[32][128];  // [d][k]

    const int tid = threadIdx.x;
    const int lr = tid >> 1;            // 0..127
    const int db = (tid & 1) * 16;      // 0 or 16
    const int tRow = (tid >> 4) * 8;
    const int tCol = (tid & 15) * 8;

    unsigned long long acc[8][4];
#pragma unroll
    for (int i = 0; i < 8; i++)
#pragma unroll
        for (int j = 0; j < 4; j++) acc[i][j] = 0ULL;

    for (int d0 = 0; d0 < HDIM; d0 += 32) {
#pragma unroll
        for (int t = 0; t < 16; t += 4) {
            float4 q4 = *reinterpret_cast<const float4*>(Qh + (size_t)(q0 + lr) * HID + d0 + db + t);
            Qs[db + t + 0][lr] = q4.x;
            Qs[db + t + 1][lr] = q4.y;
            Qs[db + t + 2][lr] = q4.z;
            Qs[db + t + 3][lr] = q4.w;
            float4 k4 = *reinterpret_cast<const float4*>(Kh + (size_t)(k0 + lr) * HID + d0 + db + t);
            Ks[db + t + 0][lr] = k4.x;
            Ks[db + t + 1][lr] = k4.y;
            Ks[db + t + 2][lr] = k4.z;
            Ks[db + t + 3][lr] = k4.w;
        }
        __syncthreads();

#pragma unroll
        for (int d = 0; d < 32; d++) {
            float4 x0 = *reinterpret_cast<const float4*>(&Qs[d][tRow]);
            float4 x1 = *reinterpret_cast<const float4*>(&Qs[d][tRow + 4]);
            ulonglong2 p01 = *reinterpret_cast<const ulonglong2*>(&Ks[d][tCol]);
            ulonglong2 p23 = *reinterpret_cast<const ulonglong2*>(&Ks[d][tCol + 4]);
            float ar[8] = {x0.x, x0.y, x0.z, x0.w, x1.x, x1.y, x1.z, x1.w};
#pragma unroll
            for (int i = 0; i < 8; i++) {
                unsigned long long ap = pack_dup(ar[i]);
                ffma2(acc[i][0], ap, p01.x);
                ffma2(acc[i][1], ap, p01.y);
                ffma2(acc[i][2], ap, p23.x);
                ffma2(acc[i][3], ap, p23.y);
            }
        }
        __syncthreads();
    }

#pragma unroll
    for (int i = 0; i < 8; i++) {
        float* Srow = S + (size_t)(q0 + tRow + i) * SEQ + k0 + tCol;
        float2 c0 = unpack2(acc[i][0]);
        float2 c1 = unpack2(acc[i][1]);
        float2 c2 = unpack2(acc[i][2]);
        float2 c3 = unpack2(acc[i][3]);
        float4 w0 = {c0.x * 0.125f, c0.y * 0.125f, c1.x * 0.125f, c1.y * 0.125f};
        float4 w1 = {c2.x * 0.125f, c2.y * 0.125f, c3.x * 0.125f, c3.y * 0.125f};
        *reinterpret_cast<float4*>(Srow)     = w0;
        *reinterpret_cast<float4*>(Srow + 4) = w1;
    }
}

// ---------------------------------------------------------------------------
// Softmax over last dim (512), one block per row.
// ---------------------------------------------------------------------------
__global__ __launch_bounds__(256)
void softmax_kernel(float* __restrict__ SC) {
    float* row = SC + (size_t)blockIdx.x * SEQ;
    const int tid = threadIdx.x;

    float2 v = *reinterpret_cast<float2*>(row + tid * 2);
    __shared__ float red[256];

    red[tid] = fmaxf(v.x, v.y);
    __syncthreads();
#pragma unroll
    for (int s = 128; s > 0; s >>= 1) {
        if (tid < s) red[tid] = fmaxf(red[tid], red[tid + s]);
        __syncthreads();
    }
    const float m = red[0];
    __syncthreads();

    v.x = __expf(v.x - m);
    v.y = __expf(v.y - m);
    red[tid] = v.x + v.y;
    __syncthreads();
#pragma unroll
    for (int s = 128; s > 0; s >>= 1) {
        if (tid < s) red[tid] += red[tid + s];
        __syncthreads();
    }
    const float inv = 1.0f / red[0];
    v.x *= inv;
    v.y *= inv;
    *reinterpret_cast<float2*>(row + tid * 2) = v;
}

// ---------------------------------------------------------------------------
// Context: CTX[bh,q,:] = P[bh,q,:] @ V[bh,:,:]
// 128 q-rows x 64 d-cols per block, 8x4 per thread, kk chunked by 32.
// ---------------------------------------------------------------------------
__global__ __launch_bounds__(256)
void ctx_kernel(const float* __restrict__ SC,
                const float* __restrict__ V,
                float* __restrict__ CTX) {
    const int bh = blockIdx.z;
    const int b = bh / NHEAD, h = bh % NHEAD;
    const int q0 = blockIdx.y * 128;

    const float* S = SC + (size_t)bh * SEQ * SEQ;
    const float* Vh = V + (size_t)(b * SEQ) * HID + h * HDIM;
    float* Ch = CTX + (size_t)(b * SEQ) * HID + h * HDIM;

    __shared__ float Ps[32][132];  // [kk][q]
    __shared__ float Vs[32][72];   // [kk][d]

    const int tid = threadIdx.x;
    const int lr = tid >> 1;          // 0..127 (q row for P loader)
    const int kb = (tid & 1) * 16;    // kk base
    const int vr = tid >> 3;          // 0..31 (kk row for V loader)
    const int vd = (tid & 7) * 8;     // d base
    const int tRow = (tid >> 4) * 8;
    const int tCol = (tid & 15) * 4;

    unsigned long long acc[8][2];
#pragma unroll
    for (int i = 0; i < 8; i++) { acc[i][0] = 0ULL; acc[i][1] = 0ULL; }

    for (int kk0 = 0; kk0 < SEQ; kk0 += 32) {
#pragma unroll
        for (int t = 0; t < 16; t += 4) {
            float4 p4 = *reinterpret_cast<const float4*>(S + (size_t)(q0 + lr) * SEQ + kk0 + kb + t);
            Ps[kb + t + 0][lr] = p4.x;
            Ps[kb + t + 1][lr] = p4.y;
            Ps[kb + t + 2][lr] = p4.z;
            Ps[kb + t + 3][lr] = p4.w;
        }
        {
            float4 v0 = *reinterpret_cast<const float4*>(Vh + (size_t)(kk0 + vr) * HID + vd);
            float4 v1 = *reinterpret_cast<const float4*>(Vh + (size_t)(kk0 + vr) * HID + vd + 4);
            *reinterpret_cast<float4*>(&Vs[vr][vd])     = v0;
            *reinterpret_cast<float4*>(&Vs[vr][vd + 4]) = v1;
        }
        __syncthreads();

#pragma unroll
        for (int kk = 0; kk < 32; kk++) {
            float4 x0 = *reinterpret_cast<const float4*>(&Ps[kk][tRow]);
            float4 x1 = *reinterpret_cast<const float4*>(&Ps[kk][tRow + 4]);
            ulonglong2 p = *reinterpret_cast<const ulonglong2*>(&Vs[kk][tCol]);
            float ar[8] = {x0.x, x0.y, x0.z, x0.w, x1.x, x1.y, x1.z, x1.w};
#pragma unroll
            for (int i = 0; i < 8; i++) {
                unsigned long long ap = pack_dup(ar[i]);
                ffma2(acc[i][0], ap, p.x);
                ffma2(acc[i][1], ap, p.y);
            }
        }
        __syncthreads();
    }

#pragma unroll
    for (int i = 0; i < 8; i++) {
        float2 c0 = unpack2(acc[i][0]);
        float2 c1 = unpack2(acc[i][1]);
        float4 w = {c0.x, c0.y, c1.x, c1.y};
        *reinterpret_cast<float4*>(Ch + (size_t)(q0 + tRow + i) * HID + tCol) = w;
    }
}

// ---------------------------------------------------------------------------
// Add + LayerNorm
// ---------------------------------------------------------------------------
__global__ __launch_bounds__(256)
void add_ln_kernel(const float* __restrict__ X,
                   const float* __restrict__ Y,
                   const float* __restrict__ g,
                   const float* __restrict__ b,
                   float* __restrict__ O) {
    const int row = blockIdx.x;
    const float* xr = X + (size_t)row * HID;
    const float* yr = Y + (size_t)row * HID;
    float* orow = O + (size_t)row * HID;
    const int tid = threadIdx.x;

    float vals[3];
    float s = 0.f, ss = 0.f;
#pragma unroll
    for (int t = 0; t < 3; t++) {
        const int c = tid + t * 256;
        float v = xr[c] + yr[c];
        vals[t] = v;
        s += v;
        ss += v * v;
    }

    __shared__ float rs[256];
    __shared__ float rss[256];
    rs[tid] = s;
    rss[tid] = ss;
    __syncthreads();
#pragma unroll
    for (int st = 128; st > 0; st >>= 1) {
        if (tid < st) {
            rs[tid] += rs[tid + st];
            rss[tid] += rss[tid + st];
        }
        __syncthreads();
    }
    const float mean = rs[0] * (1.0f / HID);
    const float var = rss[0] * (1.0f / HID) - mean * mean;
    const float inv = rsqrtf(var + 1e-12f);

#pragma unroll
    for (int t = 0; t < 3; t++) {
        const int c = tid + t * 256;
        orow[c] = (vals[t] - mean) * inv * g[c] + b[c];
    }
}

// ---------------------------------------------------------------------------
// Launch
// ---------------------------------------------------------------------------
extern "C" void kernel_launch(void* const* d_in, const int* in_sizes, int n_in,
                              void* d_out, int out_size) {
    const float* x    = (const float*)d_in[0];
    const float* Wq   = (const float*)d_in[1];
    const float* bq   = (const float*)d_in[2];
    const float* Wk   = (const float*)d_in[3];
    const float* bk   = (const float*)d_in[4];
    const float* Wv   = (const float*)d_in[5];
    const float* bv   = (const float*)d_in[6];
    const float* Wo   = (const float*)d_in[7];
    const float* bo   = (const float*)d_in[8];
    const float* g1   = (const float*)d_in[9];
    const float* be1  = (const float*)d_in[10];
    const float* W2   = (const float*)d_in[11];
    const float* b2   = (const float*)d_in[12];
    const float* g2   = (const float*)d_in[13];
    const float* be2  = (const float*)d_in[14];

    float *X, *Q, *K, *V, *CTX, *T1, *T2, *SC;
    cudaGetSymbolAddress((void**)&X,   g_X);
    cudaGetSymbolAddress((void**)&Q,   g_Q);
    cudaGetSymbolAddress((void**)&K,   g_K);
    cudaGetSymbolAddress((void**)&V,   g_V);
    cudaGetSymbolAddress((void**)&CTX, g_CTX);
    cudaGetSymbolAddress((void**)&T1,  g_T1);
    cudaGetSymbolAddress((void**)&T2,  g_T2);
    cudaGetSymbolAddress((void**)&SC,  g_SC);

    cudaMemcpyAsync(X, x, (size_t)MH * sizeof(float), cudaMemcpyDeviceToDevice);

    const dim3 gemmGrid(HID / 128, MROWS / 128);            // (6, 32)
    const dim3 scGrid(SEQ / 128, SEQ / 128, BATCH * NHEAD); // (4, 4, 96)
    const dim3 ctxGrid(1, SEQ / 128, BATCH * NHEAD);        // (1, 4, 96)

    for (int l = 0; l < NLAYERS; l++) {
        const size_t wo = (size_t)l * HID * HID;
        const size_t vo = (size_t)l * HID;

        gemm_bias_kernel<false><<<gemmGrid, 256>>>(X, Wq + wo, bq + vo, Q, MROWS, HID, HID);
        gemm_bias_kernel<false><<<gemmGrid, 256>>>(X, Wk + wo, bk + vo, K, MROWS, HID, HID);
        gemm_bias_kernel<false><<<gemmGrid, 256>>>(X, Wv + wo, bv + vo, V, MROWS, HID, HID);

        scores_kernel<<<scGrid, 256>>>(Q, K, SC);
        softmax_kernel<<<BATCH * NHEAD * SEQ, 256>>>(SC);
        ctx_kernel<<<ctxGrid, 256>>>(SC, V, CTX);

        gemm_bias_kernel<false><<<gemmGrid, 256>>>(CTX, Wo + wo, bo + vo, T1, MROWS, HID, HID);
        add_ln_kernel<<<MROWS, 256>>>(X, T1, g1 + vo, be1 + vo, T2);

        gemm_bias_kernel<true><<<gemmGrid, 256>>>(T2, W2 + wo, b2 + vo, T1, MROWS, HID, HID);
        gemm_bias_kernel<true><<<gemmGrid, 256>>>(T1, W2 + wo, b2 + vo, Q, MROWS, HID, HID);
        add_ln_kernel<<<MROWS, 256>>>(T2, Q, g2 + vo, be2 + vo, X);
    }

    cudaMemcpyAsync(d_out, X, (size_t)MH * sizeof(float), cudaMemcpyDeviceToDevice);
}

// round 8
// speedup vs baseline: 1.8773x; 1.8773x over previous
#include <cuda_runtime.h>
#include <cuda_bf16.h>
#include <math.h>
#include <stdint.h>

// Problem constants
#define NLAYERS 12
#define BATCH   8
#define SEQ     512
#define HID     768
#define NHEAD   12
#define HDIM    64
#define MROWS   (BATCH * SEQ)      // 4096
#define MH      (MROWS * HID)
#define SCELEMS (BATCH * NHEAD * SEQ * SEQ)
#define WELEMS  (NLAYERS * HID * HID)   // 7,077,888 per weight tensor

// fp32 scratch
__device__ float g_X[MH];
__device__ float g_Q[MH];
__device__ float g_K[MH];
__device__ float g_V[MH];
__device__ float g_CTX[MH];
__device__ float g_T1[MH];
__device__ float g_T2[MH];
__device__ float g_SC[SCELEMS];

// bf16 hi/lo scratch
__device__ __nv_bfloat16 g_AH[MH];
__device__ __nv_bfloat16 g_AL[MH];
__device__ __nv_bfloat16 g_WqH[WELEMS], g_WqL[WELEMS];
__device__ __nv_bfloat16 g_WkH[WELEMS], g_WkL[WELEMS];
__device__ __nv_bfloat16 g_WvH[WELEMS], g_WvL[WELEMS];
__device__ __nv_bfloat16 g_WoH[WELEMS], g_WoL[WELEMS];
__device__ __nv_bfloat16 g_W2H[WELEMS], g_W2L[WELEMS];

// ---------------------------------------------------------------------------
// helpers
// ---------------------------------------------------------------------------
__device__ __forceinline__ uint32_t smem_u32(const void* p) {
    uint32_t a;
    asm("{ .reg .u64 t; cvta.to.shared.u64 t, %1; cvt.u32.u64 %0, t; }"
        : "=r"(a) : "l"(p));
    return a;
}

#define LDSM_X4(r, addr) \
    asm volatile("ldmatrix.sync.aligned.m8n8.x4.shared.b16 {%0,%1,%2,%3}, [%4];" \
        : "=r"((r)[0]), "=r"((r)[1]), "=r"((r)[2]), "=r"((r)[3]) : "r"(addr))

#define LDSM_X4_T(r, addr) \
    asm volatile("ldmatrix.sync.aligned.m8n8.x4.trans.shared.b16 {%0,%1,%2,%3}, [%4];" \
        : "=r"((r)[0]), "=r"((r)[1]), "=r"((r)[2]), "=r"((r)[3]) : "r"(addr))

#define MMA_BF16(d, a, b0, b1) \
    asm volatile("mma.sync.aligned.m16n8k16.row.col.f32.bf16.bf16.f32 " \
        "{%0,%1,%2,%3}, {%4,%5,%6,%7}, {%8,%9}, {%0,%1,%2,%3};" \
        : "+f"((d)[0]), "+f"((d)[1]), "+f"((d)[2]), "+f"((d)[3]) \
        : "r"((a)[0]), "r"((a)[1]), "r"((a)[2]), "r"((a)[3]), "r"(b0), "r"(b1))

// ---------------------------------------------------------------------------
// fp32 -> bf16 hi/lo conversion
// ---------------------------------------------------------------------------
__global__ __launch_bounds__(256)
void conv_hl(const float* __restrict__ s,
             __nv_bfloat16* __restrict__ h,
             __nv_bfloat16* __restrict__ l,
             int n4) {
    int i = blockIdx.x * 256 + threadIdx.x;
    if (i >= n4) return;
    float4 v = reinterpret_cast<const float4*>(s)[i];
    __nv_bfloat16 h0 = __float2bfloat16(v.x);
    __nv_bfloat16 h1 = __float2bfloat16(v.y);
    __nv_bfloat16 h2 = __float2bfloat16(v.z);
    __nv_bfloat16 h3 = __float2bfloat16(v.w);
    __nv_bfloat16 l0 = __float2bfloat16(v.x - __bfloat162float(h0));
    __nv_bfloat16 l1 = __float2bfloat16(v.y - __bfloat162float(h1));
    __nv_bfloat16 l2 = __float2bfloat16(v.z - __bfloat162float(h2));
    __nv_bfloat16 l3 = __float2bfloat16(v.w - __bfloat162float(h3));
    reinterpret_cast<__nv_bfloat162*>(h)[2 * i]     = __halves2bfloat162(h0, h1);
    reinterpret_cast<__nv_bfloat162*>(h)[2 * i + 1] = __halves2bfloat162(h2, h3);
    reinterpret_cast<__nv_bfloat162*>(l)[2 * i]     = __halves2bfloat162(l0, l1);
    reinterpret_cast<__nv_bfloat162*>(l)[2 * i + 1] = __halves2bfloat162(l2, l3);
}

// ---------------------------------------------------------------------------
// bf16 split-precision tensor-core GEMM:
// C[4096,768] = A @ W + bias (opt ReLU), A/W given as bf16 hi+lo.
// BM=128, BN=64, BK=32; 8 warps (4x2), warp tile 32x32; mma.m16n8k16.
// 3-product emulation: AhBh + AhBl + AlBh (fp32 accumulate).
// ---------------------------------------------------------------------------
template <bool RELU>
__global__ __launch_bounds__(256)
void gemm_mma(const __nv_bfloat16* __restrict__ Ah,
              const __nv_bfloat16* __restrict__ Al,
              const __nv_bfloat16* __restrict__ Wh,
              const __nv_bfloat16* __restrict__ Wl,
              const float* __restrict__ bias,
              float* __restrict__ C) {
    // A tiles: 128 rows x 32 k, stride 40 elems (80B -> conflict-free ldmatrix)
    // B tiles: 32 k x 64 n, stride 72 elems (144B -> conflict-free trans ldmatrix)
    __shared__ __nv_bfloat16 Ash[128 * 40];
    __shared__ __nv_bfloat16 Asl[128 * 40];
    __shared__ __nv_bfloat16 Bsh[32 * 72];
    __shared__ __nv_bfloat16 Bsl[32 * 72];

    const int tid = threadIdx.x;
    const int wid = tid >> 5;
    const int lane = tid & 31;
    const int blockRow = blockIdx.y * 128;
    const int blockCol = blockIdx.x * 64;
    const int wm = (wid & 3) * 32;     // warp m offset
    const int wn = (wid >> 2) * 32;    // warp n offset

    float acc[2][4][4];
#pragma unroll
    for (int i = 0; i < 2; i++)
#pragma unroll
        for (int j = 0; j < 4; j++)
#pragma unroll
            for (int q = 0; q < 4; q++) acc[i][j][q] = 0.0f;

    const uint32_t sAh = smem_u32(Ash);
    const uint32_t sAl = smem_u32(Asl);
    const uint32_t sBh = smem_u32(Bsh);
    const uint32_t sBl = smem_u32(Bsl);

    // loader indices
    const int arow = tid >> 1;          // 0..127
    const int ahalf = tid & 1;          // 16-elem half of the 32-k chunk
    const int bk = tid >> 3;            // 0..31
    const int bj = tid & 7;             // 8-elem group within 64 n

    // ldmatrix per-lane byte offsets
    // A (row-major m x k): lanes 0-15 -> rows, lanes>>4 -> k-col half
    const uint32_t aoff = (uint32_t)((wm + (lane & 15)) * 80 + (lane >> 4) * 16);
    // B trans (row-major k x n): mat0/1 -> k halves, mat2/3 -> n+8
    const uint32_t boff = (uint32_t)(((lane & 7) + ((lane >> 3) & 1) * 8) * 144
                                     + (wn + (lane >> 4) * 8) * 2);

    for (int kt = 0; kt < HID / 32; kt++) {
        // ---- load A tile (hi+lo): 16 bf16 (32B) per thread per array ----
        {
            const size_t ga = (size_t)(blockRow + arow) * HID + kt * 32 + ahalf * 16;
            const uint32_t so = (uint32_t)(arow * 80 + ahalf * 32);
            uint4 v0 = *reinterpret_cast<const uint4*>(Ah + ga);
            uint4 v1 = *reinterpret_cast<const uint4*>(Ah + ga + 8);
            *reinterpret_cast<uint4*>((char*)Ash + so)      = v0;
            *reinterpret_cast<uint4*>((char*)Ash + so + 16) = v1;
            uint4 w0 = *reinterpret_cast<const uint4*>(Al + ga);
            uint4 w1 = *reinterpret_cast<const uint4*>(Al + ga + 8);
            *reinterpret_cast<uint4*>((char*)Asl + so)      = w0;
            *reinterpret_cast<uint4*>((char*)Asl + so + 16) = w1;
        }
        // ---- load B tile (hi+lo): 8 bf16 (16B) per thread per array ----
        {
            const size_t gb = (size_t)(kt * 32 + bk) * HID + blockCol + bj * 8;
            const uint32_t so = (uint32_t)(bk * 144 + bj * 16);
            uint4 v = *reinterpret_cast<const uint4*>(Wh + gb);
            *reinterpret_cast<uint4*>((char*)Bsh + so) = v;
            uint4 w = *reinterpret_cast<const uint4*>(Wl + gb);
            *reinterpret_cast<uint4*>((char*)Bsl + so) = w;
        }
        __syncthreads();

#pragma unroll
        for (int ks = 0; ks < 2; ks++) {
            uint32_t ah[2][4], al[2][4], bh[2][4], bl[2][4];
#pragma unroll
            for (int mi = 0; mi < 2; mi++) {
                LDSM_X4(ah[mi], sAh + aoff + mi * 16 * 80 + ks * 32);
                LDSM_X4(al[mi], sAl + aoff + mi * 16 * 80 + ks * 32);
            }
#pragma unroll
            for (int ni = 0; ni < 2; ni++) {
                LDSM_X4_T(bh[ni], sBh + boff + ks * 16 * 144 + ni * 32);
                LDSM_X4_T(bl[ni], sBl + boff + ks * 16 * 144 + ni * 32);
            }
#pragma unroll
            for (int mi = 0; mi < 2; mi++) {
#pragma unroll
                for (int nt = 0; nt < 4; nt++) {
                    const int ni = nt >> 1;
                    const int sel = (nt & 1) * 2;
                    MMA_BF16(acc[mi][nt], ah[mi], bh[ni][sel], bh[ni][sel + 1]);
                    MMA_BF16(acc[mi][nt], ah[mi], bl[ni][sel], bl[ni][sel + 1]);
                    MMA_BF16(acc[mi][nt], al[mi], bh[ni][sel], bh[ni][sel + 1]);
                }
            }
        }
        __syncthreads();
    }

    // ---- epilogue ----
#pragma unroll
    for (int mi = 0; mi < 2; mi++) {
#pragma unroll
        for (int nt = 0; nt < 4; nt++) {
            const int col = blockCol + wn + nt * 8 + (lane & 3) * 2;
            const float2 bv = *reinterpret_cast<const float2*>(bias + col);
            const int r0 = blockRow + wm + mi * 16 + (lane >> 2);
            float2 o0 = {acc[mi][nt][0] + bv.x, acc[mi][nt][1] + bv.y};
            float2 o1 = {acc[mi][nt][2] + bv.x, acc[mi][nt][3] + bv.y};
            if (RELU) {
                o0.x = fmaxf(o0.x, 0.f); o0.y = fmaxf(o0.y, 0.f);
                o1.x = fmaxf(o1.x, 0.f); o1.y = fmaxf(o1.y, 0.f);
            }
            *reinterpret_cast<float2*>(C + (size_t)r0 * HID + col)       = o0;
            *reinterpret_cast<float2*>(C + (size_t)(r0 + 8) * HID + col) = o1;
        }
    }
}

// ---------------------------------------------------------------------------
// Attention: scores (FFMA2), softmax, ctx (FFMA2) — unchanged from passing R3.
// ---------------------------------------------------------------------------
__device__ __forceinline__ unsigned long long pack_dup(float a) {
    unsigned long long r;
    asm("mov.b64 %0, {%1, %1};" : "=l"(r) : "f"(a));
    return r;
}
__device__ __forceinline__ void ffma2(unsigned long long& d,
                                      unsigned long long a,
                                      unsigned long long b) {
    asm("fma.rn.f32x2 %0, %1, %2, %0;" : "+l"(d) : "l"(a), "l"(b));
}
__device__ __forceinline__ float2 unpack2(unsigned long long v) {
    float2 f;
    asm("mov.b64 {%0, %1}, %2;" : "=f"(f.x), "=f"(f.y) : "l"(v));
    return f;
}

__global__ __launch_bounds__(256)
void scores_kernel(const float* __restrict__ Q,
                   const float* __restrict__ K,
                   float* __restrict__ SC) {
    const int bh = blockIdx.z;
    const int b = bh / NHEAD, h = bh % NHEAD;
    const int q0 = blockIdx.y * 128;
    const int k0 = blockIdx.x * 128;

    const float* Qh = Q + (size_t)(b * SEQ) * HID + h * HDIM;
    const float* Kh = K + (size_t)(b * SEQ) * HID + h * HDIM;
    float* S = SC + (size_t)bh * SEQ * SEQ;

    __shared__ float Qs[32][132];
    __shared__ float Ks[32][128];

    const int tid = threadIdx.x;
    const int lr = tid >> 1;
    const int db = (tid & 1) * 16;
    const int tRow = (tid >> 4) * 8;
    const int tCol = (tid & 15) * 8;

    unsigned long long acc[8][4];
#pragma unroll
    for (int i = 0; i < 8; i++)
#pragma unroll
        for (int j = 0; j < 4; j++) acc[i][j] = 0ULL;

    for (int d0 = 0; d0 < HDIM; d0 += 32) {
#pragma unroll
        for (int t = 0; t < 16; t += 4) {
            float4 q4 = *reinterpret_cast<const float4*>(Qh + (size_t)(q0 + lr) * HID + d0 + db + t);
            Qs[db + t + 0][lr] = q4.x;
            Qs[db + t + 1][lr] = q4.y;
            Qs[db + t + 2][lr] = q4.z;
            Qs[db + t + 3][lr] = q4.w;
            float4 k4 = *reinterpret_cast<const float4*>(Kh + (size_t)(k0 + lr) * HID + d0 + db + t);
            Ks[db + t + 0][lr] = k4.x;
            Ks[db + t + 1][lr] = k4.y;
            Ks[db + t + 2][lr] = k4.z;
            Ks[db + t + 3][lr] = k4.w;
        }
        __syncthreads();

#pragma unroll
        for (int d = 0; d < 32; d++) {
            float4 x0 = *reinterpret_cast<const float4*>(&Qs[d][tRow]);
            float4 x1 = *reinterpret_cast<const float4*>(&Qs[d][tRow + 4]);
            ulonglong2 p01 = *reinterpret_cast<const ulonglong2*>(&Ks[d][tCol]);
            ulonglong2 p23 = *reinterpret_cast<const ulonglong2*>(&Ks[d][tCol + 4]);
            float ar[8] = {x0.x, x0.y, x0.z, x0.w, x1.x, x1.y, x1.z, x1.w};
#pragma unroll
            for (int i = 0; i < 8; i++) {
                unsigned long long ap = pack_dup(ar[i]);
                ffma2(acc[i][0], ap, p01.x);
                ffma2(acc[i][1], ap, p01.y);
                ffma2(acc[i][2], ap, p23.x);
                ffma2(acc[i][3], ap, p23.y);
            }
        }
        __syncthreads();
    }

#pragma unroll
    for (int i = 0; i < 8; i++) {
        float* Srow = S + (size_t)(q0 + tRow + i) * SEQ + k0 + tCol;
        float2 c0 = unpack2(acc[i][0]);
        float2 c1 = unpack2(acc[i][1]);
        float2 c2 = unpack2(acc[i][2]);
        float2 c3 = unpack2(acc[i][3]);
        float4 w0 = {c0.x * 0.125f, c0.y * 0.125f, c1.x * 0.125f, c1.y * 0.125f};
        float4 w1 = {c2.x * 0.125f, c2.y * 0.125f, c3.x * 0.125f, c3.y * 0.125f};
        *reinterpret_cast<float4*>(Srow)     = w0;
        *reinterpret_cast<float4*>(Srow + 4) = w1;
    }
}

__global__ __launch_bounds__(256)
void softmax_kernel(float* __restrict__ SC) {
    float* row = SC + (size_t)blockIdx.x * SEQ;
    const int tid = threadIdx.x;

    float2 v = *reinterpret_cast<float2*>(row + tid * 2);
    __shared__ float red[256];

    red[tid] = fmaxf(v.x, v.y);
    __syncthreads();
#pragma unroll
    for (int s = 128; s > 0; s >>= 1) {
        if (tid < s) red[tid] = fmaxf(red[tid], red[tid + s]);
        __syncthreads();
    }
    const float m = red[0];
    __syncthreads();

    v.x = __expf(v.x - m);
    v.y = __expf(v.y - m);
    red[tid] = v.x + v.y;
    __syncthreads();
#pragma unroll
    for (int s = 128; s > 0; s >>= 1) {
        if (tid < s) red[tid] += red[tid + s];
        __syncthreads();
    }
    const float inv = 1.0f / red[0];
    v.x *= inv;
    v.y *= inv;
    *reinterpret_cast<float2*>(row + tid * 2) = v;
}

__global__ __launch_bounds__(256)
void ctx_kernel(const float* __restrict__ SC,
                const float* __restrict__ V,
                float* __restrict__ CTX) {
    const int bh = blockIdx.z;
    const int b = bh / NHEAD, h = bh % NHEAD;
    const int q0 = blockIdx.y * 128;

    const float* S = SC + (size_t)bh * SEQ * SEQ;
    const float* Vh = V + (size_t)(b * SEQ) * HID + h * HDIM;
    float* Ch = CTX + (size_t)(b * SEQ) * HID + h * HDIM;

    __shared__ float Ps[32][132];
    __shared__ float Vs[32][72];

    const int tid = threadIdx.x;
    const int lr = tid >> 1;
    const int kb = (tid & 1) * 16;
    const int vr = tid >> 3;
    const int vd = (tid & 7) * 8;
    const int tRow = (tid >> 4) * 8;
    const int tCol = (tid & 15) * 4;

    unsigned long long acc[8][2];
#pragma unroll
    for (int i = 0; i < 8; i++) { acc[i][0] = 0ULL; acc[i][1] = 0ULL; }

    for (int kk0 = 0; kk0 < SEQ; kk0 += 32) {
#pragma unroll
        for (int t = 0; t < 16; t += 4) {
            float4 p4 = *reinterpret_cast<const float4*>(S + (size_t)(q0 + lr) * SEQ + kk0 + kb + t);
            Ps[kb + t + 0][lr] = p4.x;
            Ps[kb + t + 1][lr] = p4.y;
            Ps[kb + t + 2][lr] = p4.z;
            Ps[kb + t + 3][lr] = p4.w;
        }
        {
            float4 v0 = *reinterpret_cast<const float4*>(Vh + (size_t)(kk0 + vr) * HID + vd);
            float4 v1 = *reinterpret_cast<const float4*>(Vh + (size_t)(kk0 + vr) * HID + vd + 4);
            *reinterpret_cast<float4*>(&Vs[vr][vd])     = v0;
            *reinterpret_cast<float4*>(&Vs[vr][vd + 4]) = v1;
        }
        __syncthreads();

#pragma unroll
        for (int kk = 0; kk < 32; kk++) {
            float4 x0 = *reinterpret_cast<const float4*>(&Ps[kk][tRow]);
            float4 x1 = *reinterpret_cast<const float4*>(&Ps[kk][tRow + 4]);
            ulonglong2 p = *reinterpret_cast<const ulonglong2*>(&Vs[kk][tCol]);
            float ar[8] = {x0.x, x0.y, x0.z, x0.w, x1.x, x1.y, x1.z, x1.w};
#pragma unroll
            for (int i = 0; i < 8; i++) {
                unsigned long long ap = pack_dup(ar[i]);
                ffma2(acc[i][0], ap, p.x);
                ffma2(acc[i][1], ap, p.y);
            }
        }
        __syncthreads();
    }

#pragma unroll
    for (int i = 0; i < 8; i++) {
        float2 c0 = unpack2(acc[i][0]);
        float2 c1 = unpack2(acc[i][1]);
        float4 w = {c0.x, c0.y, c1.x, c1.y};
        *reinterpret_cast<float4*>(Ch + (size_t)(q0 + tRow + i) * HID + tCol) = w;
    }
}

// ---------------------------------------------------------------------------
// Add + LayerNorm
// ---------------------------------------------------------------------------
__global__ __launch_bounds__(256)
void add_ln_kernel(const float* __restrict__ X,
                   const float* __restrict__ Y,
                   const float* __restrict__ g,
                   const float* __restrict__ b,
                   float* __restrict__ O) {
    const int row = blockIdx.x;
    const float* xr = X + (size_t)row * HID;
    const float* yr = Y + (size_t)row * HID;
    float* orow = O + (size_t)row * HID;
    const int tid = threadIdx.x;

    float vals[3];
    float s = 0.f, ss = 0.f;
#pragma unroll
    for (int t = 0; t < 3; t++) {
        const int c = tid + t * 256;
        float v = xr[c] + yr[c];
        vals[t] = v;
        s += v;
        ss += v * v;
    }

    __shared__ float rs[256];
    __shared__ float rss[256];
    rs[tid] = s;
    rss[tid] = ss;
    __syncthreads();
#pragma unroll
    for (int st = 128; st > 0; st >>= 1) {
        if (tid < st) {
            rs[tid] += rs[tid + st];
            rss[tid] += rss[tid + st];
        }
        __syncthreads();
    }
    const float mean = rs[0] * (1.0f / HID);
    const float var = rss[0] * (1.0f / HID) - mean * mean;
    const float inv = rsqrtf(var + 1e-12f);

#pragma unroll
    for (int t = 0; t < 3; t++) {
        const int c = tid + t * 256;
        orow[c] = (vals[t] - mean) * inv * g[c] + b[c];
    }
}

// ---------------------------------------------------------------------------
// Launch
// ---------------------------------------------------------------------------
extern "C" void kernel_launch(void* const* d_in, const int* in_sizes, int n_in,
                              void* d_out, int out_size) {
    const float* x    = (const float*)d_in[0];
    const float* Wq   = (const float*)d_in[1];
    const float* bq   = (const float*)d_in[2];
    const float* Wk   = (const float*)d_in[3];
    const float* bk   = (const float*)d_in[4];
    const float* Wv   = (const float*)d_in[5];
    const float* bv   = (const float*)d_in[6];
    const float* Wo   = (const float*)d_in[7];
    const float* bo   = (const float*)d_in[8];
    const float* g1   = (const float*)d_in[9];
    const float* be1  = (const float*)d_in[10];
    const float* W2   = (const float*)d_in[11];
    const float* b2   = (const float*)d_in[12];
    const float* g2   = (const float*)d_in[13];
    const float* be2  = (const float*)d_in[14];

    float *X, *Q, *K, *V, *CTX, *T1, *T2, *SC;
    cudaGetSymbolAddress((void**)&X,   g_X);
    cudaGetSymbolAddress((void**)&Q,   g_Q);
    cudaGetSymbolAddress((void**)&K,   g_K);
    cudaGetSymbolAddress((void**)&V,   g_V);
    cudaGetSymbolAddress((void**)&CTX, g_CTX);
    cudaGetSymbolAddress((void**)&T1,  g_T1);
    cudaGetSymbolAddress((void**)&T2,  g_T2);
    cudaGetSymbolAddress((void**)&SC,  g_SC);

    __nv_bfloat16 *AH, *AL, *WqH, *WqL, *WkH, *WkL, *WvH, *WvL, *WoH, *WoL, *W2H, *W2L;
    cudaGetSymbolAddress((void**)&AH,  g_AH);
    cudaGetSymbolAddress((void**)&AL,  g_AL);
    cudaGetSymbolAddress((void**)&WqH, g_WqH);
    cudaGetSymbolAddress((void**)&WqL, g_WqL);
    cudaGetSymbolAddress((void**)&WkH, g_WkH);
    cudaGetSymbolAddress((void**)&WkL, g_WkL);
    cudaGetSymbolAddress((void**)&WvH, g_WvH);
    cudaGetSymbolAddress((void**)&WvL, g_WvL);
    cudaGetSymbolAddress((void**)&WoH, g_WoH);
    cudaGetSymbolAddress((void**)&WoL, g_WoL);
    cudaGetSymbolAddress((void**)&W2H, g_W2H);
    cudaGetSymbolAddress((void**)&W2L, g_W2L);

    cudaMemcpyAsync(X, x, (size_t)MH * sizeof(float), cudaMemcpyDeviceToDevice);

    // convert all weights to bf16 hi/lo once
    const int wN4 = WELEMS / 4;
    const int wGrid = (wN4 + 255) / 256;
    conv_hl<<<wGrid, 256>>>(Wq, WqH, WqL, wN4);
    conv_hl<<<wGrid, 256>>>(Wk, WkH, WkL, wN4);
    conv_hl<<<wGrid, 256>>>(Wv, WvH, WvL, wN4);
    conv_hl<<<wGrid, 256>>>(Wo, WoH, WoL, wN4);
    conv_hl<<<wGrid, 256>>>(W2, W2H, W2L, wN4);

    const int aN4 = MH / 4;
    const int aGrid = (aN4 + 255) / 256;

    const dim3 gemmGrid(HID / 64, MROWS / 128);             // (12, 32)
    const dim3 scGrid(SEQ / 128, SEQ / 128, BATCH * NHEAD); // (4, 4, 96)
    const dim3 ctxGrid(1, SEQ / 128, BATCH * NHEAD);        // (1, 4, 96)

    for (int l = 0; l < NLAYERS; l++) {
        const size_t wo = (size_t)l * HID * HID;
        const size_t vo = (size_t)l * HID;

        conv_hl<<<aGrid, 256>>>(X, AH, AL, aN4);
        gemm_mma<false><<<gemmGrid, 256>>>(AH, AL, WqH + wo, WqL + wo, bq + vo, Q);
        gemm_mma<false><<<gemmGrid, 256>>>(AH, AL, WkH + wo, WkL + wo, bk + vo, K);
        gemm_mma<false><<<gemmGrid, 256>>>(AH, AL, WvH + wo, WvL + wo, bv + vo, V);

        scores_kernel<<<scGrid, 256>>>(Q, K, SC);
        softmax_kernel<<<BATCH * NHEAD * SEQ, 256>>>(SC);
        ctx_kernel<<<ctxGrid, 256>>>(SC, V, CTX);

        conv_hl<<<aGrid, 256>>>(CTX, AH, AL, aN4);
        gemm_mma<false><<<gemmGrid, 256>>>(AH, AL, WoH + wo, WoL + wo, bo + vo, T1);
        add_ln_kernel<<<MROWS, 256>>>(X, T1, g1 + vo, be1 + vo, T2);

        conv_hl<<<aGrid, 256>>>(T2, AH, AL, aN4);
        gemm_mma<true><<<gemmGrid, 256>>>(AH, AL, W2H + wo, W2L + wo, b2 + vo, T1);
        conv_hl<<<aGrid, 256>>>(T1, AH, AL, aN4);
        gemm_mma<true><<<gemmGrid, 256>>>(AH, AL, W2H + wo, W2L + wo, b2 + vo, Q);
        add_ln_kernel<<<MROWS, 256>>>(T2, Q, g2 + vo, be2 + vo, X);
    }

    cudaMemcpyAsync(d_out, X, (size_t)MH * sizeof(float), cudaMemcpyDeviceToDevice);
}

// round 9
// speedup vs baseline: 2.1424x; 1.1412x over previous
#include <cuda_runtime.h>
#include <cuda_bf16.h>
#include <math.h>
#include <stdint.h>

// Problem constants
#define NLAYERS 12
#define BATCH   8
#define SEQ     512
#define HID     768
#define NHEAD   12
#define HDIM    64
#define MROWS   (BATCH * SEQ)      // 4096
#define MH      (MROWS * HID)
#define SCELEMS (BATCH * NHEAD * SEQ * SEQ)
#define WELEMS  (NLAYERS * HID * HID)

// fp32 scratch
__device__ float g_X[MH];
__device__ float g_T1[MH];
__device__ float g_T2[MH];
__device__ float g_SC[SCELEMS];

// bf16 hi/lo scratch (activations)
__device__ __nv_bfloat16 g_XH[MH],  g_XL[MH];
__device__ __nv_bfloat16 g_QH[MH],  g_QL[MH];
__device__ __nv_bfloat16 g_KH[MH],  g_KL[MH];
__device__ __nv_bfloat16 g_VH[MH],  g_VL[MH];
__device__ __nv_bfloat16 g_CH[MH],  g_CL[MH];
__device__ __nv_bfloat16 g_TH[MH],  g_TL[MH];
__device__ __nv_bfloat16 g_UH[MH],  g_UL[MH];
__device__ __nv_bfloat16 g_PH[SCELEMS], g_PL[SCELEMS];

// bf16 hi/lo weights
__device__ __nv_bfloat16 g_WqH[WELEMS], g_WqL[WELEMS];
__device__ __nv_bfloat16 g_WkH[WELEMS], g_WkL[WELEMS];
__device__ __nv_bfloat16 g_WvH[WELEMS], g_WvL[WELEMS];
__device__ __nv_bfloat16 g_WoH[WELEMS], g_WoL[WELEMS];
__device__ __nv_bfloat16 g_W2H[WELEMS], g_W2L[WELEMS];

// ---------------------------------------------------------------------------
// helpers
// ---------------------------------------------------------------------------
__device__ __forceinline__ uint32_t smem_u32(const void* p) {
    uint32_t a;
    asm("{ .reg .u64 t; cvta.to.shared.u64 t, %1; cvt.u32.u64 %0, t; }"
        : "=r"(a) : "l"(p));
    return a;
}

#define LDSM_X4(r, addr) \
    asm volatile("ldmatrix.sync.aligned.m8n8.x4.shared.b16 {%0,%1,%2,%3}, [%4];" \
        : "=r"((r)[0]), "=r"((r)[1]), "=r"((r)[2]), "=r"((r)[3]) : "r"(addr))

#define LDSM_X4_T(r, addr) \
    asm volatile("ldmatrix.sync.aligned.m8n8.x4.trans.shared.b16 {%0,%1,%2,%3}, [%4];" \
        : "=r"((r)[0]), "=r"((r)[1]), "=r"((r)[2]), "=r"((r)[3]) : "r"(addr))

#define MMA_BF16(d, a, b0, b1) \
    asm volatile("mma.sync.aligned.m16n8k16.row.col.f32.bf16.bf16.f32 " \
        "{%0,%1,%2,%3}, {%4,%5,%6,%7}, {%8,%9}, {%0,%1,%2,%3};" \
        : "+f"((d)[0]), "+f"((d)[1]), "+f"((d)[2]), "+f"((d)[3]) \
        : "r"((a)[0]), "r"((a)[1]), "r"((a)[2]), "r"((a)[3]), "r"(b0), "r"(b1))

__device__ __forceinline__ void split_hl(float v, __nv_bfloat16& h, __nv_bfloat16& l) {
    h = __float2bfloat16(v);
    l = __float2bfloat16(v - __bfloat162float(h));
}

// ---------------------------------------------------------------------------
// fp32 -> bf16 hi/lo conversion (weights + initial X)
// ---------------------------------------------------------------------------
__global__ __launch_bounds__(256)
void conv_hl(const float* __restrict__ s,
             __nv_bfloat16* __restrict__ h,
             __nv_bfloat16* __restrict__ l,
             int n4) {
    int i = blockIdx.x * 256 + threadIdx.x;
    if (i >= n4) return;
    float4 v = reinterpret_cast<const float4*>(s)[i];
    __nv_bfloat16 h0, h1, h2, h3, l0, l1, l2, l3;
    split_hl(v.x, h0, l0); split_hl(v.y, h1, l1);
    split_hl(v.z, h2, l2); split_hl(v.w, h3, l3);
    reinterpret_cast<__nv_bfloat162*>(h)[2 * i]     = __halves2bfloat162(h0, h1);
    reinterpret_cast<__nv_bfloat162*>(h)[2 * i + 1] = __halves2bfloat162(h2, h3);
    reinterpret_cast<__nv_bfloat162*>(l)[2 * i]     = __halves2bfloat162(l0, l1);
    reinterpret_cast<__nv_bfloat162*>(l)[2 * i + 1] = __halves2bfloat162(l2, l3);
}

// ---------------------------------------------------------------------------
// bf16 split-precision GEMM: BM=128, BN=64, BK=32, 8 warps (4x2), warp 32x32.
// Outputs: fp32 C (OUTF) and/or bf16 hi/lo (OUTH).
// ---------------------------------------------------------------------------
template <bool RELU, bool OUTF, bool OUTH>
__global__ __launch_bounds__(256)
void gemm_mma(const __nv_bfloat16* __restrict__ Ah,
              const __nv_bfloat16* __restrict__ Al,
              const __nv_bfloat16* __restrict__ Wh,
              const __nv_bfloat16* __restrict__ Wl,
              const float* __restrict__ bias,
              float* __restrict__ C,
              __nv_bfloat16* __restrict__ Ch,
              __nv_bfloat16* __restrict__ Cl) {
    __shared__ __nv_bfloat16 Ash[128 * 40];
    __shared__ __nv_bfloat16 Asl[128 * 40];
    __shared__ __nv_bfloat16 Bsh[32 * 72];
    __shared__ __nv_bfloat16 Bsl[32 * 72];

    const int tid = threadIdx.x;
    const int wid = tid >> 5;
    const int lane = tid & 31;
    const int blockRow = blockIdx.y * 128;
    const int blockCol = blockIdx.x * 64;
    const int wm = (wid & 3) * 32;
    const int wn = (wid >> 2) * 32;

    float acc[2][4][4];
#pragma unroll
    for (int i = 0; i < 2; i++)
#pragma unroll
        for (int j = 0; j < 4; j++)
#pragma unroll
            for (int q = 0; q < 4; q++) acc[i][j][q] = 0.0f;

    const uint32_t sAh = smem_u32(Ash);
    const uint32_t sAl = smem_u32(Asl);
    const uint32_t sBh = smem_u32(Bsh);
    const uint32_t sBl = smem_u32(Bsl);

    const int arow = tid >> 1;
    const int ahalf = tid & 1;
    const int bk = tid >> 3;
    const int bj = tid & 7;

    const uint32_t aoff = (uint32_t)((wm + (lane & 15)) * 80 + (lane >> 4) * 16);
    const uint32_t boff = (uint32_t)(((lane & 7) + ((lane >> 3) & 1) * 8) * 144
                                     + (wn + (lane >> 4) * 8) * 2);

    for (int kt = 0; kt < HID / 32; kt++) {
        {
            const size_t ga = (size_t)(blockRow + arow) * HID + kt * 32 + ahalf * 16;
            const uint32_t so = (uint32_t)(arow * 80 + ahalf * 32);
            uint4 v0 = *reinterpret_cast<const uint4*>(Ah + ga);
            uint4 v1 = *reinterpret_cast<const uint4*>(Ah + ga + 8);
            *reinterpret_cast<uint4*>((char*)Ash + so)      = v0;
            *reinterpret_cast<uint4*>((char*)Ash + so + 16) = v1;
            uint4 w0 = *reinterpret_cast<const uint4*>(Al + ga);
            uint4 w1 = *reinterpret_cast<const uint4*>(Al + ga + 8);
            *reinterpret_cast<uint4*>((char*)Asl + so)      = w0;
            *reinterpret_cast<uint4*>((char*)Asl + so + 16) = w1;
        }
        {
            const size_t gb = (size_t)(kt * 32 + bk) * HID + blockCol + bj * 8;
            const uint32_t so = (uint32_t)(bk * 144 + bj * 16);
            uint4 v = *reinterpret_cast<const uint4*>(Wh + gb);
            *reinterpret_cast<uint4*>((char*)Bsh + so) = v;
            uint4 w = *reinterpret_cast<const uint4*>(Wl + gb);
            *reinterpret_cast<uint4*>((char*)Bsl + so) = w;
        }
        __syncthreads();

#pragma unroll
        for (int ks = 0; ks < 2; ks++) {
            uint32_t ah[2][4], al[2][4], bh[2][4], bl[2][4];
#pragma unroll
            for (int mi = 0; mi < 2; mi++) {
                LDSM_X4(ah[mi], sAh + aoff + mi * 16 * 80 + ks * 32);
                LDSM_X4(al[mi], sAl + aoff + mi * 16 * 80 + ks * 32);
            }
#pragma unroll
            for (int ni = 0; ni < 2; ni++) {
                LDSM_X4_T(bh[ni], sBh + boff + ks * 16 * 144 + ni * 32);
                LDSM_X4_T(bl[ni], sBl + boff + ks * 16 * 144 + ni * 32);
            }
#pragma unroll
            for (int mi = 0; mi < 2; mi++) {
#pragma unroll
                for (int nt = 0; nt < 4; nt++) {
                    const int ni = nt >> 1;
                    const int sel = (nt & 1) * 2;
                    MMA_BF16(acc[mi][nt], ah[mi], bh[ni][sel], bh[ni][sel + 1]);
                    MMA_BF16(acc[mi][nt], ah[mi], bl[ni][sel], bl[ni][sel + 1]);
                    MMA_BF16(acc[mi][nt], al[mi], bh[ni][sel], bh[ni][sel + 1]);
                }
            }
        }
        __syncthreads();
    }

#pragma unroll
    for (int mi = 0; mi < 2; mi++) {
#pragma unroll
        for (int nt = 0; nt < 4; nt++) {
            const int col = blockCol + wn + nt * 8 + (lane & 3) * 2;
            const float2 bv = *reinterpret_cast<const float2*>(bias + col);
            const int r0 = blockRow + wm + mi * 16 + (lane >> 2);
            float2 o0 = {acc[mi][nt][0] + bv.x, acc[mi][nt][1] + bv.y};
            float2 o1 = {acc[mi][nt][2] + bv.x, acc[mi][nt][3] + bv.y};
            if (RELU) {
                o0.x = fmaxf(o0.x, 0.f); o0.y = fmaxf(o0.y, 0.f);
                o1.x = fmaxf(o1.x, 0.f); o1.y = fmaxf(o1.y, 0.f);
            }
            if (OUTF) {
                *reinterpret_cast<float2*>(C + (size_t)r0 * HID + col)       = o0;
                *reinterpret_cast<float2*>(C + (size_t)(r0 + 8) * HID + col) = o1;
            }
            if (OUTH) {
                __nv_bfloat16 h0, h1, l0, l1;
                split_hl(o0.x, h0, l0); split_hl(o0.y, h1, l1);
                *reinterpret_cast<__nv_bfloat162*>(Ch + (size_t)r0 * HID + col) = __halves2bfloat162(h0, h1);
                *reinterpret_cast<__nv_bfloat162*>(Cl + (size_t)r0 * HID + col) = __halves2bfloat162(l0, l1);
                split_hl(o1.x, h0, l0); split_hl(o1.y, h1, l1);
                *reinterpret_cast<__nv_bfloat162*>(Ch + (size_t)(r0 + 8) * HID + col) = __halves2bfloat162(h0, h1);
                *reinterpret_cast<__nv_bfloat162*>(Cl + (size_t)(r0 + 8) * HID + col) = __halves2bfloat162(l0, l1);
            }
        }
    }
}

// ---------------------------------------------------------------------------
// Scores MMA: S[bh,q,s] = 0.125 * sum_d Q[q,d] K[s,d]  (hi/lo 3-product)
// BM=128 (q), BN=64 (s), BK=32 (d). B = K tile, row-major [s][d] -> non-trans ldmatrix.
// ---------------------------------------------------------------------------
__global__ __launch_bounds__(256)
void scores_mma(const __nv_bfloat16* __restrict__ Qh,
                const __nv_bfloat16* __restrict__ Ql,
                const __nv_bfloat16* __restrict__ Kh,
                const __nv_bfloat16* __restrict__ Kl,
                float* __restrict__ SC) {
    __shared__ __nv_bfloat16 Ash[128 * 40];
    __shared__ __nv_bfloat16 Asl[128 * 40];
    __shared__ __nv_bfloat16 Bsh[64 * 40];
    __shared__ __nv_bfloat16 Bsl[64 * 40];

    const int bh = blockIdx.z;
    const int b = bh / NHEAD, h = bh % NHEAD;
    const int q0 = blockIdx.y * 128;
    const int s0 = blockIdx.x * 64;

    const __nv_bfloat16* Qhp = Qh + (size_t)(b * SEQ) * HID + h * HDIM;
    const __nv_bfloat16* Qlp = Ql + (size_t)(b * SEQ) * HID + h * HDIM;
    const __nv_bfloat16* Khp = Kh + (size_t)(b * SEQ) * HID + h * HDIM;
    const __nv_bfloat16* Klp = Kl + (size_t)(b * SEQ) * HID + h * HDIM;
    float* S = SC + (size_t)bh * SEQ * SEQ;

    const int tid = threadIdx.x;
    const int wid = tid >> 5;
    const int lane = tid & 31;
    const int wm = (wid & 3) * 32;
    const int wn = (wid >> 2) * 32;

    float acc[2][4][4];
#pragma unroll
    for (int i = 0; i < 2; i++)
#pragma unroll
        for (int j = 0; j < 4; j++)
#pragma unroll
            for (int q = 0; q < 4; q++) acc[i][j][q] = 0.0f;

    const uint32_t sAh = smem_u32(Ash);
    const uint32_t sAl = smem_u32(Asl);
    const uint32_t sBh = smem_u32(Bsh);
    const uint32_t sBl = smem_u32(Bsl);

    const int arow = tid >> 1;
    const int ahalf = tid & 1;
    const int brow = tid >> 2;          // 0..63
    const int bg = (tid & 3) * 8;       // d group

    const uint32_t aoff = (uint32_t)((wm + (lane & 15)) * 80 + (lane >> 4) * 16);
    // B non-trans: two 16-row groups at wn, wn+16
    const uint32_t boff = (uint32_t)((wn + (lane & 15)) * 80 + (lane >> 4) * 16);

    for (int kt = 0; kt < HDIM / 32; kt++) {
        {
            const size_t ga = (size_t)(q0 + arow) * HID + kt * 32 + ahalf * 16;
            const uint32_t so = (uint32_t)(arow * 80 + ahalf * 32);
            uint4 v0 = *reinterpret_cast<const uint4*>(Qhp + ga);
            uint4 v1 = *reinterpret_cast<const uint4*>(Qhp + ga + 8);
            *reinterpret_cast<uint4*>((char*)Ash + so)      = v0;
            *reinterpret_cast<uint4*>((char*)Ash + so + 16) = v1;
            uint4 w0 = *reinterpret_cast<const uint4*>(Qlp + ga);
            uint4 w1 = *reinterpret_cast<const uint4*>(Qlp + ga + 8);
            *reinterpret_cast<uint4*>((char*)Asl + so)      = w0;
            *reinterpret_cast<uint4*>((char*)Asl + so + 16) = w1;
        }
        {
            const size_t gb = (size_t)(s0 + brow) * HID + kt * 32 + bg;
            const uint32_t so = (uint32_t)(brow * 80 + bg * 2);
            uint4 v = *reinterpret_cast<const uint4*>(Khp + gb);
            *reinterpret_cast<uint4*>((char*)Bsh + so) = v;
            uint4 w = *reinterpret_cast<const uint4*>(Klp + gb);
            *reinterpret_cast<uint4*>((char*)Bsl + so) = w;
        }
        __syncthreads();

#pragma unroll
        for (int ks = 0; ks < 2; ks++) {
            uint32_t ah[2][4], al[2][4], bh2[2][4], bl2[2][4];
#pragma unroll
            for (int mi = 0; mi < 2; mi++) {
                LDSM_X4(ah[mi], sAh + aoff + mi * 16 * 80 + ks * 32);
                LDSM_X4(al[mi], sAl + aoff + mi * 16 * 80 + ks * 32);
            }
#pragma unroll
            for (int g = 0; g < 2; g++) {
                LDSM_X4(bh2[g], sBh + boff + g * 16 * 80 + ks * 32);
                LDSM_X4(bl2[g], sBl + boff + g * 16 * 80 + ks * 32);
            }
#pragma unroll
            for (int mi = 0; mi < 2; mi++) {
#pragma unroll
                for (int nt = 0; nt < 4; nt++) {
                    const int g = nt >> 1;
                    const int sel = nt & 1;   // frag = {r[sel], r[sel+2]}
                    MMA_BF16(acc[mi][nt], ah[mi], bh2[g][sel], bh2[g][sel + 2]);
                    MMA_BF16(acc[mi][nt], ah[mi], bl2[g][sel], bl2[g][sel + 2]);
                    MMA_BF16(acc[mi][nt], al[mi], bh2[g][sel], bh2[g][sel + 2]);
                }
            }
        }
        __syncthreads();
    }

#pragma unroll
    for (int mi = 0; mi < 2; mi++) {
#pragma unroll
        for (int nt = 0; nt < 4; nt++) {
            const int col = s0 + wn + nt * 8 + (lane & 3) * 2;
            const int r0 = q0 + wm + mi * 16 + (lane >> 2);
            float2 o0 = {acc[mi][nt][0] * 0.125f, acc[mi][nt][1] * 0.125f};
            float2 o1 = {acc[mi][nt][2] * 0.125f, acc[mi][nt][3] * 0.125f};
            *reinterpret_cast<float2*>(S + (size_t)r0 * SEQ + col)       = o0;
            *reinterpret_cast<float2*>(S + (size_t)(r0 + 8) * SEQ + col) = o1;
        }
    }
}

// ---------------------------------------------------------------------------
// Softmax over last dim (512) -> bf16 hi/lo P
// ---------------------------------------------------------------------------
__global__ __launch_bounds__(256)
void softmax_kernel(const float* __restrict__ SC,
                    __nv_bfloat16* __restrict__ PH,
                    __nv_bfloat16* __restrict__ PL) {
    const size_t rowoff = (size_t)blockIdx.x * SEQ;
    const float* row = SC + rowoff;
    const int tid = threadIdx.x;

    float2 v = *reinterpret_cast<const float2*>(row + tid * 2);
    __shared__ float red[256];

    red[tid] = fmaxf(v.x, v.y);
    __syncthreads();
#pragma unroll
    for (int s = 128; s > 0; s >>= 1) {
        if (tid < s) red[tid] = fmaxf(red[tid], red[tid + s]);
        __syncthreads();
    }
    const float m = red[0];
    __syncthreads();

    v.x = __expf(v.x - m);
    v.y = __expf(v.y - m);
    red[tid] = v.x + v.y;
    __syncthreads();
#pragma unroll
    for (int s = 128; s > 0; s >>= 1) {
        if (tid < s) red[tid] += red[tid + s];
        __syncthreads();
    }
    const float inv = 1.0f / red[0];
    v.x *= inv;
    v.y *= inv;

    __nv_bfloat16 h0, h1, l0, l1;
    split_hl(v.x, h0, l0);
    split_hl(v.y, h1, l1);
    *reinterpret_cast<__nv_bfloat162*>(PH + rowoff + tid * 2) = __halves2bfloat162(h0, h1);
    *reinterpret_cast<__nv_bfloat162*>(PL + rowoff + tid * 2) = __halves2bfloat162(l0, l1);
}

// ---------------------------------------------------------------------------
// Context MMA: CTX[q,d] = sum_s P[q,s] V[s,d] -> bf16 hi/lo out
// BM=128 (q), BN=64 (d), BK=32 (s), 16 chunks. V via trans ldmatrix.
// ---------------------------------------------------------------------------
__global__ __launch_bounds__(256)
void ctx_mma(const __nv_bfloat16* __restrict__ PH,
             const __nv_bfloat16* __restrict__ PL,
             const __nv_bfloat16* __restrict__ Vh,
             const __nv_bfloat16* __restrict__ Vl,
             __nv_bfloat16* __restrict__ Ch,
             __nv_bfloat16* __restrict__ Cl) {
    __shared__ __nv_bfloat16 Ash[128 * 40];
    __shared__ __nv_bfloat16 Asl[128 * 40];
    __shared__ __nv_bfloat16 Bsh[32 * 72];
    __shared__ __nv_bfloat16 Bsl[32 * 72];

    const int bh = blockIdx.y;
    const int b = bh / NHEAD, h = bh % NHEAD;
    const int q0 = blockIdx.x * 128;

    const __nv_bfloat16* Php = PH + (size_t)bh * SEQ * SEQ;
    const __nv_bfloat16* Plp = PL + (size_t)bh * SEQ * SEQ;
    const __nv_bfloat16* Vhp = Vh + (size_t)(b * SEQ) * HID + h * HDIM;
    const __nv_bfloat16* Vlp = Vl + (size_t)(b * SEQ) * HID + h * HDIM;
    __nv_bfloat16* Chp = Ch + (size_t)(b * SEQ) * HID + h * HDIM;
    __nv_bfloat16* Clp = Cl + (size_t)(b * SEQ) * HID + h * HDIM;

    const int tid = threadIdx.x;
    const int wid = tid >> 5;
    const int lane = tid & 31;
    const int wm = (wid & 3) * 32;
    const int wn = (wid >> 2) * 32;

    float acc[2][4][4];
#pragma unroll
    for (int i = 0; i < 2; i++)
#pragma unroll
        for (int j = 0; j < 4; j++)
#pragma unroll
            for (int q = 0; q < 4; q++) acc[i][j][q] = 0.0f;

    const uint32_t sAh = smem_u32(Ash);
    const uint32_t sAl = smem_u32(Asl);
    const uint32_t sBh = smem_u32(Bsh);
    const uint32_t sBl = smem_u32(Bsl);

    const int arow = tid >> 1;
    const int ahalf = tid & 1;
    const int bk = tid >> 3;
    const int bj = tid & 7;

    const uint32_t aoff = (uint32_t)((wm + (lane & 15)) * 80 + (lane >> 4) * 16);
    const uint32_t boff = (uint32_t)(((lane & 7) + ((lane >> 3) & 1) * 8) * 144
                                     + (wn + (lane >> 4) * 8) * 2);

    for (int kt = 0; kt < SEQ / 32; kt++) {
        {
            const size_t ga = (size_t)(q0 + arow) * SEQ + kt * 32 + ahalf * 16;
            const uint32_t so = (uint32_t)(arow * 80 + ahalf * 32);
            uint4 v0 = *reinterpret_cast<const uint4*>(Php + ga);
            uint4 v1 = *reinterpret_cast<const uint4*>(Php + ga + 8);
            *reinterpret_cast<uint4*>((char*)Ash + so)      = v0;
            *reinterpret_cast<uint4*>((char*)Ash + so + 16) = v1;
            uint4 w0 = *reinterpret_cast<const uint4*>(Plp + ga);
            uint4 w1 = *reinterpret_cast<const uint4*>(Plp + ga + 8);
            *reinterpret_cast<uint4*>((char*)Asl + so)      = w0;
            *reinterpret_cast<uint4*>((char*)Asl + so + 16) = w1;
        }
        {
            const size_t gb = (size_t)(kt * 32 + bk) * HID + bj * 8;
            const uint32_t so = (uint32_t)(bk * 144 + bj * 16);
            uint4 v = *reinterpret_cast<const uint4*>(Vhp + gb);
            *reinterpret_cast<uint4*>((char*)Bsh + so) = v;
            uint4 w = *reinterpret_cast<const uint4*>(Vlp + gb);
            *reinterpret_cast<uint4*>((char*)Bsl + so) = w;
        }
        __syncthreads();

#pragma unroll
        for (int ks = 0; ks < 2; ks++) {
            uint32_t ah[2][4], al[2][4], bh2[2][4], bl2[2][4];
#pragma unroll
            for (int mi = 0; mi < 2; mi++) {
                LDSM_X4(ah[mi], sAh + aoff + mi * 16 * 80 + ks * 32);
                LDSM_X4(al[mi], sAl + aoff + mi * 16 * 80 + ks * 32);
            }
#pragma unroll
            for (int ni = 0; ni < 2; ni++) {
                LDSM_X4_T(bh2[ni], sBh + boff + ks * 16 * 144 + ni * 32);
                LDSM_X4_T(bl2[ni], sBl + boff + ks * 16 * 144 + ni * 32);
            }
#pragma unroll
            for (int mi = 0; mi < 2; mi++) {
#pragma unroll
                for (int nt = 0; nt < 4; nt++) {
                    const int ni = nt >> 1;
                    const int sel = (nt & 1) * 2;
                    MMA_BF16(acc[mi][nt], ah[mi], bh2[ni][sel], bh2[ni][sel + 1]);
                    MMA_BF16(acc[mi][nt], ah[mi], bl2[ni][sel], bl2[ni][sel + 1]);
                    MMA_BF16(acc[mi][nt], al[mi], bh2[ni][sel], bh2[ni][sel + 1]);
                }
            }
        }
        __syncthreads();
    }

#pragma unroll
    for (int mi = 0; mi < 2; mi++) {
#pragma unroll
        for (int nt = 0; nt < 4; nt++) {
            const int col = wn + nt * 8 + (lane & 3) * 2;
            const int r0 = q0 + wm + mi * 16 + (lane >> 2);
            __nv_bfloat16 h0, h1, l0, l1;
            split_hl(acc[mi][nt][0], h0, l0);
            split_hl(acc[mi][nt][1], h1, l1);
            *reinterpret_cast<__nv_bfloat162*>(Chp + (size_t)r0 * HID + col) = __halves2bfloat162(h0, h1);
            *reinterpret_cast<__nv_bfloat162*>(Clp + (size_t)r0 * HID + col) = __halves2bfloat162(l0, l1);
            split_hl(acc[mi][nt][2], h0, l0);
            split_hl(acc[mi][nt][3], h1, l1);
            *reinterpret_cast<__nv_bfloat162*>(Chp + (size_t)(r0 + 8) * HID + col) = __halves2bfloat162(h0, h1);
            *reinterpret_cast<__nv_bfloat162*>(Clp + (size_t)(r0 + 8) * HID + col) = __halves2bfloat162(l0, l1);
        }
    }
}

// ---------------------------------------------------------------------------
// Add + LayerNorm -> fp32 out + bf16 hi/lo out
// ---------------------------------------------------------------------------
__global__ __launch_bounds__(256)
void add_ln_kernel(const float* __restrict__ X,
                   const float* __restrict__ Y,
                   const float* __restrict__ g,
                   const float* __restrict__ b,
                   float* __restrict__ O,
                   __nv_bfloat16* __restrict__ Oh,
                   __nv_bfloat16* __restrict__ Ol) {
    const int row = blockIdx.x;
    const float* xr = X + (size_t)row * HID;
    const float* yr = Y + (size_t)row * HID;
    float* orow = O + (size_t)row * HID;
    __nv_bfloat16* ohr = Oh + (size_t)row * HID;
    __nv_bfloat16* olr = Ol + (size_t)row * HID;
    const int tid = threadIdx.x;

    float vals[3];
    float s = 0.f, ss = 0.f;
#pragma unroll
    for (int t = 0; t < 3; t++) {
        const int c = tid + t * 256;
        float v = xr[c] + yr[c];
        vals[t] = v;
        s += v;
        ss += v * v;
    }

    __shared__ float rs[256];
    __shared__ float rss[256];
    rs[tid] = s;
    rss[tid] = ss;
    __syncthreads();
#pragma unroll
    for (int st = 128; st > 0; st >>= 1) {
        if (tid < st) {
            rs[tid] += rs[tid + st];
            rss[tid] += rss[tid + st];
        }
        __syncthreads();
    }
    const float mean = rs[0] * (1.0f / HID);
    const float var = rss[0] * (1.0f / HID) - mean * mean;
    const float inv = rsqrtf(var + 1e-12f);

#pragma unroll
    for (int t = 0; t < 3; t++) {
        const int c = tid + t * 256;
        const float o = (vals[t] - mean) * inv * g[c] + b[c];
        orow[c] = o;
        __nv_bfloat16 h, l;
        split_hl(o, h, l);
        ohr[c] = h;
        olr[c] = l;
    }
}

// ---------------------------------------------------------------------------
// Launch
// ---------------------------------------------------------------------------
extern "C" void kernel_launch(void* const* d_in, const int* in_sizes, int n_in,
                              void* d_out, int out_size) {
    const float* x    = (const float*)d_in[0];
    const float* Wq   = (const float*)d_in[1];
    const float* bq   = (const float*)d_in[2];
    const float* Wk   = (const float*)d_in[3];
    const float* bk   = (const float*)d_in[4];
    const float* Wv   = (const float*)d_in[5];
    const float* bv   = (const float*)d_in[6];
    const float* Wo   = (const float*)d_in[7];
    const float* bo   = (const float*)d_in[8];
    const float* g1   = (const float*)d_in[9];
    const float* be1  = (const float*)d_in[10];
    const float* W2   = (const float*)d_in[11];
    const float* b2   = (const float*)d_in[12];
    const float* g2   = (const float*)d_in[13];
    const float* be2  = (const float*)d_in[14];

    float *X, *T1, *T2, *SC;
    cudaGetSymbolAddress((void**)&X,  g_X);
    cudaGetSymbolAddress((void**)&T1, g_T1);
    cudaGetSymbolAddress((void**)&T2, g_T2);
    cudaGetSymbolAddress((void**)&SC, g_SC);

    __nv_bfloat16 *XH, *XL, *QH, *QL, *KH, *KL, *VH, *VL, *CH, *CL, *TH, *TL, *UH, *UL, *PH, *PL;
    cudaGetSymbolAddress((void**)&XH, g_XH); cudaGetSymbolAddress((void**)&XL, g_XL);
    cudaGetSymbolAddress((void**)&QH, g_QH); cudaGetSymbolAddress((void**)&QL, g_QL);
    cudaGetSymbolAddress((void**)&KH, g_KH); cudaGetSymbolAddress((void**)&KL, g_KL);
    cudaGetSymbolAddress((void**)&VH, g_VH); cudaGetSymbolAddress((void**)&VL, g_VL);
    cudaGetSymbolAddress((void**)&CH, g_CH); cudaGetSymbolAddress((void**)&CL, g_CL);
    cudaGetSymbolAddress((void**)&TH, g_TH); cudaGetSymbolAddress((void**)&TL, g_TL);
    cudaGetSymbolAddress((void**)&UH, g_UH); cudaGetSymbolAddress((void**)&UL, g_UL);
    cudaGetSymbolAddress((void**)&PH, g_PH); cudaGetSymbolAddress((void**)&PL, g_PL);

    __nv_bfloat16 *WqH, *WqL, *WkH, *WkL, *WvH, *WvL, *WoH, *WoL, *W2H, *W2L;
    cudaGetSymbolAddress((void**)&WqH, g_WqH); cudaGetSymbolAddress((void**)&WqL, g_WqL);
    cudaGetSymbolAddress((void**)&WkH, g_WkH); cudaGetSymbolAddress((void**)&WkL, g_WkL);
    cudaGetSymbolAddress((void**)&WvH, g_WvH); cudaGetSymbolAddress((void**)&WvL, g_WvL);
    cudaGetSymbolAddress((void**)&WoH, g_WoH); cudaGetSymbolAddress((void**)&WoL, g_WoL);
    cudaGetSymbolAddress((void**)&W2H, g_W2H); cudaGetSymbolAddress((void**)&W2L, g_W2L);

    cudaMemcpyAsync(X, x, (size_t)MH * sizeof(float), cudaMemcpyDeviceToDevice);

    const int wN4 = WELEMS / 4;
    const int wGrid = (wN4 + 255) / 256;
    conv_hl<<<wGrid, 256>>>(Wq, WqH, WqL, wN4);
    conv_hl<<<wGrid, 256>>>(Wk, WkH, WkL, wN4);
    conv_hl<<<wGrid, 256>>>(Wv, WvH, WvL, wN4);
    conv_hl<<<wGrid, 256>>>(Wo, WoH, WoL, wN4);
    conv_hl<<<wGrid, 256>>>(W2, W2H, W2L, wN4);

    const int aN4 = MH / 4;
    const int aGrid = (aN4 + 255) / 256;
    conv_hl<<<aGrid, 256>>>(X, XH, XL, aN4);

    const dim3 gemmGrid(HID / 64, MROWS / 128);              // (12, 32)
    const dim3 scGrid(SEQ / 64, SEQ / 128, BATCH * NHEAD);   // (8, 4, 96)
    const dim3 cxGrid(SEQ / 128, BATCH * NHEAD);             // (4, 96)

    for (int l = 0; l < NLAYERS; l++) {
        const size_t wo = (size_t)l * HID * HID;
        const size_t vo = (size_t)l * HID;

        gemm_mma<false, false, true><<<gemmGrid, 256>>>(XH, XL, WqH + wo, WqL + wo, bq + vo, nullptr, QH, QL);
        gemm_mma<false, false, true><<<gemmGrid, 256>>>(XH, XL, WkH + wo, WkL + wo, bk + vo, nullptr, KH, KL);
        gemm_mma<false, false, true><<<gemmGrid, 256>>>(XH, XL, WvH + wo, WvL + wo, bv + vo, nullptr, VH, VL);

        scores_mma<<<scGrid, 256>>>(QH, QL, KH, KL, SC);
        softmax_kernel<<<BATCH * NHEAD * SEQ, 256>>>(SC, PH, PL);
        ctx_mma<<<cxGrid, 256>>>(PH, PL, VH, VL, CH, CL);

        gemm_mma<false, true, false><<<gemmGrid, 256>>>(CH, CL, WoH + wo, WoL + wo, bo + vo, T1, nullptr, nullptr);
        add_ln_kernel<<<MROWS, 256>>>(X, T1, g1 + vo, be1 + vo, T2, TH, TL);

        gemm_mma<true, false, true><<<gemmGrid, 256>>>(TH, TL, W2H + wo, W2L + wo, b2 + vo, nullptr, UH, UL);
        gemm_mma<true, true, false><<<gemmGrid, 256>>>(UH, UL, W2H + wo, W2L + wo, b2 + vo, T1, nullptr, nullptr);
        add_ln_kernel<<<MROWS, 256>>>(T2, T1, g2 + vo, be2 + vo, X, XH, XL);
    }

    cudaMemcpyAsync(d_out, X, (size_t)MH * sizeof(float), cudaMemcpyDeviceToDevice);
}

// round 10
// speedup vs baseline: 2.9051x; 1.3560x over previous
#include <cuda_runtime.h>
#include <cuda_bf16.h>
#include <math.h>
#include <stdint.h>

// Problem constants
#define NLAYERS 12
#define BATCH   8
#define SEQ     512
#define HID     768
#define NHEAD   12
#define HDIM    64
#define MROWS   (BATCH * SEQ)      // 4096
#define MH      (MROWS * HID)
#define SCELEMS (BATCH * NHEAD * SEQ * SEQ)
#define WELEMS  (NLAYERS * HID * HID)

// fp32 scratch
__device__ float g_X[MH];
__device__ float g_T1[MH];
__device__ float g_T2[MH];
__device__ float g_SC[SCELEMS];

// bf16 hi/lo scratch (activations)
__device__ __nv_bfloat16 g_XH[MH],  g_XL[MH];
__device__ __nv_bfloat16 g_QH[MH],  g_QL[MH];
__device__ __nv_bfloat16 g_KH[MH],  g_KL[MH];
__device__ __nv_bfloat16 g_VH[MH],  g_VL[MH];
__device__ __nv_bfloat16 g_CH[MH],  g_CL[MH];
__device__ __nv_bfloat16 g_TH[MH],  g_TL[MH];
__device__ __nv_bfloat16 g_UH[MH],  g_UL[MH];
__device__ __nv_bfloat16 g_PH[SCELEMS];

// bf16 hi/lo weights
__device__ __nv_bfloat16 g_WqH[WELEMS], g_WqL[WELEMS];
__device__ __nv_bfloat16 g_WkH[WELEMS], g_WkL[WELEMS];
__device__ __nv_bfloat16 g_WvH[WELEMS], g_WvL[WELEMS];
__device__ __nv_bfloat16 g_WoH[WELEMS], g_WoL[WELEMS];
__device__ __nv_bfloat16 g_W2H[WELEMS], g_W2L[WELEMS];

// ---------------------------------------------------------------------------
// helpers
// ---------------------------------------------------------------------------
__device__ __forceinline__ uint32_t smem_u32(const void* p) {
    uint32_t a;
    asm("{ .reg .u64 t; cvta.to.shared.u64 t, %1; cvt.u32.u64 %0, t; }"
        : "=r"(a) : "l"(p));
    return a;
}

#define LDSM_X4(r, addr) \
    asm volatile("ldmatrix.sync.aligned.m8n8.x4.shared.b16 {%0,%1,%2,%3}, [%4];" \
        : "=r"((r)[0]), "=r"((r)[1]), "=r"((r)[2]), "=r"((r)[3]) : "r"(addr))

#define LDSM_X4_T(r, addr) \
    asm volatile("ldmatrix.sync.aligned.m8n8.x4.trans.shared.b16 {%0,%1,%2,%3}, [%4];" \
        : "=r"((r)[0]), "=r"((r)[1]), "=r"((r)[2]), "=r"((r)[3]) : "r"(addr))

#define MMA_BF16(d, a, b0, b1) \
    asm volatile("mma.sync.aligned.m16n8k16.row.col.f32.bf16.bf16.f32 " \
        "{%0,%1,%2,%3}, {%4,%5,%6,%7}, {%8,%9}, {%0,%1,%2,%3};" \
        : "+f"((d)[0]), "+f"((d)[1]), "+f"((d)[2]), "+f"((d)[3]) \
        : "r"((a)[0]), "r"((a)[1]), "r"((a)[2]), "r"((a)[3]), "r"(b0), "r"(b1))

#define CP_ASYNC16(dst, src) \
    asm volatile("cp.async.ca.shared.global [%0], [%1], 16;" :: "r"(dst), "l"(src))
#define CP_COMMIT() asm volatile("cp.async.commit_group;" ::: "memory")
#define CP_WAIT(n)  asm volatile("cp.async.wait_group %0;" :: "n"(n) : "memory")

__device__ __forceinline__ void split_hl(float v, __nv_bfloat16& h, __nv_bfloat16& l) {
    h = __float2bfloat16(v);
    l = __float2bfloat16(v - __bfloat162float(h));
}

// ---------------------------------------------------------------------------
// fp32 -> bf16 hi/lo conversion (weights + initial X)
// ---------------------------------------------------------------------------
__global__ __launch_bounds__(256)
void conv_hl(const float* __restrict__ s,
             __nv_bfloat16* __restrict__ h,
             __nv_bfloat16* __restrict__ l,
             int n4) {
    int i = blockIdx.x * 256 + threadIdx.x;
    if (i >= n4) return;
    float4 v = reinterpret_cast<const float4*>(s)[i];
    __nv_bfloat16 h0, h1, h2, h3, l0, l1, l2, l3;
    split_hl(v.x, h0, l0); split_hl(v.y, h1, l1);
    split_hl(v.z, h2, l2); split_hl(v.w, h3, l3);
    reinterpret_cast<__nv_bfloat162*>(h)[2 * i]     = __halves2bfloat162(h0, h1);
    reinterpret_cast<__nv_bfloat162*>(h)[2 * i + 1] = __halves2bfloat162(h2, h3);
    reinterpret_cast<__nv_bfloat162*>(l)[2 * i]     = __halves2bfloat162(l0, l1);
    reinterpret_cast<__nv_bfloat162*>(l)[2 * i + 1] = __halves2bfloat162(l2, l3);
}

// ---------------------------------------------------------------------------
// bf16 split-precision GEMM with cp.async double buffering.
// BM=128, BN=64, BK=32, 8 warps (4x2), warp 32x32. 3-product hi/lo.
// Dynamic smem layout (bytes):
//   AH: st*10240,  AL: 20480+st*10240,  BH: 40960+st*4608,  BL: 50176+st*4608
// ---------------------------------------------------------------------------
#define G_AH(st) ((st) * 10240)
#define G_AL(st) (20480 + (st) * 10240)
#define G_BH(st) (40960 + (st) * 4608)
#define G_BL(st) (50176 + (st) * 4608)
#define GEMM_SMEM 59392

template <bool RELU, bool OUTF, bool OUTH>
__global__ __launch_bounds__(256)
void gemm_mma(const __nv_bfloat16* __restrict__ Ah,
              const __nv_bfloat16* __restrict__ Al,
              const __nv_bfloat16* __restrict__ Wh,
              const __nv_bfloat16* __restrict__ Wl,
              const float* __restrict__ bias,
              float* __restrict__ C,
              __nv_bfloat16* __restrict__ Ch,
              __nv_bfloat16* __restrict__ Cl) {
    extern __shared__ char dynsm[];
    const uint32_t sb = smem_u32(dynsm);

    const int tid = threadIdx.x;
    const int wid = tid >> 5;
    const int lane = tid & 31;
    const int blockRow = blockIdx.y * 128;
    const int blockCol = blockIdx.x * 64;
    const int wm = (wid & 3) * 32;
    const int wn = (wid >> 2) * 32;

    float acc[2][4][4];
#pragma unroll
    for (int i = 0; i < 2; i++)
#pragma unroll
        for (int j = 0; j < 4; j++)
#pragma unroll
            for (int q = 0; q < 4; q++) acc[i][j][q] = 0.0f;

    const int arow = tid >> 1;
    const int ahalf = tid & 1;
    const int bk = tid >> 3;
    const int bj = tid & 7;

    const uint32_t aso = (uint32_t)(arow * 80 + ahalf * 32);
    const uint32_t bso = (uint32_t)(bk * 144 + bj * 16);

    const uint32_t aoff = (uint32_t)((wm + (lane & 15)) * 80 + (lane >> 4) * 16);
    const uint32_t boff = (uint32_t)(((lane & 7) + ((lane >> 3) & 1) * 8) * 144
                                     + (wn + (lane >> 4) * 8) * 2);

    const int NT = HID / 32;

    // prefetch tile 0 into stage 0
    {
        const size_t ga = (size_t)(blockRow + arow) * HID + ahalf * 16;
        const size_t gb = (size_t)bk * HID + blockCol + bj * 8;
        CP_ASYNC16(sb + G_AH(0) + aso,      Ah + ga);
        CP_ASYNC16(sb + G_AH(0) + aso + 16, Ah + ga + 8);
        CP_ASYNC16(sb + G_AL(0) + aso,      Al + ga);
        CP_ASYNC16(sb + G_AL(0) + aso + 16, Al + ga + 8);
        CP_ASYNC16(sb + G_BH(0) + bso, Wh + gb);
        CP_ASYNC16(sb + G_BL(0) + bso, Wl + gb);
        CP_COMMIT();
    }

    for (int kt = 0; kt < NT; kt++) {
        const int st = kt & 1;
        if (kt + 1 < NT) {
            const int ns = st ^ 1;
            const size_t ga = (size_t)(blockRow + arow) * HID + (kt + 1) * 32 + ahalf * 16;
            const size_t gb = (size_t)((kt + 1) * 32 + bk) * HID + blockCol + bj * 8;
            CP_ASYNC16(sb + G_AH(ns) + aso,      Ah + ga);
            CP_ASYNC16(sb + G_AH(ns) + aso + 16, Ah + ga + 8);
            CP_ASYNC16(sb + G_AL(ns) + aso,      Al + ga);
            CP_ASYNC16(sb + G_AL(ns) + aso + 16, Al + ga + 8);
            CP_ASYNC16(sb + G_BH(ns) + bso, Wh + gb);
            CP_ASYNC16(sb + G_BL(ns) + bso, Wl + gb);
            CP_COMMIT();
            CP_WAIT(1);
        } else {
            CP_WAIT(0);
        }
        __syncthreads();

        const uint32_t sAh = sb + G_AH(st);
        const uint32_t sAl = sb + G_AL(st);
        const uint32_t sBh = sb + G_BH(st);
        const uint32_t sBl = sb + G_BL(st);
#pragma unroll
        for (int ks = 0; ks < 2; ks++) {
            uint32_t ah[2][4], al[2][4], bh[2][4], bl[2][4];
#pragma unroll
            for (int mi = 0; mi < 2; mi++) {
                LDSM_X4(ah[mi], sAh + aoff + mi * 16 * 80 + ks * 32);
                LDSM_X4(al[mi], sAl + aoff + mi * 16 * 80 + ks * 32);
            }
#pragma unroll
            for (int ni = 0; ni < 2; ni++) {
                LDSM_X4_T(bh[ni], sBh + boff + ks * 16 * 144 + ni * 32);
                LDSM_X4_T(bl[ni], sBl + boff + ks * 16 * 144 + ni * 32);
            }
#pragma unroll
            for (int mi = 0; mi < 2; mi++) {
#pragma unroll
                for (int nt = 0; nt < 4; nt++) {
                    const int ni = nt >> 1;
                    const int sel = (nt & 1) * 2;
                    MMA_BF16(acc[mi][nt], ah[mi], bh[ni][sel], bh[ni][sel + 1]);
                    MMA_BF16(acc[mi][nt], ah[mi], bl[ni][sel], bl[ni][sel + 1]);
                    MMA_BF16(acc[mi][nt], al[mi], bh[ni][sel], bh[ni][sel + 1]);
                }
            }
        }
        __syncthreads();
    }

#pragma unroll
    for (int mi = 0; mi < 2; mi++) {
#pragma unroll
        for (int nt = 0; nt < 4; nt++) {
            const int col = blockCol + wn + nt * 8 + (lane & 3) * 2;
            const float2 bv = *reinterpret_cast<const float2*>(bias + col);
            const int r0 = blockRow + wm + mi * 16 + (lane >> 2);
            float2 o0 = {acc[mi][nt][0] + bv.x, acc[mi][nt][1] + bv.y};
            float2 o1 = {acc[mi][nt][2] + bv.x, acc[mi][nt][3] + bv.y};
            if (RELU) {
                o0.x = fmaxf(o0.x, 0.f); o0.y = fmaxf(o0.y, 0.f);
                o1.x = fmaxf(o1.x, 0.f); o1.y = fmaxf(o1.y, 0.f);
            }
            if (OUTF) {
                *reinterpret_cast<float2*>(C + (size_t)r0 * HID + col)       = o0;
                *reinterpret_cast<float2*>(C + (size_t)(r0 + 8) * HID + col) = o1;
            }
            if (OUTH) {
                __nv_bfloat16 h0, h1, l0, l1;
                split_hl(o0.x, h0, l0); split_hl(o0.y, h1, l1);
                *reinterpret_cast<__nv_bfloat162*>(Ch + (size_t)r0 * HID + col) = __halves2bfloat162(h0, h1);
                *reinterpret_cast<__nv_bfloat162*>(Cl + (size_t)r0 * HID + col) = __halves2bfloat162(l0, l1);
                split_hl(o1.x, h0, l0); split_hl(o1.y, h1, l1);
                *reinterpret_cast<__nv_bfloat162*>(Ch + (size_t)(r0 + 8) * HID + col) = __halves2bfloat162(h0, h1);
                *reinterpret_cast<__nv_bfloat162*>(Cl + (size_t)(r0 + 8) * HID + col) = __halves2bfloat162(l0, l1);
            }
        }
    }
}

// ---------------------------------------------------------------------------
// Scores MMA: S[bh,q,s] = 0.125 * sum_d Q[q,d] K[s,d]  (hi/lo 3-product)
// ---------------------------------------------------------------------------
__global__ __launch_bounds__(256)
void scores_mma(const __nv_bfloat16* __restrict__ Qh,
                const __nv_bfloat16* __restrict__ Ql,
                const __nv_bfloat16* __restrict__ Kh,
                const __nv_bfloat16* __restrict__ Kl,
                float* __restrict__ SC) {
    __shared__ __nv_bfloat16 Ash[128 * 40];
    __shared__ __nv_bfloat16 Asl[128 * 40];
    __shared__ __nv_bfloat16 Bsh[64 * 40];
    __shared__ __nv_bfloat16 Bsl[64 * 40];

    const int bh = blockIdx.z;
    const int b = bh / NHEAD, h = bh % NHEAD;
    const int q0 = blockIdx.y * 128;
    const int s0 = blockIdx.x * 64;

    const __nv_bfloat16* Qhp = Qh + (size_t)(b * SEQ) * HID + h * HDIM;
    const __nv_bfloat16* Qlp = Ql + (size_t)(b * SEQ) * HID + h * HDIM;
    const __nv_bfloat16* Khp = Kh + (size_t)(b * SEQ) * HID + h * HDIM;
    const __nv_bfloat16* Klp = Kl + (size_t)(b * SEQ) * HID + h * HDIM;
    float* S = SC + (size_t)bh * SEQ * SEQ;

    const int tid = threadIdx.x;
    const int wid = tid >> 5;
    const int lane = tid & 31;
    const int wm = (wid & 3) * 32;
    const int wn = (wid >> 2) * 32;

    float acc[2][4][4];
#pragma unroll
    for (int i = 0; i < 2; i++)
#pragma unroll
        for (int j = 0; j < 4; j++)
#pragma unroll
            for (int q = 0; q < 4; q++) acc[i][j][q] = 0.0f;

    const uint32_t sAh = smem_u32(Ash);
    const uint32_t sAl = smem_u32(Asl);
    const uint32_t sBh = smem_u32(Bsh);
    const uint32_t sBl = smem_u32(Bsl);

    const int arow = tid >> 1;
    const int ahalf = tid & 1;
    const int brow = tid >> 2;
    const int bg = (tid & 3) * 8;

    const uint32_t aoff = (uint32_t)((wm + (lane & 15)) * 80 + (lane >> 4) * 16);
    const uint32_t boff = (uint32_t)((wn + (lane & 15)) * 80 + (lane >> 4) * 16);

    for (int kt = 0; kt < HDIM / 32; kt++) {
        {
            const size_t ga = (size_t)(q0 + arow) * HID + kt * 32 + ahalf * 16;
            const uint32_t so = (uint32_t)(arow * 80 + ahalf * 32);
            uint4 v0 = *reinterpret_cast<const uint4*>(Qhp + ga);
            uint4 v1 = *reinterpret_cast<const uint4*>(Qhp + ga + 8);
            *reinterpret_cast<uint4*>((char*)Ash + so)      = v0;
            *reinterpret_cast<uint4*>((char*)Ash + so + 16) = v1;
            uint4 w0 = *reinterpret_cast<const uint4*>(Qlp + ga);
            uint4 w1 = *reinterpret_cast<const uint4*>(Qlp + ga + 8);
            *reinterpret_cast<uint4*>((char*)Asl + so)      = w0;
            *reinterpret_cast<uint4*>((char*)Asl + so + 16) = w1;
        }
        {
            const size_t gb = (size_t)(s0 + brow) * HID + kt * 32 + bg;
            const uint32_t so = (uint32_t)(brow * 80 + bg * 2);
            uint4 v = *reinterpret_cast<const uint4*>(Khp + gb);
            *reinterpret_cast<uint4*>((char*)Bsh + so) = v;
            uint4 w = *reinterpret_cast<const uint4*>(Klp + gb);
            *reinterpret_cast<uint4*>((char*)Bsl + so) = w;
        }
        __syncthreads();

#pragma unroll
        for (int ks = 0; ks < 2; ks++) {
            uint32_t ah[2][4], al[2][4], bh2[2][4], bl2[2][4];
#pragma unroll
            for (int mi = 0; mi < 2; mi++) {
                LDSM_X4(ah[mi], sAh + aoff + mi * 16 * 80 + ks * 32);
                LDSM_X4(al[mi], sAl + aoff + mi * 16 * 80 + ks * 32);
            }
#pragma unroll
            for (int g = 0; g < 2; g++) {
                LDSM_X4(bh2[g], sBh + boff + g * 16 * 80 + ks * 32);
                LDSM_X4(bl2[g], sBl + boff + g * 16 * 80 + ks * 32);
            }
#pragma unroll
            for (int mi = 0; mi < 2; mi++) {
#pragma unroll
                for (int nt = 0; nt < 4; nt++) {
                    const int g = nt >> 1;
                    const int sel = nt & 1;
                    MMA_BF16(acc[mi][nt], ah[mi], bh2[g][sel], bh2[g][sel + 2]);
                    MMA_BF16(acc[mi][nt], ah[mi], bl2[g][sel], bl2[g][sel + 2]);
                    MMA_BF16(acc[mi][nt], al[mi], bh2[g][sel], bh2[g][sel + 2]);
                }
            }
        }
        __syncthreads();
    }

#pragma unroll
    for (int mi = 0; mi < 2; mi++) {
#pragma unroll
        for (int nt = 0; nt < 4; nt++) {
            const int col = s0 + wn + nt * 8 + (lane & 3) * 2;
            const int r0 = q0 + wm + mi * 16 + (lane >> 2);
            float2 o0 = {acc[mi][nt][0] * 0.125f, acc[mi][nt][1] * 0.125f};
            float2 o1 = {acc[mi][nt][2] * 0.125f, acc[mi][nt][3] * 0.125f};
            *reinterpret_cast<float2*>(S + (size_t)r0 * SEQ + col)       = o0;
            *reinterpret_cast<float2*>(S + (size_t)(r0 + 8) * SEQ + col) = o1;
        }
    }
}

// ---------------------------------------------------------------------------
// Softmax: one warp per row (512), shuffle reductions -> bf16 hi P only
// ---------------------------------------------------------------------------
__global__ __launch_bounds__(256)
void softmax_kernel(const float* __restrict__ SC,
                    __nv_bfloat16* __restrict__ PH) {
    const int wid = threadIdx.x >> 5;
    const int lane = threadIdx.x & 31;
    const size_t row = (size_t)blockIdx.x * 8 + wid;
    const float* r = SC + row * SEQ;

    float4 v[4];
    float mx = -1e30f;
#pragma unroll
    for (int j = 0; j < 4; j++) {
        v[j] = *reinterpret_cast<const float4*>(r + (lane + 32 * j) * 4);
        mx = fmaxf(mx, fmaxf(fmaxf(v[j].x, v[j].y), fmaxf(v[j].z, v[j].w)));
    }
#pragma unroll
    for (int o = 16; o > 0; o >>= 1)
        mx = fmaxf(mx, __shfl_xor_sync(0xffffffffu, mx, o));

    float sum = 0.f;
#pragma unroll
    for (int j = 0; j < 4; j++) {
        v[j].x = __expf(v[j].x - mx);
        v[j].y = __expf(v[j].y - mx);
        v[j].z = __expf(v[j].z - mx);
        v[j].w = __expf(v[j].w - mx);
        sum += (v[j].x + v[j].y) + (v[j].z + v[j].w);
    }
#pragma unroll
    for (int o = 16; o > 0; o >>= 1)
        sum += __shfl_xor_sync(0xffffffffu, sum, o);
    const float inv = 1.0f / sum;

    __nv_bfloat16* ph = PH + row * SEQ;
#pragma unroll
    for (int j = 0; j < 4; j++) {
        __nv_bfloat162 a = __halves2bfloat162(__float2bfloat16(v[j].x * inv),
                                              __float2bfloat16(v[j].y * inv));
        __nv_bfloat162 b = __halves2bfloat162(__float2bfloat16(v[j].z * inv),
                                              __float2bfloat16(v[j].w * inv));
        uint2 pk;
        pk.x = *reinterpret_cast<uint32_t*>(&a);
        pk.y = *reinterpret_cast<uint32_t*>(&b);
        *reinterpret_cast<uint2*>(ph + (lane + 32 * j) * 4) = pk;
    }
}

// ---------------------------------------------------------------------------
// Context MMA with cp.async double buffering, P hi only (2-product):
// CTX[q,d] = sum_s P[q,s] V[s,d] -> bf16 hi/lo out
// Dynamic smem: PH: st*10240 (20480), VH: 20480+st*4608, VL: 29696+st*4608
// ---------------------------------------------------------------------------
#define C_PH(st) ((st) * 10240)
#define C_VH(st) (20480 + (st) * 4608)
#define C_VL(st) (29696 + (st) * 4608)
#define CTX_SMEM 38912

__global__ __launch_bounds__(256)
void ctx_mma(const __nv_bfloat16* __restrict__ PH,
             const __nv_bfloat16* __restrict__ Vh,
             const __nv_bfloat16* __restrict__ Vl,
             __nv_bfloat16* __restrict__ Ch,
             __nv_bfloat16* __restrict__ Cl) {
    extern __shared__ char dynsm[];
    const uint32_t sb = smem_u32(dynsm);

    const int bh = blockIdx.y;
    const int b = bh / NHEAD, h = bh % NHEAD;
    const int q0 = blockIdx.x * 128;

    const __nv_bfloat16* Php = PH + (size_t)bh * SEQ * SEQ;
    const __nv_bfloat16* Vhp = Vh + (size_t)(b * SEQ) * HID + h * HDIM;
    const __nv_bfloat16* Vlp = Vl + (size_t)(b * SEQ) * HID + h * HDIM;
    __nv_bfloat16* Chp = Ch + (size_t)(b * SEQ) * HID + h * HDIM;
    __nv_bfloat16* Clp = Cl + (size_t)(b * SEQ) * HID + h * HDIM;

    const int tid = threadIdx.x;
    const int wid = tid >> 5;
    const int lane = tid & 31;
    const int wm = (wid & 3) * 32;
    const int wn = (wid >> 2) * 32;

    float acc[2][4][4];
#pragma unroll
    for (int i = 0; i < 2; i++)
#pragma unroll
        for (int j = 0; j < 4; j++)
#pragma unroll
            for (int q = 0; q < 4; q++) acc[i][j][q] = 0.0f;

    const int arow = tid >> 1;
    const int ahalf = tid & 1;
    const int bk = tid >> 3;
    const int bj = tid & 7;

    const uint32_t aso = (uint32_t)(arow * 80 + ahalf * 32);
    const uint32_t bso = (uint32_t)(bk * 144 + bj * 16);

    const uint32_t aoff = (uint32_t)((wm + (lane & 15)) * 80 + (lane >> 4) * 16);
    const uint32_t boff = (uint32_t)(((lane & 7) + ((lane >> 3) & 1) * 8) * 144
                                     + (wn + (lane >> 4) * 8) * 2);

    const int NT = SEQ / 32;   // 16

    {
        const size_t ga = (size_t)(q0 + arow) * SEQ + ahalf * 16;
        const size_t gb = (size_t)bk * HID + bj * 8;
        CP_ASYNC16(sb + C_PH(0) + aso,      Php + ga);
        CP_ASYNC16(sb + C_PH(0) + aso + 16, Php + ga + 8);
        CP_ASYNC16(sb + C_VH(0) + bso, Vhp + gb);
        CP_ASYNC16(sb + C_VL(0) + bso, Vlp + gb);
        CP_COMMIT();
    }

    for (int kt = 0; kt < NT; kt++) {
        const int st = kt & 1;
        if (kt + 1 < NT) {
            const int ns = st ^ 1;
            const size_t ga = (size_t)(q0 + arow) * SEQ + (kt + 1) * 32 + ahalf * 16;
            const size_t gb = (size_t)((kt + 1) * 32 + bk) * HID + bj * 8;
            CP_ASYNC16(sb + C_PH(ns) + aso,      Php + ga);
            CP_ASYNC16(sb + C_PH(ns) + aso + 16, Php + ga + 8);
            CP_ASYNC16(sb + C_VH(ns) + bso, Vhp + gb);
            CP_ASYNC16(sb + C_VL(ns) + bso, Vlp + gb);
            CP_COMMIT();
            CP_WAIT(1);
        } else {
            CP_WAIT(0);
        }
        __syncthreads();

        const uint32_t sAh = sb + C_PH(st);
        const uint32_t sBh = sb + C_VH(st);
        const uint32_t sBl = sb + C_VL(st);
#pragma unroll
        for (int ks = 0; ks < 2; ks++) {
            uint32_t ah[2][4], bh2[2][4], bl2[2][4];
#pragma unroll
            for (int mi = 0; mi < 2; mi++)
                LDSM_X4(ah[mi], sAh + aoff + mi * 16 * 80 + ks * 32);
#pragma unroll
            for (int ni = 0; ni < 2; ni++) {
                LDSM_X4_T(bh2[ni], sBh + boff + ks * 16 * 144 + ni * 32);
                LDSM_X4_T(bl2[ni], sBl + boff + ks * 16 * 144 + ni * 32);
            }
#pragma unroll
            for (int mi = 0; mi < 2; mi++) {
#pragma unroll
                for (int nt = 0; nt < 4; nt++) {
                    const int ni = nt >> 1;
                    const int sel = (nt & 1) * 2;
                    MMA_BF16(acc[mi][nt], ah[mi], bh2[ni][sel], bh2[ni][sel + 1]);
                    MMA_BF16(acc[mi][nt], ah[mi], bl2[ni][sel], bl2[ni][sel + 1]);
                }
            }
        }
        __syncthreads();
    }

#pragma unroll
    for (int mi = 0; mi < 2; mi++) {
#pragma unroll
        for (int nt = 0; nt < 4; nt++) {
            const int col = wn + nt * 8 + (lane & 3) * 2;
            const int r0 = q0 + wm + mi * 16 + (lane >> 2);
            __nv_bfloat16 h0, h1, l0, l1;
            split_hl(acc[mi][nt][0], h0, l0);
            split_hl(acc[mi][nt][1], h1, l1);
            *reinterpret_cast<__nv_bfloat162*>(Chp + (size_t)r0 * HID + col) = __halves2bfloat162(h0, h1);
            *reinterpret_cast<__nv_bfloat162*>(Clp + (size_t)r0 * HID + col) = __halves2bfloat162(l0, l1);
            split_hl(acc[mi][nt][2], h0, l0);
            split_hl(acc[mi][nt][3], h1, l1);
            *reinterpret_cast<__nv_bfloat162*>(Chp + (size_t)(r0 + 8) * HID + col) = __halves2bfloat162(h0, h1);
            *reinterpret_cast<__nv_bfloat162*>(Clp + (size_t)(r0 + 8) * HID + col) = __halves2bfloat162(l0, l1);
        }
    }
}

// ---------------------------------------------------------------------------
// Add + LayerNorm -> fp32 out + bf16 hi/lo out
// ---------------------------------------------------------------------------
__global__ __launch_bounds__(256)
void add_ln_kernel(const float* __restrict__ X,
                   const float* __restrict__ Y,
                   const float* __restrict__ g,
                   const float* __restrict__ b,
                   float* __restrict__ O,
                   __nv_bfloat16* __restrict__ Oh,
                   __nv_bfloat16* __restrict__ Ol) {
    const int row = blockIdx.x;
    const float* xr = X + (size_t)row * HID;
    const float* yr = Y + (size_t)row * HID;
    float* orow = O + (size_t)row * HID;
    __nv_bfloat16* ohr = Oh + (size_t)row * HID;
    __nv_bfloat16* olr = Ol + (size_t)row * HID;
    const int tid = threadIdx.x;

    float vals[3];
    float s = 0.f, ss = 0.f;
#pragma unroll
    for (int t = 0; t < 3; t++) {
        const int c = tid + t * 256;
        float v = xr[c] + yr[c];
        vals[t] = v;
        s += v;
        ss += v * v;
    }

    __shared__ float rs[256];
    __shared__ float rss[256];
    rs[tid] = s;
    rss[tid] = ss;
    __syncthreads();
#pragma unroll
    for (int st = 128; st > 0; st >>= 1) {
        if (tid < st) {
            rs[tid] += rs[tid + st];
            rss[tid] += rss[tid + st];
        }
        __syncthreads();
    }
    const float mean = rs[0] * (1.0f / HID);
    const float var = rss[0] * (1.0f / HID) - mean * mean;
    const float inv = rsqrtf(var + 1e-12f);

#pragma unroll
    for (int t = 0; t < 3; t++) {
        const int c = tid + t * 256;
        const float o = (vals[t] - mean) * inv * g[c] + b[c];
        orow[c] = o;
        __nv_bfloat16 h, l;
        split_hl(o, h, l);
        ohr[c] = h;
        olr[c] = l;
    }
}

// ---------------------------------------------------------------------------
// Launch
// ---------------------------------------------------------------------------
extern "C" void kernel_launch(void* const* d_in, const int* in_sizes, int n_in,
                              void* d_out, int out_size) {
    const float* x    = (const float*)d_in[0];
    const float* Wq   = (const float*)d_in[1];
    const float* bq   = (const float*)d_in[2];
    const float* Wk   = (const float*)d_in[3];
    const float* bk   = (const float*)d_in[4];
    const float* Wv   = (const float*)d_in[5];
    const float* bv   = (const float*)d_in[6];
    const float* Wo   = (const float*)d_in[7];
    const float* bo   = (const float*)d_in[8];
    const float* g1   = (const float*)d_in[9];
    const float* be1  = (const float*)d_in[10];
    const float* W2   = (const float*)d_in[11];
    const float* b2   = (const float*)d_in[12];
    const float* g2   = (const float*)d_in[13];
    const float* be2  = (const float*)d_in[14];

    float *X, *T1, *T2, *SC;
    cudaGetSymbolAddress((void**)&X,  g_X);
    cudaGetSymbolAddress((void**)&T1, g_T1);
    cudaGetSymbolAddress((void**)&T2, g_T2);
    cudaGetSymbolAddress((void**)&SC, g_SC);

    __nv_bfloat16 *XH, *XL, *QH, *QL, *KH, *KL, *VH, *VL, *CH, *CL, *TH, *TL, *UH, *UL, *PH;
    cudaGetSymbolAddress((void**)&XH, g_XH); cudaGetSymbolAddress((void**)&XL, g_XL);
    cudaGetSymbolAddress((void**)&QH, g_QH); cudaGetSymbolAddress((void**)&QL, g_QL);
    cudaGetSymbolAddress((void**)&KH, g_KH); cudaGetSymbolAddress((void**)&KL, g_KL);
    cudaGetSymbolAddress((void**)&VH, g_VH); cudaGetSymbolAddress((void**)&VL, g_VL);
    cudaGetSymbolAddress((void**)&CH, g_CH); cudaGetSymbolAddress((void**)&CL, g_CL);
    cudaGetSymbolAddress((void**)&TH, g_TH); cudaGetSymbolAddress((void**)&TL, g_TL);
    cudaGetSymbolAddress((void**)&UH, g_UH); cudaGetSymbolAddress((void**)&UL, g_UL);
    cudaGetSymbolAddress((void**)&PH, g_PH);

    __nv_bfloat16 *WqH, *WqL, *WkH, *WkL, *WvH, *WvL, *WoH, *WoL, *W2H, *W2L;
    cudaGetSymbolAddress((void**)&WqH, g_WqH); cudaGetSymbolAddress((void**)&WqL, g_WqL);
    cudaGetSymbolAddress((void**)&WkH, g_WkH); cudaGetSymbolAddress((void**)&WkL, g_WkL);
    cudaGetSymbolAddress((void**)&WvH, g_WvH); cudaGetSymbolAddress((void**)&WvL, g_WvL);
    cudaGetSymbolAddress((void**)&WoH, g_WoH); cudaGetSymbolAddress((void**)&WoL, g_WoL);
    cudaGetSymbolAddress((void**)&W2H, g_W2H); cudaGetSymbolAddress((void**)&W2L, g_W2L);

    cudaFuncSetAttribute(gemm_mma<false, false, true>, cudaFuncAttributeMaxDynamicSharedMemorySize, GEMM_SMEM);
    cudaFuncSetAttribute(gemm_mma<false, true, false>, cudaFuncAttributeMaxDynamicSharedMemorySize, GEMM_SMEM);
    cudaFuncSetAttribute(gemm_mma<true, false, true>,  cudaFuncAttributeMaxDynamicSharedMemorySize, GEMM_SMEM);
    cudaFuncSetAttribute(gemm_mma<true, true, false>,  cudaFuncAttributeMaxDynamicSharedMemorySize, GEMM_SMEM);
    cudaFuncSetAttribute(ctx_mma, cudaFuncAttributeMaxDynamicSharedMemorySize, CTX_SMEM);

    cudaMemcpyAsync(X, x, (size_t)MH * sizeof(float), cudaMemcpyDeviceToDevice);

    const int wN4 = WELEMS / 4;
    const int wGrid = (wN4 + 255) / 256;
    conv_hl<<<wGrid, 256>>>(Wq, WqH, WqL, wN4);
    conv_hl<<<wGrid, 256>>>(Wk, WkH, WkL, wN4);
    conv_hl<<<wGrid, 256>>>(Wv, WvH, WvL, wN4);
    conv_hl<<<wGrid, 256>>>(Wo, WoH, WoL, wN4);
    conv_hl<<<wGrid, 256>>>(W2, W2H, W2L, wN4);

    const int aN4 = MH / 4;
    const int aGrid = (aN4 + 255) / 256;
    conv_hl<<<aGrid, 256>>>(X, XH, XL, aN4);

    const dim3 gemmGrid(HID / 64, MROWS / 128);              // (12, 32)
    const dim3 scGrid(SEQ / 64, SEQ / 128, BATCH * NHEAD);   // (8, 4, 96)
    const dim3 cxGrid(SEQ / 128, BATCH * NHEAD);             // (4, 96)
    const int smGrid = (BATCH * NHEAD * SEQ) / 8;            // 6144

    for (int l = 0; l < NLAYERS; l++) {
        const size_t wo = (size_t)l * HID * HID;
        const size_t vo = (size_t)l * HID;

        gemm_mma<false, false, true><<<gemmGrid, 256, GEMM_SMEM>>>(XH, XL, WqH + wo, WqL + wo, bq + vo, nullptr, QH, QL);
        gemm_mma<false, false, true><<<gemmGrid, 256, GEMM_SMEM>>>(XH, XL, WkH + wo, WkL + wo, bk + vo, nullptr, KH, KL);
        gemm_mma<false, false, true><<<gemmGrid, 256, GEMM_SMEM>>>(XH, XL, WvH + wo, WvL + wo, bv + vo, nullptr, VH, VL);

        scores_mma<<<scGrid, 256>>>(QH, QL, KH, KL, SC);
        softmax_kernel<<<smGrid, 256>>>(SC, PH);
        ctx_mma<<<cxGrid, 256, CTX_SMEM>>>(PH, VH, VL, CH, CL);

        gemm_mma<false, true, false><<<gemmGrid, 256, GEMM_SMEM>>>(CH, CL, WoH + wo, WoL + wo, bo + vo, T1, nullptr, nullptr);
        add_ln_kernel<<<MROWS, 256>>>(X, T1, g1 + vo, be1 + vo, T2, TH, TL);

        gemm_mma<true, false, true><<<gemmGrid, 256, GEMM_SMEM>>>(TH, TL, W2H + wo, W2L + wo, b2 + vo, nullptr, UH, UL);
        gemm_mma<true, true, false><<<gemmGrid, 256, GEMM_SMEM>>>(UH, UL, W2H + wo, W2L + wo, b2 + vo, T1, nullptr, nullptr);
        add_ln_kernel<<<MROWS, 256>>>(T2, T1, g2 + vo, be2 + vo, X, XH, XL);
    }

    cudaMemcpyAsync(d_out, X, (size_t)MH * sizeof(float), cudaMemcpyDeviceToDevice);
}

// round 11
// speedup vs baseline: 3.1530x; 1.0853x over previous
#include <cuda_runtime.h>
#include <cuda_bf16.h>
#include <math.h>
#include <stdint.h>

// Problem constants
#define NLAYERS 12
#define BATCH   8
#define SEQ     512
#define HID     768
#define NHEAD   12
#define HDIM    64
#define MROWS   (BATCH * SEQ)      // 4096
#define MH      (MROWS * HID)
#define WELEMS  (NLAYERS * HID * HID)

// fp32 scratch
__device__ float g_X[MH];
__device__ float g_T1[MH];
__device__ float g_T2[MH];

// bf16 hi/lo scratch (activations)
__device__ __nv_bfloat16 g_XH[MH],  g_XL[MH];
__device__ __nv_bfloat16 g_QH[MH],  g_QL[MH];
__device__ __nv_bfloat16 g_KH[MH],  g_KL[MH];
__device__ __nv_bfloat16 g_VH[MH],  g_VL[MH];
__device__ __nv_bfloat16 g_CH[MH],  g_CL[MH];
__device__ __nv_bfloat16 g_TH[MH],  g_TL[MH];
__device__ __nv_bfloat16 g_UH[MH],  g_UL[MH];

// bf16 hi/lo weights
__device__ __nv_bfloat16 g_WqH[WELEMS], g_WqL[WELEMS];
__device__ __nv_bfloat16 g_WkH[WELEMS], g_WkL[WELEMS];
__device__ __nv_bfloat16 g_WvH[WELEMS], g_WvL[WELEMS];
__device__ __nv_bfloat16 g_WoH[WELEMS], g_WoL[WELEMS];
__device__ __nv_bfloat16 g_W2H[WELEMS], g_W2L[WELEMS];

// ---------------------------------------------------------------------------
// helpers
// ---------------------------------------------------------------------------
__device__ __forceinline__ uint32_t smem_u32(const void* p) {
    uint32_t a;
    asm("{ .reg .u64 t; cvta.to.shared.u64 t, %1; cvt.u32.u64 %0, t; }"
        : "=r"(a) : "l"(p));
    return a;
}

#define LDSM_X4(r, addr) \
    asm volatile("ldmatrix.sync.aligned.m8n8.x4.shared.b16 {%0,%1,%2,%3}, [%4];" \
        : "=r"((r)[0]), "=r"((r)[1]), "=r"((r)[2]), "=r"((r)[3]) : "r"(addr))

#define LDSM_X4_T(r, addr) \
    asm volatile("ldmatrix.sync.aligned.m8n8.x4.trans.shared.b16 {%0,%1,%2,%3}, [%4];" \
        : "=r"((r)[0]), "=r"((r)[1]), "=r"((r)[2]), "=r"((r)[3]) : "r"(addr))

#define MMA_BF16(d, a, b0, b1) \
    asm volatile("mma.sync.aligned.m16n8k16.row.col.f32.bf16.bf16.f32 " \
        "{%0,%1,%2,%3}, {%4,%5,%6,%7}, {%8,%9}, {%0,%1,%2,%3};" \
        : "+f"((d)[0]), "+f"((d)[1]), "+f"((d)[2]), "+f"((d)[3]) \
        : "r"((a)[0]), "r"((a)[1]), "r"((a)[2]), "r"((a)[3]), "r"(b0), "r"(b1))

#define CP_ASYNC16(dst, src) \
    asm volatile("cp.async.ca.shared.global [%0], [%1], 16;" :: "r"(dst), "l"(src))
#define CP_COMMIT() asm volatile("cp.async.commit_group;" ::: "memory")
#define CP_WAIT(n)  asm volatile("cp.async.wait_group %0;" :: "n"(n) : "memory")

__device__ __forceinline__ void split_hl(float v, __nv_bfloat16& h, __nv_bfloat16& l) {
    h = __float2bfloat16(v);
    l = __float2bfloat16(v - __bfloat162float(h));
}

__device__ __forceinline__ float ex2_approx(float x) {
    float y;
    asm("ex2.approx.f32 %0, %1;" : "=f"(y) : "f"(x));
    return y;
}

__device__ __forceinline__ uint32_t pack_bf2(float a, float b) {
    __nv_bfloat162 p = __halves2bfloat162(__float2bfloat16(a), __float2bfloat16(b));
    return *reinterpret_cast<uint32_t*>(&p);
}

// ---------------------------------------------------------------------------
// fp32 -> bf16 hi/lo conversion (weights + initial X)
// ---------------------------------------------------------------------------
__global__ __launch_bounds__(256)
void conv_hl(const float* __restrict__ s,
             __nv_bfloat16* __restrict__ h,
             __nv_bfloat16* __restrict__ l,
             int n4) {
    int i = blockIdx.x * 256 + threadIdx.x;
    if (i >= n4) return;
    float4 v = reinterpret_cast<const float4*>(s)[i];
    __nv_bfloat16 h0, h1, h2, h3, l0, l1, l2, l3;
    split_hl(v.x, h0, l0); split_hl(v.y, h1, l1);
    split_hl(v.z, h2, l2); split_hl(v.w, h3, l3);
    reinterpret_cast<__nv_bfloat162*>(h)[2 * i]     = __halves2bfloat162(h0, h1);
    reinterpret_cast<__nv_bfloat162*>(h)[2 * i + 1] = __halves2bfloat162(h2, h3);
    reinterpret_cast<__nv_bfloat162*>(l)[2 * i]     = __halves2bfloat162(l0, l1);
    reinterpret_cast<__nv_bfloat162*>(l)[2 * i + 1] = __halves2bfloat162(l2, l3);
}

// ---------------------------------------------------------------------------
// bf16 split-precision GEMM with cp.async double buffering.
// BM=128, BN=64, BK=32, 8 warps (4x2), warp 32x32. 3-product hi/lo.
// ---------------------------------------------------------------------------
#define G_AH(st) ((st) * 10240)
#define G_AL(st) (20480 + (st) * 10240)
#define G_BH(st) (40960 + (st) * 4608)
#define G_BL(st) (50176 + (st) * 4608)
#define GEMM_SMEM 59392

template <bool RELU, bool OUTF, bool OUTH>
__global__ __launch_bounds__(256)
void gemm_mma(const __nv_bfloat16* __restrict__ Ah,
              const __nv_bfloat16* __restrict__ Al,
              const __nv_bfloat16* __restrict__ Wh,
              const __nv_bfloat16* __restrict__ Wl,
              const float* __restrict__ bias,
              float* __restrict__ C,
              __nv_bfloat16* __restrict__ Ch,
              __nv_bfloat16* __restrict__ Cl) {
    extern __shared__ char dynsm[];
    const uint32_t sb = smem_u32(dynsm);

    const int tid = threadIdx.x;
    const int wid = tid >> 5;
    const int lane = tid & 31;
    const int blockRow = blockIdx.y * 128;
    const int blockCol = blockIdx.x * 64;
    const int wm = (wid & 3) * 32;
    const int wn = (wid >> 2) * 32;

    float acc[2][4][4];
#pragma unroll
    for (int i = 0; i < 2; i++)
#pragma unroll
        for (int j = 0; j < 4; j++)
#pragma unroll
            for (int q = 0; q < 4; q++) acc[i][j][q] = 0.0f;

    const int arow = tid >> 1;
    const int ahalf = tid & 1;
    const int bk = tid >> 3;
    const int bj = tid & 7;

    const uint32_t aso = (uint32_t)(arow * 80 + ahalf * 32);
    const uint32_t bso = (uint32_t)(bk * 144 + bj * 16);

    const uint32_t aoff = (uint32_t)((wm + (lane & 15)) * 80 + (lane >> 4) * 16);
    const uint32_t boff = (uint32_t)(((lane & 7) + ((lane >> 3) & 1) * 8) * 144
                                     + (wn + (lane >> 4) * 8) * 2);

    const int NT = HID / 32;

    {
        const size_t ga = (size_t)(blockRow + arow) * HID + ahalf * 16;
        const size_t gb = (size_t)bk * HID + blockCol + bj * 8;
        CP_ASYNC16(sb + G_AH(0) + aso,      Ah + ga);
        CP_ASYNC16(sb + G_AH(0) + aso + 16, Ah + ga + 8);
        CP_ASYNC16(sb + G_AL(0) + aso,      Al + ga);
        CP_ASYNC16(sb + G_AL(0) + aso + 16, Al + ga + 8);
        CP_ASYNC16(sb + G_BH(0) + bso, Wh + gb);
        CP_ASYNC16(sb + G_BL(0) + bso, Wl + gb);
        CP_COMMIT();
    }

    for (int kt = 0; kt < NT; kt++) {
        const int st = kt & 1;
        if (kt + 1 < NT) {
            const int ns = st ^ 1;
            const size_t ga = (size_t)(blockRow + arow) * HID + (kt + 1) * 32 + ahalf * 16;
            const size_t gb = (size_t)((kt + 1) * 32 + bk) * HID + blockCol + bj * 8;
            CP_ASYNC16(sb + G_AH(ns) + aso,      Ah + ga);
            CP_ASYNC16(sb + G_AH(ns) + aso + 16, Ah + ga + 8);
            CP_ASYNC16(sb + G_AL(ns) + aso,      Al + ga);
            CP_ASYNC16(sb + G_AL(ns) + aso + 16, Al + ga + 8);
            CP_ASYNC16(sb + G_BH(ns) + bso, Wh + gb);
            CP_ASYNC16(sb + G_BL(ns) + bso, Wl + gb);
            CP_COMMIT();
            CP_WAIT(1);
        } else {
            CP_WAIT(0);
        }
        __syncthreads();

        const uint32_t sAh = sb + G_AH(st);
        const uint32_t sAl = sb + G_AL(st);
        const uint32_t sBh = sb + G_BH(st);
        const uint32_t sBl = sb + G_BL(st);
#pragma unroll
        for (int ks = 0; ks < 2; ks++) {
            uint32_t ah[2][4], al[2][4], bh[2][4], bl[2][4];
#pragma unroll
            for (int mi = 0; mi < 2; mi++) {
                LDSM_X4(ah[mi], sAh + aoff + mi * 16 * 80 + ks * 32);
                LDSM_X4(al[mi], sAl + aoff + mi * 16 * 80 + ks * 32);
            }
#pragma unroll
            for (int ni = 0; ni < 2; ni++) {
                LDSM_X4_T(bh[ni], sBh + boff + ks * 16 * 144 + ni * 32);
                LDSM_X4_T(bl[ni], sBl + boff + ks * 16 * 144 + ni * 32);
            }
#pragma unroll
            for (int mi = 0; mi < 2; mi++) {
#pragma unroll
                for (int nt = 0; nt < 4; nt++) {
                    const int ni = nt >> 1;
                    const int sel = (nt & 1) * 2;
                    MMA_BF16(acc[mi][nt], ah[mi], bh[ni][sel], bh[ni][sel + 1]);
                    MMA_BF16(acc[mi][nt], ah[mi], bl[ni][sel], bl[ni][sel + 1]);
                    MMA_BF16(acc[mi][nt], al[mi], bh[ni][sel], bh[ni][sel + 1]);
                }
            }
        }
        __syncthreads();
    }

#pragma unroll
    for (int mi = 0; mi < 2; mi++) {
#pragma unroll
        for (int nt = 0; nt < 4; nt++) {
            const int col = blockCol + wn + nt * 8 + (lane & 3) * 2;
            const float2 bv = *reinterpret_cast<const float2*>(bias + col);
            const int r0 = blockRow + wm + mi * 16 + (lane >> 2);
            float2 o0 = {acc[mi][nt][0] + bv.x, acc[mi][nt][1] + bv.y};
            float2 o1 = {acc[mi][nt][2] + bv.x, acc[mi][nt][3] + bv.y};
            if (RELU) {
                o0.x = fmaxf(o0.x, 0.f); o0.y = fmaxf(o0.y, 0.f);
                o1.x = fmaxf(o1.x, 0.f); o1.y = fmaxf(o1.y, 0.f);
            }
            if (OUTF) {
                *reinterpret_cast<float2*>(C + (size_t)r0 * HID + col)       = o0;
                *reinterpret_cast<float2*>(C + (size_t)(r0 + 8) * HID + col) = o1;
            }
            if (OUTH) {
                __nv_bfloat16 h0, h1, l0, l1;
                split_hl(o0.x, h0, l0); split_hl(o0.y, h1, l1);
                *reinterpret_cast<__nv_bfloat162*>(Ch + (size_t)r0 * HID + col) = __halves2bfloat162(h0, h1);
                *reinterpret_cast<__nv_bfloat162*>(Cl + (size_t)r0 * HID + col) = __halves2bfloat162(l0, l1);
                split_hl(o1.x, h0, l0); split_hl(o1.y, h1, l1);
                *reinterpret_cast<__nv_bfloat162*>(Ch + (size_t)(r0 + 8) * HID + col) = __halves2bfloat162(h0, h1);
                *reinterpret_cast<__nv_bfloat162*>(Cl + (size_t)(r0 + 8) * HID + col) = __halves2bfloat162(l0, l1);
            }
        }
    }
}

// ---------------------------------------------------------------------------
// Fused attention: per (bh, 128-q-tile) block.
// S = (Q K^T)/8 (3-product hi/lo), exp (no max-subtract: |s| small),
// unnormalized O += P~ V (P hi only, V hi/lo), normalize by rowsum at end.
// 8 warps, each owns 16 q rows x full 64 cols.
// smem: Q hi/lo resident; K/V hi/lo double-buffered 64-row tiles.
// ---------------------------------------------------------------------------
#define AT_QH 0
#define AT_QL 18432
#define AT_KH(s) (36864 + (s) * 18432)
#define AT_KL(s) (46080 + (s) * 18432)
#define AT_VH(s) (73728 + (s) * 18432)
#define AT_VL(s) (82944 + (s) * 18432)
#define ATT_SMEM 110592
#define EXP_SCL 0.18033688f   // 0.125 * log2(e)

__global__ __launch_bounds__(256)
void attn_fused(const __nv_bfloat16* __restrict__ Qh,
                const __nv_bfloat16* __restrict__ Ql,
                const __nv_bfloat16* __restrict__ Kh,
                const __nv_bfloat16* __restrict__ Kl,
                const __nv_bfloat16* __restrict__ Vh,
                const __nv_bfloat16* __restrict__ Vl,
                __nv_bfloat16* __restrict__ Ch,
                __nv_bfloat16* __restrict__ Cl) {
    extern __shared__ char dynsm[];
    const uint32_t sb = smem_u32(dynsm);

    const int bh = blockIdx.y;
    const int b = bh / NHEAD, h = bh % NHEAD;
    const int q0 = blockIdx.x * 128;

    const __nv_bfloat16* Qhp = Qh + (size_t)(b * SEQ) * HID + h * HDIM;
    const __nv_bfloat16* Qlp = Ql + (size_t)(b * SEQ) * HID + h * HDIM;
    const __nv_bfloat16* Khp = Kh + (size_t)(b * SEQ) * HID + h * HDIM;
    const __nv_bfloat16* Klp = Kl + (size_t)(b * SEQ) * HID + h * HDIM;
    const __nv_bfloat16* Vhp = Vh + (size_t)(b * SEQ) * HID + h * HDIM;
    const __nv_bfloat16* Vlp = Vl + (size_t)(b * SEQ) * HID + h * HDIM;
    __nv_bfloat16* Chp = Ch + (size_t)(b * SEQ) * HID + h * HDIM;
    __nv_bfloat16* Clp = Cl + (size_t)(b * SEQ) * HID + h * HDIM;

    const int tid = threadIdx.x;
    const int wid = tid >> 5;
    const int lane = tid & 31;
    const int wrow = wid * 16;

    // loader indices
    const int qrow = tid >> 1;       // 0..127
    const int kvrow = tid >> 2;      // 0..63

    // prefetch: Q (whole) + K/V tile 0 -> group 0
    {
#pragma unroll
        for (int j = 0; j < 4; j++) {
            const int seg = (tid & 1) * 4 + j;
            const size_t g = (size_t)(q0 + qrow) * HID + seg * 8;
            const uint32_t d = (uint32_t)(qrow * 144 + seg * 16);
            CP_ASYNC16(sb + AT_QH + d, Qhp + g);
            CP_ASYNC16(sb + AT_QL + d, Qlp + g);
        }
#pragma unroll
        for (int j = 0; j < 2; j++) {
            const int seg = (tid & 3) * 2 + j;
            const size_t g = (size_t)kvrow * HID + seg * 8;
            const uint32_t d = (uint32_t)(kvrow * 144 + seg * 16);
            CP_ASYNC16(sb + AT_KH(0) + d, Khp + g);
            CP_ASYNC16(sb + AT_KL(0) + d, Klp + g);
            CP_ASYNC16(sb + AT_VH(0) + d, Vhp + g);
            CP_ASYNC16(sb + AT_VL(0) + d, Vlp + g);
        }
        CP_COMMIT();
    }

    float oacc[8][4];
#pragma unroll
    for (int i = 0; i < 8; i++)
#pragma unroll
        for (int j = 0; j < 4; j++) oacc[i][j] = 0.0f;
    float rs0 = 0.f, rs1 = 0.f;

    // per-warp ldmatrix addresses
    const uint32_t qoff = (uint32_t)((wrow + (lane & 15)) * 144 + (lane >> 4) * 16);
    const uint32_t koff = (uint32_t)((lane & 15) * 144 + (lane >> 4) * 16);
    const uint32_t voff = (uint32_t)(((lane & 7) + ((lane >> 3) & 1) * 8) * 144
                                     + ((lane >> 4) * 8) * 2);

    const int NT = SEQ / 64;   // 8

    for (int ts = 0; ts < NT; ts++) {
        const int st = ts & 1;
        if (ts + 1 < NT) {
            const int ns = st ^ 1;
#pragma unroll
            for (int j = 0; j < 2; j++) {
                const int seg = (tid & 3) * 2 + j;
                const size_t g = (size_t)((ts + 1) * 64 + kvrow) * HID + seg * 8;
                const uint32_t d = (uint32_t)(kvrow * 144 + seg * 16);
                CP_ASYNC16(sb + AT_KH(ns) + d, Khp + g);
                CP_ASYNC16(sb + AT_KL(ns) + d, Klp + g);
                CP_ASYNC16(sb + AT_VH(ns) + d, Vhp + g);
                CP_ASYNC16(sb + AT_VL(ns) + d, Vlp + g);
            }
            CP_COMMIT();
            CP_WAIT(1);
        } else {
            CP_WAIT(0);
        }
        __syncthreads();

        // ---- S = Q K^T (3-product), warp: 16q x 64s ----
        float sacc[8][4];
#pragma unroll
        for (int i = 0; i < 8; i++)
#pragma unroll
            for (int j = 0; j < 4; j++) sacc[i][j] = 0.0f;

        const uint32_t kbh = sb + AT_KH(st);
        const uint32_t kbl = sb + AT_KL(st);
#pragma unroll
        for (int ks = 0; ks < 4; ks++) {
            uint32_t qfh[4], qfl[4];
            LDSM_X4(qfh, sb + AT_QH + qoff + ks * 32);
            LDSM_X4(qfl, sb + AT_QL + qoff + ks * 32);
            uint32_t kfh[4][4], kfl[4][4];
#pragma unroll
            for (int g = 0; g < 4; g++) {
                LDSM_X4(kfh[g], kbh + koff + g * 16 * 144 + ks * 32);
                LDSM_X4(kfl[g], kbl + koff + g * 16 * 144 + ks * 32);
            }
#pragma unroll
            for (int nt = 0; nt < 8; nt++) {
                const int g = nt >> 1;
                const int sel = nt & 1;
                MMA_BF16(sacc[nt], qfh, kfh[g][sel], kfh[g][sel + 2]);
                MMA_BF16(sacc[nt], qfh, kfl[g][sel], kfl[g][sel + 2]);
                MMA_BF16(sacc[nt], qfl, kfh[g][sel], kfh[g][sel + 2]);
            }
        }

        // ---- exp (no max-subtract) + rowsum ----
#pragma unroll
        for (int nt = 0; nt < 8; nt++) {
            const float e0 = ex2_approx(sacc[nt][0] * EXP_SCL);
            const float e1 = ex2_approx(sacc[nt][1] * EXP_SCL);
            const float e2 = ex2_approx(sacc[nt][2] * EXP_SCL);
            const float e3 = ex2_approx(sacc[nt][3] * EXP_SCL);
            sacc[nt][0] = e0; sacc[nt][1] = e1;
            sacc[nt][2] = e2; sacc[nt][3] = e3;
            rs0 += e0 + e1;
            rs1 += e2 + e3;
        }

        // ---- C-frag -> A-frag conversion (P~ in bf16 hi) ----
        uint32_t pf[4][4];
#pragma unroll
        for (int j = 0; j < 4; j++) {
            pf[j][0] = pack_bf2(sacc[2 * j][0],     sacc[2 * j][1]);
            pf[j][1] = pack_bf2(sacc[2 * j][2],     sacc[2 * j][3]);
            pf[j][2] = pack_bf2(sacc[2 * j + 1][0], sacc[2 * j + 1][1]);
            pf[j][3] = pack_bf2(sacc[2 * j + 1][2], sacc[2 * j + 1][3]);
        }

        // ---- O += P~ V (V hi + lo) ----
        const uint32_t vbh = sb + AT_VH(st);
        const uint32_t vbl = sb + AT_VL(st);
#pragma unroll
        for (int ks = 0; ks < 4; ks++) {
            uint32_t vfh[4][4], vfl[4][4];
#pragma unroll
            for (int ni = 0; ni < 4; ni++) {
                LDSM_X4_T(vfh[ni], vbh + voff + ks * 16 * 144 + ni * 32);
                LDSM_X4_T(vfl[ni], vbl + voff + ks * 16 * 144 + ni * 32);
            }
#pragma unroll
            for (int nt = 0; nt < 8; nt++) {
                const int ni = nt >> 1;
                const int sel = (nt & 1) * 2;
                MMA_BF16(oacc[nt], pf[ks], vfh[ni][sel], vfh[ni][sel + 1]);
                MMA_BF16(oacc[nt], pf[ks], vfl[ni][sel], vfl[ni][sel + 1]);
            }
        }
        __syncthreads();
    }

    // ---- normalize + write bf16 hi/lo ----
    rs0 += __shfl_xor_sync(0xffffffffu, rs0, 1);
    rs0 += __shfl_xor_sync(0xffffffffu, rs0, 2);
    rs1 += __shfl_xor_sync(0xffffffffu, rs1, 1);
    rs1 += __shfl_xor_sync(0xffffffffu, rs1, 2);
    const float inv0 = 1.0f / rs0;
    const float inv1 = 1.0f / rs1;

    const int r0 = q0 + wrow + (lane >> 2);
#pragma unroll
    for (int nt = 0; nt < 8; nt++) {
        const int col = nt * 8 + (lane & 3) * 2;
        __nv_bfloat16 h0, h1, l0, l1;
        split_hl(oacc[nt][0] * inv0, h0, l0);
        split_hl(oacc[nt][1] * inv0, h1, l1);
        *reinterpret_cast<__nv_bfloat162*>(Chp + (size_t)r0 * HID + col) = __halves2bfloat162(h0, h1);
        *reinterpret_cast<__nv_bfloat162*>(Clp + (size_t)r0 * HID + col) = __halves2bfloat162(l0, l1);
        split_hl(oacc[nt][2] * inv1, h0, l0);
        split_hl(oacc[nt][3] * inv1, h1, l1);
        *reinterpret_cast<__nv_bfloat162*>(Chp + (size_t)(r0 + 8) * HID + col) = __halves2bfloat162(h0, h1);
        *reinterpret_cast<__nv_bfloat162*>(Clp + (size_t)(r0 + 8) * HID + col) = __halves2bfloat162(l0, l1);
    }
}

// ---------------------------------------------------------------------------
// Add + LayerNorm -> fp32 out + bf16 hi/lo out
// ---------------------------------------------------------------------------
__global__ __launch_bounds__(256)
void add_ln_kernel(const float* __restrict__ X,
                   const float* __restrict__ Y,
                   const float* __restrict__ g,
                   const float* __restrict__ b,
                   float* __restrict__ O,
                   __nv_bfloat16* __restrict__ Oh,
                   __nv_bfloat16* __restrict__ Ol) {
    const int row = blockIdx.x;
    const float* xr = X + (size_t)row * HID;
    const float* yr = Y + (size_t)row * HID;
    float* orow = O + (size_t)row * HID;
    __nv_bfloat16* ohr = Oh + (size_t)row * HID;
    __nv_bfloat16* olr = Ol + (size_t)row * HID;
    const int tid = threadIdx.x;

    float vals[3];
    float s = 0.f, ss = 0.f;
#pragma unroll
    for (int t = 0; t < 3; t++) {
        const int c = tid + t * 256;
        float v = xr[c] + yr[c];
        vals[t] = v;
        s += v;
        ss += v * v;
    }

    __shared__ float rs[256];
    __shared__ float rss[256];
    rs[tid] = s;
    rss[tid] = ss;
    __syncthreads();
#pragma unroll
    for (int st = 128; st > 0; st >>= 1) {
        if (tid < st) {
            rs[tid] += rs[tid + st];
            rss[tid] += rss[tid + st];
        }
        __syncthreads();
    }
    const float mean = rs[0] * (1.0f / HID);
    const float var = rss[0] * (1.0f / HID) - mean * mean;
    const float inv = rsqrtf(var + 1e-12f);

#pragma unroll
    for (int t = 0; t < 3; t++) {
        const int c = tid + t * 256;
        const float o = (vals[t] - mean) * inv * g[c] + b[c];
        orow[c] = o;
        __nv_bfloat16 h, l;
        split_hl(o, h, l);
        ohr[c] = h;
        olr[c] = l;
    }
}

// ---------------------------------------------------------------------------
// Launch
// ---------------------------------------------------------------------------
extern "C" void kernel_launch(void* const* d_in, const int* in_sizes, int n_in,
                              void* d_out, int out_size) {
    const float* x    = (const float*)d_in[0];
    const float* Wq   = (const float*)d_in[1];
    const float* bq   = (const float*)d_in[2];
    const float* Wk   = (const float*)d_in[3];
    const float* bk   = (const float*)d_in[4];
    const float* Wv   = (const float*)d_in[5];
    const float* bv   = (const float*)d_in[6];
    const float* Wo   = (const float*)d_in[7];
    const float* bo   = (const float*)d_in[8];
    const float* g1   = (const float*)d_in[9];
    const float* be1  = (const float*)d_in[10];
    const float* W2   = (const float*)d_in[11];
    const float* b2   = (const float*)d_in[12];
    const float* g2   = (const float*)d_in[13];
    const float* be2  = (const float*)d_in[14];

    float *X, *T1, *T2;
    cudaGetSymbolAddress((void**)&X,  g_X);
    cudaGetSymbolAddress((void**)&T1, g_T1);
    cudaGetSymbolAddress((void**)&T2, g_T2);

    __nv_bfloat16 *XH, *XL, *QH, *QL, *KH, *KL, *VH, *VL, *CH, *CL, *TH, *TL, *UH, *UL;
    cudaGetSymbolAddress((void**)&XH, g_XH); cudaGetSymbolAddress((void**)&XL, g_XL);
    cudaGetSymbolAddress((void**)&QH, g_QH); cudaGetSymbolAddress((void**)&QL, g_QL);
    cudaGetSymbolAddress((void**)&KH, g_KH); cudaGetSymbolAddress((void**)&KL, g_KL);
    cudaGetSymbolAddress((void**)&VH, g_VH); cudaGetSymbolAddress((void**)&VL, g_VL);
    cudaGetSymbolAddress((void**)&CH, g_CH); cudaGetSymbolAddress((void**)&CL, g_CL);
    cudaGetSymbolAddress((void**)&TH, g_TH); cudaGetSymbolAddress((void**)&TL, g_TL);
    cudaGetSymbolAddress((void**)&UH, g_UH); cudaGetSymbolAddress((void**)&UL, g_UL);

    __nv_bfloat16 *WqH, *WqL, *WkH, *WkL, *WvH, *WvL, *WoH, *WoL, *W2H, *W2L;
    cudaGetSymbolAddress((void**)&WqH, g_WqH); cudaGetSymbolAddress((void**)&WqL, g_WqL);
    cudaGetSymbolAddress((void**)&WkH, g_WkH); cudaGetSymbolAddress((void**)&WkL, g_WkL);
    cudaGetSymbolAddress((void**)&WvH, g_WvH); cudaGetSymbolAddress((void**)&WvL, g_WvL);
    cudaGetSymbolAddress((void**)&WoH, g_WoH); cudaGetSymbolAddress((void**)&WoL, g_WoL);
    cudaGetSymbolAddress((void**)&W2H, g_W2H); cudaGetSymbolAddress((void**)&W2L, g_W2L);

    cudaFuncSetAttribute(gemm_mma<false, false, true>, cudaFuncAttributeMaxDynamicSharedMemorySize, GEMM_SMEM);
    cudaFuncSetAttribute(gemm_mma<false, true, false>, cudaFuncAttributeMaxDynamicSharedMemorySize, GEMM_SMEM);
    cudaFuncSetAttribute(gemm_mma<true, false, true>,  cudaFuncAttributeMaxDynamicSharedMemorySize, GEMM_SMEM);
    cudaFuncSetAttribute(gemm_mma<true, true, false>,  cudaFuncAttributeMaxDynamicSharedMemorySize, GEMM_SMEM);
    cudaFuncSetAttribute(attn_fused, cudaFuncAttributeMaxDynamicSharedMemorySize, ATT_SMEM);

    cudaMemcpyAsync(X, x, (size_t)MH * sizeof(float), cudaMemcpyDeviceToDevice);

    const int wN4 = WELEMS / 4;
    const int wGrid = (wN4 + 255) / 256;
    conv_hl<<<wGrid, 256>>>(Wq, WqH, WqL, wN4);
    conv_hl<<<wGrid, 256>>>(Wk, WkH, WkL, wN4);
    conv_hl<<<wGrid, 256>>>(Wv, WvH, WvL, wN4);
    conv_hl<<<wGrid, 256>>>(Wo, WoH, WoL, wN4);
    conv_hl<<<wGrid, 256>>>(W2, W2H, W2L, wN4);

    const int aN4 = MH / 4;
    const int aGrid = (aN4 + 255) / 256;
    conv_hl<<<aGrid, 256>>>(X, XH, XL, aN4);

    const dim3 gemmGrid(HID / 64, MROWS / 128);   // (12, 32)
    const dim3 atGrid(SEQ / 128, BATCH * NHEAD);  // (4, 96)

    for (int l = 0; l < NLAYERS; l++) {
        const size_t wo = (size_t)l * HID * HID;
        const size_t vo = (size_t)l * HID;

        gemm_mma<false, false, true><<<gemmGrid, 256, GEMM_SMEM>>>(XH, XL, WqH + wo, WqL + wo, bq + vo, nullptr, QH, QL);
        gemm_mma<false, false, true><<<gemmGrid, 256, GEMM_SMEM>>>(XH, XL, WkH + wo, WkL + wo, bk + vo, nullptr, KH, KL);
        gemm_mma<false, false, true><<<gemmGrid, 256, GEMM_SMEM>>>(XH, XL, WvH + wo, WvL + wo, bv + vo, nullptr, VH, VL);

        attn_fused<<<atGrid, 256, ATT_SMEM>>>(QH, QL, KH, KL, VH, VL, CH, CL);

        gemm_mma<false, true, false><<<gemmGrid, 256, GEMM_SMEM>>>(CH, CL, WoH + wo, WoL + wo, bo + vo, T1, nullptr, nullptr);
        add_ln_kernel<<<MROWS, 256>>>(X, T1, g1 + vo, be1 + vo, T2, TH, TL);

        gemm_mma<true, false, true><<<gemmGrid, 256, GEMM_SMEM>>>(TH, TL, W2H + wo, W2L + wo, b2 + vo, nullptr, UH, UL);
        gemm_mma<true, true, false><<<gemmGrid, 256, GEMM_SMEM>>>(UH, UL, W2H + wo, W2L + wo, b2 + vo, T1, nullptr, nullptr);
        add_ln_kernel<<<MROWS, 256>>>(T2, T1, g2 + vo, be2 + vo, X, XH, XL);
    }

    cudaMemcpyAsync(d_out, X, (size_t)MH * sizeof(float), cudaMemcpyDeviceToDevice);
}

// round 16
// speedup vs baseline: 3.1678x; 1.0047x over previous
#include <cuda_runtime.h>
#include <cuda_bf16.h>
#include <math.h>
#include <stdint.h>

// Problem constants
#define NLAYERS 12
#define BATCH   8
#define SEQ     512
#define HID     768
#define NHEAD   12
#define HDIM    64
#define MROWS   (BATCH * SEQ)      // 4096
#define MH      (MROWS * HID)
#define WELEMS  (NLAYERS * HID * HID)

// fp32 scratch
__device__ float g_X[MH];
__device__ float g_T1[MH];
__device__ float g_T2[MH];

// bf16 hi/lo scratch (activations)
__device__ __nv_bfloat16 g_XH[MH],  g_XL[MH];
__device__ __nv_bfloat16 g_QH[MH],  g_QL[MH];
__device__ __nv_bfloat16 g_KH[MH],  g_KL[MH];
__device__ __nv_bfloat16 g_VH[MH],  g_VL[MH];
__device__ __nv_bfloat16 g_CH[MH],  g_CL[MH];
__device__ __nv_bfloat16 g_TH[MH],  g_TL[MH];
__device__ __nv_bfloat16 g_UH[MH],  g_UL[MH];

// bf16 hi/lo weights
__device__ __nv_bfloat16 g_WqH[WELEMS], g_WqL[WELEMS];
__device__ __nv_bfloat16 g_WkH[WELEMS], g_WkL[WELEMS];
__device__ __nv_bfloat16 g_WvH[WELEMS], g_WvL[WELEMS];
__device__ __nv_bfloat16 g_WoH[WELEMS], g_WoL[WELEMS];
__device__ __nv_bfloat16 g_W2H[WELEMS], g_W2L[WELEMS];

// ---------------------------------------------------------------------------
// helpers
// ---------------------------------------------------------------------------
__device__ __forceinline__ uint32_t smem_u32(const void* p) {
    uint32_t a;
    asm("{ .reg .u64 t; cvta.to.shared.u64 t, %1; cvt.u32.u64 %0, t; }"
        : "=r"(a) : "l"(p));
    return a;
}

#define LDSM_X4(r, addr) \
    asm volatile("ldmatrix.sync.aligned.m8n8.x4.shared.b16 {%0,%1,%2,%3}, [%4];" \
        : "=r"((r)[0]), "=r"((r)[1]), "=r"((r)[2]), "=r"((r)[3]) : "r"(addr))

#define LDSM_X4_T(r, addr) \
    asm volatile("ldmatrix.sync.aligned.m8n8.x4.trans.shared.b16 {%0,%1,%2,%3}, [%4];" \
        : "=r"((r)[0]), "=r"((r)[1]), "=r"((r)[2]), "=r"((r)[3]) : "r"(addr))

#define MMA_BF16(d, a, b0, b1) \
    asm volatile("mma.sync.aligned.m16n8k16.row.col.f32.bf16.bf16.f32 " \
        "{%0,%1,%2,%3}, {%4,%5,%6,%7}, {%8,%9}, {%0,%1,%2,%3};" \
        : "+f"((d)[0]), "+f"((d)[1]), "+f"((d)[2]), "+f"((d)[3]) \
        : "r"((a)[0]), "r"((a)[1]), "r"((a)[2]), "r"((a)[3]), "r"(b0), "r"(b1))

#define CP_ASYNC16(dst, src) \
    asm volatile("cp.async.ca.shared.global [%0], [%1], 16;" :: "r"(dst), "l"(src))
#define CP_COMMIT() asm volatile("cp.async.commit_group;" ::: "memory")
#define CP_WAIT(n)  asm volatile("cp.async.wait_group %0;" :: "n"(n) : "memory")

__device__ __forceinline__ void split_hl(float v, __nv_bfloat16& h, __nv_bfloat16& l) {
    h = __float2bfloat16(v);
    l = __float2bfloat16(v - __bfloat162float(h));
}

__device__ __forceinline__ float ex2_approx(float x) {
    float y;
    asm("ex2.approx.f32 %0, %1;" : "=f"(y) : "f"(x));
    return y;
}

__device__ __forceinline__ uint32_t pack_bf2(float a, float b) {
    __nv_bfloat162 p = __halves2bfloat162(__float2bfloat16(a), __float2bfloat16(b));
    return *reinterpret_cast<uint32_t*>(&p);
}

// ---------------------------------------------------------------------------
// fp32 -> bf16 hi/lo conversion (weights + initial X)
// ---------------------------------------------------------------------------
__global__ __launch_bounds__(256)
void conv_hl(const float* __restrict__ s,
             __nv_bfloat16* __restrict__ h,
             __nv_bfloat16* __restrict__ l,
             int n4) {
    int i = blockIdx.x * 256 + threadIdx.x;
    if (i >= n4) return;
    float4 v = reinterpret_cast<const float4*>(s)[i];
    __nv_bfloat16 h0, h1, h2, h3, l0, l1, l2, l3;
    split_hl(v.x, h0, l0); split_hl(v.y, h1, l1);
    split_hl(v.z, h2, l2); split_hl(v.w, h3, l3);
    reinterpret_cast<__nv_bfloat162*>(h)[2 * i]     = __halves2bfloat162(h0, h1);
    reinterpret_cast<__nv_bfloat162*>(h)[2 * i + 1] = __halves2bfloat162(h2, h3);
    reinterpret_cast<__nv_bfloat162*>(l)[2 * i]     = __halves2bfloat162(l0, l1);
    reinterpret_cast<__nv_bfloat162*>(l)[2 * i + 1] = __halves2bfloat162(l2, l3);
}

// ---------------------------------------------------------------------------
// bf16 split-precision GEMM body with 3-stage cp.async pipeline.
// BM=128, BN=64, BK=32, 8 warps (4x2), warp 32x32. 3-product hi/lo.
// smem stages: AH 3x10240, AL 3x10240, BH 3x4608, BL 3x4608 = 89088 B
// ---------------------------------------------------------------------------
#define G_AH(st) ((st) * 10240)
#define G_AL(st) (30720 + (st) * 10240)
#define G_BH(st) (61440 + (st) * 4608)
#define G_BL(st) (75264 + (st) * 4608)
#define GEMM_SMEM 89088

template <bool RELU, bool OUTF, bool OUTH>
__device__ __forceinline__
void gemm_body(uint32_t sb,
               const __nv_bfloat16* __restrict__ Ah,
               const __nv_bfloat16* __restrict__ Al,
               const __nv_bfloat16* __restrict__ Wh,
               const __nv_bfloat16* __restrict__ Wl,
               const float* __restrict__ bias,
               float* __restrict__ C,
               __nv_bfloat16* __restrict__ Ch,
               __nv_bfloat16* __restrict__ Cl,
               int blockRow, int blockCol) {
    const int tid = threadIdx.x;
    const int wid = tid >> 5;
    const int lane = tid & 31;
    const int wm = (wid & 3) * 32;
    const int wn = (wid >> 2) * 32;

    float acc[2][4][4];
#pragma unroll
    for (int i = 0; i < 2; i++)
#pragma unroll
        for (int j = 0; j < 4; j++)
#pragma unroll
            for (int q = 0; q < 4; q++) acc[i][j][q] = 0.0f;

    const int arow = tid >> 1;
    const int ahalf = tid & 1;
    const int bk = tid >> 3;
    const int bj = tid & 7;

    const uint32_t aso = (uint32_t)(arow * 80 + ahalf * 32);
    const uint32_t bso = (uint32_t)(bk * 144 + bj * 16);

    const uint32_t aoff = (uint32_t)((wm + (lane & 15)) * 80 + (lane >> 4) * 16);
    const uint32_t boff = (uint32_t)(((lane & 7) + ((lane >> 3) & 1) * 8) * 144
                                     + (wn + (lane >> 4) * 8) * 2);

    const int NT = HID / 32;  // 24

    auto issue_tile = [&](int t, int st) {
        const size_t ga = (size_t)(blockRow + arow) * HID + t * 32 + ahalf * 16;
        const size_t gb = (size_t)(t * 32 + bk) * HID + blockCol + bj * 8;
        CP_ASYNC16(sb + G_AH(st) + aso,      Ah + ga);
        CP_ASYNC16(sb + G_AH(st) + aso + 16, Ah + ga + 8);
        CP_ASYNC16(sb + G_AL(st) + aso,      Al + ga);
        CP_ASYNC16(sb + G_AL(st) + aso + 16, Al + ga + 8);
        CP_ASYNC16(sb + G_BH(st) + bso, Wh + gb);
        CP_ASYNC16(sb + G_BL(st) + bso, Wl + gb);
    };

    issue_tile(0, 0); CP_COMMIT();
    issue_tile(1, 1); CP_COMMIT();

    int st = 0;      // stage of tile kt
    int pst = 2;     // stage where tile kt+2 goes
    for (int kt = 0; kt < NT; kt++) {
        if (kt + 2 < NT) {
            issue_tile(kt + 2, pst);
            CP_COMMIT();
            CP_WAIT(2);
        } else if (kt + 1 < NT) {
            CP_WAIT(1);
        } else {
            CP_WAIT(0);
        }
        __syncthreads();

        const uint32_t sAh = sb + G_AH(st);
        const uint32_t sAl = sb + G_AL(st);
        const uint32_t sBh = sb + G_BH(st);
        const uint32_t sBl = sb + G_BL(st);
#pragma unroll
        for (int ks = 0; ks < 2; ks++) {
            uint32_t ah[2][4], al[2][4], bh[2][4], bl[2][4];
#pragma unroll
            for (int mi = 0; mi < 2; mi++) {
                LDSM_X4(ah[mi], sAh + aoff + mi * 16 * 80 + ks * 32);
                LDSM_X4(al[mi], sAl + aoff + mi * 16 * 80 + ks * 32);
            }
#pragma unroll
            for (int ni = 0; ni < 2; ni++) {
                LDSM_X4_T(bh[ni], sBh + boff + ks * 16 * 144 + ni * 32);
                LDSM_X4_T(bl[ni], sBl + boff + ks * 16 * 144 + ni * 32);
            }
#pragma unroll
            for (int mi = 0; mi < 2; mi++) {
#pragma unroll
                for (int nt = 0; nt < 4; nt++) {
                    const int ni = nt >> 1;
                    const int sel = (nt & 1) * 2;
                    MMA_BF16(acc[mi][nt], ah[mi], bh[ni][sel], bh[ni][sel + 1]);
                    MMA_BF16(acc[mi][nt], ah[mi], bl[ni][sel], bl[ni][sel + 1]);
                    MMA_BF16(acc[mi][nt], al[mi], bh[ni][sel], bh[ni][sel + 1]);
                }
            }
        }
        __syncthreads();
        st = (st == 2) ? 0 : st + 1;
        pst = (pst == 2) ? 0 : pst + 1;
    }

#pragma unroll
    for (int mi = 0; mi < 2; mi++) {
#pragma unroll
        for (int nt = 0; nt < 4; nt++) {
            const int col = blockCol + wn + nt * 8 + (lane & 3) * 2;
            const float2 bv = *reinterpret_cast<const float2*>(bias + col);
            const int r0 = blockRow + wm + mi * 16 + (lane >> 2);
            float2 o0 = {acc[mi][nt][0] + bv.x, acc[mi][nt][1] + bv.y};
            float2 o1 = {acc[mi][nt][2] + bv.x, acc[mi][nt][3] + bv.y};
            if (RELU) {
                o0.x = fmaxf(o0.x, 0.f); o0.y = fmaxf(o0.y, 0.f);
                o1.x = fmaxf(o1.x, 0.f); o1.y = fmaxf(o1.y, 0.f);
            }
            if (OUTF) {
                *reinterpret_cast<float2*>(C + (size_t)r0 * HID + col)       = o0;
                *reinterpret_cast<float2*>(C + (size_t)(r0 + 8) * HID + col) = o1;
            }
            if (OUTH) {
                __nv_bfloat16 h0, h1, l0, l1;
                split_hl(o0.x, h0, l0); split_hl(o0.y, h1, l1);
                *reinterpret_cast<__nv_bfloat162*>(Ch + (size_t)r0 * HID + col) = __halves2bfloat162(h0, h1);
                *reinterpret_cast<__nv_bfloat162*>(Cl + (size_t)r0 * HID + col) = __halves2bfloat162(l0, l1);
                split_hl(o1.x, h0, l0); split_hl(o1.y, h1, l1);
                *reinterpret_cast<__nv_bfloat162*>(Ch + (size_t)(r0 + 8) * HID + col) = __halves2bfloat162(h0, h1);
                *reinterpret_cast<__nv_bfloat162*>(Cl + (size_t)(r0 + 8) * HID + col) = __halves2bfloat162(l0, l1);
            }
        }
    }
}

template <bool RELU, bool OUTF, bool OUTH>
__global__ __launch_bounds__(256)
void gemm_mma(const __nv_bfloat16* __restrict__ Ah,
              const __nv_bfloat16* __restrict__ Al,
              const __nv_bfloat16* __restrict__ Wh,
              const __nv_bfloat16* __restrict__ Wl,
              const float* __restrict__ bias,
              float* __restrict__ C,
              __nv_bfloat16* __restrict__ Ch,
              __nv_bfloat16* __restrict__ Cl) {
    extern __shared__ char dynsm[];
    gemm_body<RELU, OUTF, OUTH>(smem_u32(dynsm), Ah, Al, Wh, Wl, bias,
                                C, Ch, Cl, blockIdx.y * 128, blockIdx.x * 64);
}

// Fused Q/K/V: one launch, gridDim.z selects projection (merges wave tails).
__global__ __launch_bounds__(256)
void gemm_qkv(const __nv_bfloat16* __restrict__ Ah,
              const __nv_bfloat16* __restrict__ Al,
              const __nv_bfloat16* __restrict__ WqH, const __nv_bfloat16* __restrict__ WqL,
              const float* __restrict__ bq,
              __nv_bfloat16* __restrict__ QH, __nv_bfloat16* __restrict__ QL,
              const __nv_bfloat16* __restrict__ WkH, const __nv_bfloat16* __restrict__ WkL,
              const float* __restrict__ bk,
              __nv_bfloat16* __restrict__ KH, __nv_bfloat16* __restrict__ KL,
              const __nv_bfloat16* __restrict__ WvH, const __nv_bfloat16* __restrict__ WvL,
              const float* __restrict__ bv,
              __nv_bfloat16* __restrict__ VH, __nv_bfloat16* __restrict__ VL) {
    extern __shared__ char dynsm[];
    const __nv_bfloat16 *Wh, *Wl;
    const float* bias;
    __nv_bfloat16 *Ch, *Cl;
    if (blockIdx.z == 0)      { Wh = WqH; Wl = WqL; bias = bq; Ch = QH; Cl = QL; }
    else if (blockIdx.z == 1) { Wh = WkH; Wl = WkL; bias = bk; Ch = KH; Cl = KL; }
    else                      { Wh = WvH; Wl = WvL; bias = bv; Ch = VH; Cl = VL; }
    gemm_body<false, false, true>(smem_u32(dynsm), Ah, Al, Wh, Wl, bias,
                                  nullptr, Ch, Cl, blockIdx.y * 128, blockIdx.x * 64);
}

// ---------------------------------------------------------------------------
// Fused attention (unchanged from R11 passing version)
// ---------------------------------------------------------------------------
#define AT_QH 0
#define AT_QL 18432
#define AT_KH(s) (36864 + (s) * 18432)
#define AT_KL(s) (46080 + (s) * 18432)
#define AT_VH(s) (73728 + (s) * 18432)
#define AT_VL(s) (82944 + (s) * 18432)
#define ATT_SMEM 110592
#define EXP_SCL 0.18033688f   // 0.125 * log2(e)

__global__ __launch_bounds__(256)
void attn_fused(const __nv_bfloat16* __restrict__ Qh,
                const __nv_bfloat16* __restrict__ Ql,
                const __nv_bfloat16* __restrict__ Kh,
                const __nv_bfloat16* __restrict__ Kl,
                const __nv_bfloat16* __restrict__ Vh,
                const __nv_bfloat16* __restrict__ Vl,
                __nv_bfloat16* __restrict__ Ch,
                __nv_bfloat16* __restrict__ Cl) {
    extern __shared__ char dynsm[];
    const uint32_t sb = smem_u32(dynsm);

    const int bh = blockIdx.y;
    const int b = bh / NHEAD, h = bh % NHEAD;
    const int q0 = blockIdx.x * 128;

    const __nv_bfloat16* Qhp = Qh + (size_t)(b * SEQ) * HID + h * HDIM;
    const __nv_bfloat16* Qlp = Ql + (size_t)(b * SEQ) * HID + h * HDIM;
    const __nv_bfloat16* Khp = Kh + (size_t)(b * SEQ) * HID + h * HDIM;
    const __nv_bfloat16* Klp = Kl + (size_t)(b * SEQ) * HID + h * HDIM;
    const __nv_bfloat16* Vhp = Vh + (size_t)(b * SEQ) * HID + h * HDIM;
    const __nv_bfloat16* Vlp = Vl + (size_t)(b * SEQ) * HID + h * HDIM;
    __nv_bfloat16* Chp = Ch + (size_t)(b * SEQ) * HID + h * HDIM;
    __nv_bfloat16* Clp = Cl + (size_t)(b * SEQ) * HID + h * HDIM;

    const int tid = threadIdx.x;
    const int wid = tid >> 5;
    const int lane = tid & 31;
    const int wrow = wid * 16;

    const int qrow = tid >> 1;
    const int kvrow = tid >> 2;

    {
#pragma unroll
        for (int j = 0; j < 4; j++) {
            const int seg = (tid & 1) * 4 + j;
            const size_t g = (size_t)(q0 + qrow) * HID + seg * 8;
            const uint32_t d = (uint32_t)(qrow * 144 + seg * 16);
            CP_ASYNC16(sb + AT_QH + d, Qhp + g);
            CP_ASYNC16(sb + AT_QL + d, Qlp + g);
        }
#pragma unroll
        for (int j = 0; j < 2; j++) {
            const int seg = (tid & 3) * 2 + j;
            const size_t g = (size_t)kvrow * HID + seg * 8;
            const uint32_t d = (uint32_t)(kvrow * 144 + seg * 16);
            CP_ASYNC16(sb + AT_KH(0) + d, Khp + g);
            CP_ASYNC16(sb + AT_KL(0) + d, Klp + g);
            CP_ASYNC16(sb + AT_VH(0) + d, Vhp + g);
            CP_ASYNC16(sb + AT_VL(0) + d, Vlp + g);
        }
        CP_COMMIT();
    }

    float oacc[8][4];
#pragma unroll
    for (int i = 0; i < 8; i++)
#pragma unroll
        for (int j = 0; j < 4; j++) oacc[i][j] = 0.0f;
    float rs0 = 0.f, rs1 = 0.f;

    const uint32_t qoff = (uint32_t)((wrow + (lane & 15)) * 144 + (lane >> 4) * 16);
    const uint32_t koff = (uint32_t)((lane & 15) * 144 + (lane >> 4) * 16);
    const uint32_t voff = (uint32_t)(((lane & 7) + ((lane >> 3) & 1) * 8) * 144
                                     + ((lane >> 4) * 8) * 2);

    const int NT = SEQ / 64;

    for (int ts = 0; ts < NT; ts++) {
        const int st = ts & 1;
        if (ts + 1 < NT) {
            const int ns = st ^ 1;
#pragma unroll
            for (int j = 0; j < 2; j++) {
                const int seg = (tid & 3) * 2 + j;
                const size_t g = (size_t)((ts + 1) * 64 + kvrow) * HID + seg * 8;
                const uint32_t d = (uint32_t)(kvrow * 144 + seg * 16);
                CP_ASYNC16(sb + AT_KH(ns) + d, Khp + g);
                CP_ASYNC16(sb + AT_KL(ns) + d, Klp + g);
                CP_ASYNC16(sb + AT_VH(ns) + d, Vhp + g);
                CP_ASYNC16(sb + AT_VL(ns) + d, Vlp + g);
            }
            CP_COMMIT();
            CP_WAIT(1);
        } else {
            CP_WAIT(0);
        }
        __syncthreads();

        float sacc[8][4];
#pragma unroll
        for (int i = 0; i < 8; i++)
#pragma unroll
            for (int j = 0; j < 4; j++) sacc[i][j] = 0.0f;

        const uint32_t kbh = sb + AT_KH(st);
        const uint32_t kbl = sb + AT_KL(st);
#pragma unroll
        for (int ks = 0; ks < 4; ks++) {
            uint32_t qfh[4], qfl[4];
            LDSM_X4(qfh, sb + AT_QH + qoff + ks * 32);
            LDSM_X4(qfl, sb + AT_QL + qoff + ks * 32);
            uint32_t kfh[4][4], kfl[4][4];
#pragma unroll
            for (int g = 0; g < 4; g++) {
                LDSM_X4(kfh[g], kbh + koff + g * 16 * 144 + ks * 32);
                LDSM_X4(kfl[g], kbl + koff + g * 16 * 144 + ks * 32);
            }
#pragma unroll
            for (int nt = 0; nt < 8; nt++) {
                const int g = nt >> 1;
                const int sel = nt & 1;
                MMA_BF16(sacc[nt], qfh, kfh[g][sel], kfh[g][sel + 2]);
                MMA_BF16(sacc[nt], qfh, kfl[g][sel], kfl[g][sel + 2]);
                MMA_BF16(sacc[nt], qfl, kfh[g][sel], kfh[g][sel + 2]);
            }
        }

#pragma unroll
        for (int nt = 0; nt < 8; nt++) {
            const float e0 = ex2_approx(sacc[nt][0] * EXP_SCL);
            const float e1 = ex2_approx(sacc[nt][1] * EXP_SCL);
            const float e2 = ex2_approx(sacc[nt][2] * EXP_SCL);
            const float e3 = ex2_approx(sacc[nt][3] * EXP_SCL);
            sacc[nt][0] = e0; sacc[nt][1] = e1;
            sacc[nt][2] = e2; sacc[nt][3] = e3;
            rs0 += e0 + e1;
            rs1 += e2 + e3;
        }

        uint32_t pf[4][4];
#pragma unroll
        for (int j = 0; j < 4; j++) {
            pf[j][0] = pack_bf2(sacc[2 * j][0],     sacc[2 * j][1]);
            pf[j][1] = pack_bf2(sacc[2 * j][2],     sacc[2 * j][3]);
            pf[j][2] = pack_bf2(sacc[2 * j + 1][0], sacc[2 * j + 1][1]);
            pf[j][3] = pack_bf2(sacc[2 * j + 1][2], sacc[2 * j + 1][3]);
        }

        const uint32_t vbh = sb + AT_VH(st);
        const uint32_t vbl = sb + AT_VL(st);
#pragma unroll
        for (int ks = 0; ks < 4; ks++) {
            uint32_t vfh[4][4], vfl[4][4];
#pragma unroll
            for (int ni = 0; ni < 4; ni++) {
                LDSM_X4_T(vfh[ni], vbh + voff + ks * 16 * 144 + ni * 32);
                LDSM_X4_T(vfl[ni], vbl + voff + ks * 16 * 144 + ni * 32);
            }
#pragma unroll
            for (int nt = 0; nt < 8; nt++) {
                const int ni = nt >> 1;
                const int sel = (nt & 1) * 2;
                MMA_BF16(oacc[nt], pf[ks], vfh[ni][sel], vfh[ni][sel + 1]);
                MMA_BF16(oacc[nt], pf[ks], vfl[ni][sel], vfl[ni][sel + 1]);
            }
        }
        __syncthreads();
    }

    rs0 += __shfl_xor_sync(0xffffffffu, rs0, 1);
    rs0 += __shfl_xor_sync(0xffffffffu, rs0, 2);
    rs1 += __shfl_xor_sync(0xffffffffu, rs1, 1);
    rs1 += __shfl_xor_sync(0xffffffffu, rs1, 2);
    const float inv0 = 1.0f / rs0;
    const float inv1 = 1.0f / rs1;

    const int r0 = q0 + wrow + (lane >> 2);
#pragma unroll
    for (int nt = 0; nt < 8; nt++) {
        const int col = nt * 8 + (lane & 3) * 2;
        __nv_bfloat16 h0, h1, l0, l1;
        split_hl(oacc[nt][0] * inv0, h0, l0);
        split_hl(oacc[nt][1] * inv0, h1, l1);
        *reinterpret_cast<__nv_bfloat162*>(Chp + (size_t)r0 * HID + col) = __halves2bfloat162(h0, h1);
        *reinterpret_cast<__nv_bfloat162*>(Clp + (size_t)r0 * HID + col) = __halves2bfloat162(l0, l1);
        split_hl(oacc[nt][2] * inv1, h0, l0);
        split_hl(oacc[nt][3] * inv1, h1, l1);
        *reinterpret_cast<__nv_bfloat162*>(Chp + (size_t)(r0 + 8) * HID + col) = __halves2bfloat162(h0, h1);
        *reinterpret_cast<__nv_bfloat162*>(Clp + (size_t)(r0 + 8) * HID + col) = __halves2bfloat162(l0, l1);
    }
}

// ---------------------------------------------------------------------------
// Add + LayerNorm -> fp32 out + bf16 hi/lo out
// ---------------------------------------------------------------------------
__global__ __launch_bounds__(256)
void add_ln_kernel(const float* __restrict__ X,
                   const float* __restrict__ Y,
                   const float* __restrict__ g,
                   const float* __restrict__ b,
                   float* __restrict__ O,
                   __nv_bfloat16* __restrict__ Oh,
                   __nv_bfloat16* __restrict__ Ol) {
    const int row = blockIdx.x;
    const float* xr = X + (size_t)row * HID;
    const float* yr = Y + (size_t)row * HID;
    float* orow = O + (size_t)row * HID;
    __nv_bfloat16* ohr = Oh + (size_t)row * HID;
    __nv_bfloat16* olr = Ol + (size_t)row * HID;
    const int tid = threadIdx.x;

    float vals[3];
    float s = 0.f, ss = 0.f;
#pragma unroll
    for (int t = 0; t < 3; t++) {
        const int c = tid + t * 256;
        float v = xr[c] + yr[c];
        vals[t] = v;
        s += v;
        ss += v * v;
    }

    __shared__ float rs[256];
    __shared__ float rss[256];
    rs[tid] = s;
    rss[tid] = ss;
    __syncthreads();
#pragma unroll
    for (int st = 128; st > 0; st >>= 1) {
        if (tid < st) {
            rs[tid] += rs[tid + st];
            rss[tid] += rss[tid + st];
        }
        __syncthreads();
    }
    const float mean = rs[0] * (1.0f / HID);
    const float var = rss[0] * (1.0f / HID) - mean * mean;
    const float inv = rsqrtf(var + 1e-12f);

#pragma unroll
    for (int t = 0; t < 3; t++) {
        const int c = tid + t * 256;
        const float o = (vals[t] - mean) * inv * g[c] + b[c];
        orow[c] = o;
        __nv_bfloat16 h, l;
        split_hl(o, h, l);
        ohr[c] = h;
        olr[c] = l;
    }
}

// ---------------------------------------------------------------------------
// Launch
// ---------------------------------------------------------------------------
extern "C" void kernel_launch(void* const* d_in, const int* in_sizes, int n_in,
                              void* d_out, int out_size) {
    const float* x    = (const float*)d_in[0];
    const float* Wq   = (const float*)d_in[1];
    const float* bq   = (const float*)d_in[2];
    const float* Wk   = (const float*)d_in[3];
    const float* bk   = (const float*)d_in[4];
    const float* Wv   = (const float*)d_in[5];
    const float* bv   = (const float*)d_in[6];
    const float* Wo   = (const float*)d_in[7];
    const float* bo   = (const float*)d_in[8];
    const float* g1   = (const float*)d_in[9];
    const float* be1  = (const float*)d_in[10];
    const float* W2   = (const float*)d_in[11];
    const float* b2   = (const float*)d_in[12];
    const float* g2   = (const float*)d_in[13];
    const float* be2  = (const float*)d_in[14];

    float *X, *T1, *T2;
    cudaGetSymbolAddress((void**)&X,  g_X);
    cudaGetSymbolAddress((void**)&T1, g_T1);
    cudaGetSymbolAddress((void**)&T2, g_T2);

    __nv_bfloat16 *XH, *XL, *QH, *QL, *KH, *KL, *VH, *VL, *CH, *CL, *TH, *TL, *UH, *UL;
    cudaGetSymbolAddress((void**)&XH, g_XH); cudaGetSymbolAddress((void**)&XL, g_XL);
    cudaGetSymbolAddress((void**)&QH, g_QH); cudaGetSymbolAddress((void**)&QL, g_QL);
    cudaGetSymbolAddress((void**)&KH, g_KH); cudaGetSymbolAddress((void**)&KL, g_KL);
    cudaGetSymbolAddress((void**)&VH, g_VH); cudaGetSymbolAddress((void**)&VL, g_VL);
    cudaGetSymbolAddress((void**)&CH, g_CH); cudaGetSymbolAddress((void**)&CL, g_CL);
    cudaGetSymbolAddress((void**)&TH, g_TH); cudaGetSymbolAddress((void**)&TL, g_TL);
    cudaGetSymbolAddress((void**)&UH, g_UH); cudaGetSymbolAddress((void**)&UL, g_UL);

    __nv_bfloat16 *WqH, *WqL, *WkH, *WkL, *WvH, *WvL, *WoH, *WoL, *W2H, *W2L;
    cudaGetSymbolAddress((void**)&WqH, g_WqH); cudaGetSymbolAddress((void**)&WqL, g_WqL);
    cudaGetSymbolAddress((void**)&WkH, g_WkH); cudaGetSymbolAddress((void**)&WkL, g_WkL);
    cudaGetSymbolAddress((void**)&WvH, g_WvH); cudaGetSymbolAddress((void**)&WvL, g_WvL);
    cudaGetSymbolAddress((void**)&WoH, g_WoH); cudaGetSymbolAddress((void**)&WoL, g_WoL);
    cudaGetSymbolAddress((void**)&W2H, g_W2H); cudaGetSymbolAddress((void**)&W2L, g_W2L);

    cudaFuncSetAttribute(gemm_mma<false, true, false>, cudaFuncAttributeMaxDynamicSharedMemorySize, GEMM_SMEM);
    cudaFuncSetAttribute(gemm_mma<true, false, true>,  cudaFuncAttributeMaxDynamicSharedMemorySize, GEMM_SMEM);
    cudaFuncSetAttribute(gemm_mma<true, true, false>,  cudaFuncAttributeMaxDynamicSharedMemorySize, GEMM_SMEM);
    cudaFuncSetAttribute(gemm_qkv, cudaFuncAttributeMaxDynamicSharedMemorySize, GEMM_SMEM);
    cudaFuncSetAttribute(attn_fused, cudaFuncAttributeMaxDynamicSharedMemorySize, ATT_SMEM);

    cudaMemcpyAsync(X, x, (size_t)MH * sizeof(float), cudaMemcpyDeviceToDevice);

    const int wN4 = WELEMS / 4;
    const int wGrid = (wN4 + 255) / 256;
    conv_hl<<<wGrid, 256>>>(Wq, WqH, WqL, wN4);
    conv_hl<<<wGrid, 256>>>(Wk, WkH, WkL, wN4);
    conv_hl<<<wGrid, 256>>>(Wv, WvH, WvL, wN4);
    conv_hl<<<wGrid, 256>>>(Wo, WoH, WoL, wN4);
    conv_hl<<<wGrid, 256>>>(W2, W2H, W2L, wN4);

    const int aN4 = MH / 4;
    const int aGrid = (aN4 + 255) / 256;
    conv_hl<<<aGrid, 256>>>(X, XH, XL, aN4);

    const dim3 gemmGrid(HID / 64, MROWS / 128);        // (12, 32)
    const dim3 qkvGrid(HID / 64, MROWS / 128, 3);      // (12, 32, 3)
    const dim3 atGrid(SEQ / 128, BATCH * NHEAD);       // (4, 96)

    for (int l = 0; l < NLAYERS; l++) {
        const size_t wo = (size_t)l * HID * HID;
        const size_t vo = (size_t)l * HID;

        gemm_qkv<<<qkvGrid, 256, GEMM_SMEM>>>(XH, XL,
            WqH + wo, WqL + wo, bq + vo, QH, QL,
            WkH + wo, WkL + wo, bk + vo, KH, KL,
            WvH + wo, WvL + wo, bv + vo, VH, VL);

        attn_fused<<<atGrid, 256, ATT_SMEM>>>(QH, QL, KH, KL, VH, VL, CH, CL);

        gemm_mma<false, true, false><<<gemmGrid, 256, GEMM_SMEM>>>(CH, CL, WoH + wo, WoL + wo, bo + vo, T1, nullptr, nullptr);
        add_ln_kernel<<<MROWS, 256>>>(X, T1, g1 + vo, be1 + vo, T2, TH, TL);

        gemm_mma<true, false, true><<<gemmGrid, 256, GEMM_SMEM>>>(TH, TL, W2H + wo, W2L + wo, b2 + vo, nullptr, UH, UL);
        gemm_mma<true, true, false><<<gemmGrid, 256, GEMM_SMEM>>>(UH, UL, W2H + wo, W2L + wo, b2 + vo, T1, nullptr, nullptr);
        add_ln_kernel<<<MROWS, 256>>>(T2, T1, g2 + vo, be2 + vo, X, XH, XL);
    }

    cudaMemcpyAsync(d_out, X, (size_t)MH * sizeof(float), cudaMemcpyDeviceToDevice);
}

// round 17
// speedup vs baseline: 3.1936x; 1.0082x over previous
#include <cuda_runtime.h>
#include <cuda_bf16.h>
#include <math.h>
#include <stdint.h>

// Problem constants
#define NLAYERS 12
#define BATCH   8
#define SEQ     512
#define HID     768
#define NHEAD   12
#define HDIM    64
#define MROWS   (BATCH * SEQ)      // 4096
#define MH      (MROWS * HID)
#define WELEMS  (NLAYERS * HID * HID)

// fp32 scratch
__device__ float g_X[MH];
__device__ float g_T1[MH];
__device__ float g_T2[MH];

// bf16 hi/lo scratch (activations)
__device__ __nv_bfloat16 g_XH[MH],  g_XL[MH];
__device__ __nv_bfloat16 g_QH[MH],  g_QL[MH];
__device__ __nv_bfloat16 g_KH[MH],  g_KL[MH];
__device__ __nv_bfloat16 g_VH[MH],  g_VL[MH];
__device__ __nv_bfloat16 g_CH[MH],  g_CL[MH];
__device__ __nv_bfloat16 g_TH[MH],  g_TL[MH];
__device__ __nv_bfloat16 g_UH[MH],  g_UL[MH];

// bf16 hi/lo weights
__device__ __nv_bfloat16 g_WqH[WELEMS], g_WqL[WELEMS];
__device__ __nv_bfloat16 g_WkH[WELEMS], g_WkL[WELEMS];
__device__ __nv_bfloat16 g_WvH[WELEMS], g_WvL[WELEMS];
__device__ __nv_bfloat16 g_WoH[WELEMS], g_WoL[WELEMS];
__device__ __nv_bfloat16 g_W2H[WELEMS], g_W2L[WELEMS];

// ---------------------------------------------------------------------------
// helpers
// ---------------------------------------------------------------------------
__device__ __forceinline__ uint32_t smem_u32(const void* p) {
    uint32_t a;
    asm("{ .reg .u64 t; cvta.to.shared.u64 t, %1; cvt.u32.u64 %0, t; }"
        : "=r"(a) : "l"(p));
    return a;
}

#define LDSM_X4(r, addr) \
    asm volatile("ldmatrix.sync.aligned.m8n8.x4.shared.b16 {%0,%1,%2,%3}, [%4];" \
        : "=r"((r)[0]), "=r"((r)[1]), "=r"((r)[2]), "=r"((r)[3]) : "r"(addr))

#define LDSM_X4_T(r, addr) \
    asm volatile("ldmatrix.sync.aligned.m8n8.x4.trans.shared.b16 {%0,%1,%2,%3}, [%4];" \
        : "=r"((r)[0]), "=r"((r)[1]), "=r"((r)[2]), "=r"((r)[3]) : "r"(addr))

#define MMA_BF16(d, a, b0, b1) \
    asm volatile("mma.sync.aligned.m16n8k16.row.col.f32.bf16.bf16.f32 " \
        "{%0,%1,%2,%3}, {%4,%5,%6,%7}, {%8,%9}, {%0,%1,%2,%3};" \
        : "+f"((d)[0]), "+f"((d)[1]), "+f"((d)[2]), "+f"((d)[3]) \
        : "r"((a)[0]), "r"((a)[1]), "r"((a)[2]), "r"((a)[3]), "r"(b0), "r"(b1))

#define CP_ASYNC16(dst, src) \
    asm volatile("cp.async.ca.shared.global [%0], [%1], 16;" :: "r"(dst), "l"(src))
#define CP_COMMIT() asm volatile("cp.async.commit_group;" ::: "memory")
#define CP_WAIT(n)  asm volatile("cp.async.wait_group %0;" :: "n"(n) : "memory")

__device__ __forceinline__ void split_hl(float v, __nv_bfloat16& h, __nv_bfloat16& l) {
    h = __float2bfloat16(v);
    l = __float2bfloat16(v - __bfloat162float(h));
}

__device__ __forceinline__ float ex2_approx(float x) {
    float y;
    asm("ex2.approx.f32 %0, %1;" : "=f"(y) : "f"(x));
    return y;
}

__device__ __forceinline__ uint32_t pack_bf2(float a, float b) {
    __nv_bfloat162 p = __halves2bfloat162(__float2bfloat16(a), __float2bfloat16(b));
    return *reinterpret_cast<uint32_t*>(&p);
}

// ---------------------------------------------------------------------------
// fp32 -> bf16 hi/lo conversion (2 float4 per thread for MLP)
// ---------------------------------------------------------------------------
__global__ __launch_bounds__(256)
void conv_hl(const float* __restrict__ s,
             __nv_bfloat16* __restrict__ h,
             __nv_bfloat16* __restrict__ l,
             int n4) {
    const int i0 = (blockIdx.x * 256 + threadIdx.x) * 2;
    if (i0 >= n4) return;
    float4 v0 = reinterpret_cast<const float4*>(s)[i0];
    float4 v1 = reinterpret_cast<const float4*>(s)[i0 + 1];
    __nv_bfloat16 h0, h1, h2, h3, h4, h5, h6, h7;
    __nv_bfloat16 l0, l1, l2, l3, l4, l5, l6, l7;
    split_hl(v0.x, h0, l0); split_hl(v0.y, h1, l1);
    split_hl(v0.z, h2, l2); split_hl(v0.w, h3, l3);
    split_hl(v1.x, h4, l4); split_hl(v1.y, h5, l5);
    split_hl(v1.z, h6, l6); split_hl(v1.w, h7, l7);
    __nv_bfloat162* hp = reinterpret_cast<__nv_bfloat162*>(h) + 2 * i0;
    __nv_bfloat162* lp = reinterpret_cast<__nv_bfloat162*>(l) + 2 * i0;
    hp[0] = __halves2bfloat162(h0, h1);
    hp[1] = __halves2bfloat162(h2, h3);
    hp[2] = __halves2bfloat162(h4, h5);
    hp[3] = __halves2bfloat162(h6, h7);
    lp[0] = __halves2bfloat162(l0, l1);
    lp[1] = __halves2bfloat162(l2, l3);
    lp[2] = __halves2bfloat162(l4, l5);
    lp[3] = __halves2bfloat162(l6, l7);
}

// ---------------------------------------------------------------------------
// bf16 split-precision GEMM body, 3-stage cp.async pipeline, ONE sync/iter.
// BM=128, BN=64, BK=32, 8 warps (4x2), warp 32x32. 3-product hi/lo,
// product-major MMA issue order.
// ---------------------------------------------------------------------------
#define G_AH(st) ((st) * 10240)
#define G_AL(st) (30720 + (st) * 10240)
#define G_BH(st) (61440 + (st) * 4608)
#define G_BL(st) (75264 + (st) * 4608)
#define GEMM_SMEM 89088

template <bool RELU, bool OUTF, bool OUTH>
__device__ __forceinline__
void gemm_body(uint32_t sb,
               const __nv_bfloat16* __restrict__ Ah,
               const __nv_bfloat16* __restrict__ Al,
               const __nv_bfloat16* __restrict__ Wh,
               const __nv_bfloat16* __restrict__ Wl,
               const float* __restrict__ bias,
               float* __restrict__ C,
               __nv_bfloat16* __restrict__ Ch,
               __nv_bfloat16* __restrict__ Cl,
               int blockRow, int blockCol) {
    const int tid = threadIdx.x;
    const int wid = tid >> 5;
    const int lane = tid & 31;
    const int wm = (wid & 3) * 32;
    const int wn = (wid >> 2) * 32;

    float acc[2][4][4];
#pragma unroll
    for (int i = 0; i < 2; i++)
#pragma unroll
        for (int j = 0; j < 4; j++)
#pragma unroll
            for (int q = 0; q < 4; q++) acc[i][j][q] = 0.0f;

    const int arow = tid >> 1;
    const int ahalf = tid & 1;
    const int bk = tid >> 3;
    const int bj = tid & 7;

    const uint32_t aso = (uint32_t)(arow * 80 + ahalf * 32);
    const uint32_t bso = (uint32_t)(bk * 144 + bj * 16);

    const uint32_t aoff = (uint32_t)((wm + (lane & 15)) * 80 + (lane >> 4) * 16);
    const uint32_t boff = (uint32_t)(((lane & 7) + ((lane >> 3) & 1) * 8) * 144
                                     + (wn + (lane >> 4) * 8) * 2);

    const int NT = HID / 32;  // 24

    auto issue_tile = [&](int t, int st) {
        const size_t ga = (size_t)(blockRow + arow) * HID + t * 32 + ahalf * 16;
        const size_t gb = (size_t)(t * 32 + bk) * HID + blockCol + bj * 8;
        CP_ASYNC16(sb + G_AH(st) + aso,      Ah + ga);
        CP_ASYNC16(sb + G_AH(st) + aso + 16, Ah + ga + 8);
        CP_ASYNC16(sb + G_AL(st) + aso,      Al + ga);
        CP_ASYNC16(sb + G_AL(st) + aso + 16, Al + ga + 8);
        CP_ASYNC16(sb + G_BH(st) + bso, Wh + gb);
        CP_ASYNC16(sb + G_BL(st) + bso, Wl + gb);
    };

    issue_tile(0, 0); CP_COMMIT();
    issue_tile(1, 1); CP_COMMIT();

    int st = 0;      // stage of tile kt
    int pst = 2;     // stage where tile kt+2 goes
    for (int kt = 0; kt < NT; kt++) {
        // wait for tile kt, single sync, then prefetch kt+2 (safe: the sync
        // orders all warps past compute(kt-1), which ran on stage pst)
        if (kt < NT - 1) { CP_WAIT(1); } else { CP_WAIT(0); }
        __syncthreads();
        if (kt + 2 < NT) {
            issue_tile(kt + 2, pst);
            CP_COMMIT();
        }

        const uint32_t sAh = sb + G_AH(st);
        const uint32_t sAl = sb + G_AL(st);
        const uint32_t sBh = sb + G_BH(st);
        const uint32_t sBl = sb + G_BL(st);
#pragma unroll
        for (int ks = 0; ks < 2; ks++) {
            uint32_t ah[2][4], al[2][4], bh[2][4], bl[2][4];
#pragma unroll
            for (int mi = 0; mi < 2; mi++) {
                LDSM_X4(ah[mi], sAh + aoff + mi * 16 * 80 + ks * 32);
                LDSM_X4(al[mi], sAl + aoff + mi * 16 * 80 + ks * 32);
            }
#pragma unroll
            for (int ni = 0; ni < 2; ni++) {
                LDSM_X4_T(bh[ni], sBh + boff + ks * 16 * 144 + ni * 32);
                LDSM_X4_T(bl[ni], sBl + boff + ks * 16 * 144 + ni * 32);
            }
            // product-major order: 16-acc reuse distance
#pragma unroll
            for (int mi = 0; mi < 2; mi++)
#pragma unroll
                for (int nt = 0; nt < 4; nt++) {
                    const int ni = nt >> 1;
                    const int sel = (nt & 1) * 2;
                    MMA_BF16(acc[mi][nt], ah[mi], bh[ni][sel], bh[ni][sel + 1]);
                }
#pragma unroll
            for (int mi = 0; mi < 2; mi++)
#pragma unroll
                for (int nt = 0; nt < 4; nt++) {
                    const int ni = nt >> 1;
                    const int sel = (nt & 1) * 2;
                    MMA_BF16(acc[mi][nt], ah[mi], bl[ni][sel], bl[ni][sel + 1]);
                }
#pragma unroll
            for (int mi = 0; mi < 2; mi++)
#pragma unroll
                for (int nt = 0; nt < 4; nt++) {
                    const int ni = nt >> 1;
                    const int sel = (nt & 1) * 2;
                    MMA_BF16(acc[mi][nt], al[mi], bh[ni][sel], bh[ni][sel + 1]);
                }
        }
        st = (st == 2) ? 0 : st + 1;
        pst = (pst == 2) ? 0 : pst + 1;
    }

#pragma unroll
    for (int mi = 0; mi < 2; mi++) {
#pragma unroll
        for (int nt = 0; nt < 4; nt++) {
            const int col = blockCol + wn + nt * 8 + (lane & 3) * 2;
            const float2 bv = *reinterpret_cast<const float2*>(bias + col);
            const int r0 = blockRow + wm + mi * 16 + (lane >> 2);
            float2 o0 = {acc[mi][nt][0] + bv.x, acc[mi][nt][1] + bv.y};
            float2 o1 = {acc[mi][nt][2] + bv.x, acc[mi][nt][3] + bv.y};
            if (RELU) {
                o0.x = fmaxf(o0.x, 0.f); o0.y = fmaxf(o0.y, 0.f);
                o1.x = fmaxf(o1.x, 0.f); o1.y = fmaxf(o1.y, 0.f);
            }
            if (OUTF) {
                *reinterpret_cast<float2*>(C + (size_t)r0 * HID + col)       = o0;
                *reinterpret_cast<float2*>(C + (size_t)(r0 + 8) * HID + col) = o1;
            }
            if (OUTH) {
                __nv_bfloat16 h0, h1, l0, l1;
                split_hl(o0.x, h0, l0); split_hl(o0.y, h1, l1);
                *reinterpret_cast<__nv_bfloat162*>(Ch + (size_t)r0 * HID + col) = __halves2bfloat162(h0, h1);
                *reinterpret_cast<__nv_bfloat162*>(Cl + (size_t)r0 * HID + col) = __halves2bfloat162(l0, l1);
                split_hl(o1.x, h0, l0); split_hl(o1.y, h1, l1);
                *reinterpret_cast<__nv_bfloat162*>(Ch + (size_t)(r0 + 8) * HID + col) = __halves2bfloat162(h0, h1);
                *reinterpret_cast<__nv_bfloat162*>(Cl + (size_t)(r0 + 8) * HID + col) = __halves2bfloat162(l0, l1);
            }
        }
    }
}

template <bool RELU, bool OUTF, bool OUTH>
__global__ __launch_bounds__(256)
void gemm_mma(const __nv_bfloat16* __restrict__ Ah,
              const __nv_bfloat16* __restrict__ Al,
              const __nv_bfloat16* __restrict__ Wh,
              const __nv_bfloat16* __restrict__ Wl,
              const float* __restrict__ bias,
              float* __restrict__ C,
              __nv_bfloat16* __restrict__ Ch,
              __nv_bfloat16* __restrict__ Cl) {
    extern __shared__ char dynsm[];
    gemm_body<RELU, OUTF, OUTH>(smem_u32(dynsm), Ah, Al, Wh, Wl, bias,
                                C, Ch, Cl, blockIdx.y * 128, blockIdx.x * 64);
}

// Fused Q/K/V: one launch, gridDim.z selects projection.
__global__ __launch_bounds__(256)
void gemm_qkv(const __nv_bfloat16* __restrict__ Ah,
              const __nv_bfloat16* __restrict__ Al,
              const __nv_bfloat16* __restrict__ WqH, const __nv_bfloat16* __restrict__ WqL,
              const float* __restrict__ bq,
              __nv_bfloat16* __restrict__ QH, __nv_bfloat16* __restrict__ QL,
              const __nv_bfloat16* __restrict__ WkH, const __nv_bfloat16* __restrict__ WkL,
              const float* __restrict__ bk,
              __nv_bfloat16* __restrict__ KH, __nv_bfloat16* __restrict__ KL,
              const __nv_bfloat16* __restrict__ WvH, const __nv_bfloat16* __restrict__ WvL,
              const float* __restrict__ bv,
              __nv_bfloat16* __restrict__ VH, __nv_bfloat16* __restrict__ VL) {
    extern __shared__ char dynsm[];
    const __nv_bfloat16 *Wh, *Wl;
    const float* bias;
    __nv_bfloat16 *Ch, *Cl;
    if (blockIdx.z == 0)      { Wh = WqH; Wl = WqL; bias = bq; Ch = QH; Cl = QL; }
    else if (blockIdx.z == 1) { Wh = WkH; Wl = WkL; bias = bk; Ch = KH; Cl = KL; }
    else                      { Wh = WvH; Wl = WvL; bias = bv; Ch = VH; Cl = VL; }
    gemm_body<false, false, true>(smem_u32(dynsm), Ah, Al, Wh, Wl, bias,
                                  nullptr, Ch, Cl, blockIdx.y * 128, blockIdx.x * 64);
}

// ---------------------------------------------------------------------------
// Fused attention, single sync per tile.
// ---------------------------------------------------------------------------
#define AT_QH 0
#define AT_QL 18432
#define AT_KH(s) (36864 + (s) * 18432)
#define AT_KL(s) (46080 + (s) * 18432)
#define AT_VH(s) (73728 + (s) * 18432)
#define AT_VL(s) (82944 + (s) * 18432)
#define ATT_SMEM 110592
#define EXP_SCL 0.18033688f   // 0.125 * log2(e)

__global__ __launch_bounds__(256)
void attn_fused(const __nv_bfloat16* __restrict__ Qh,
                const __nv_bfloat16* __restrict__ Ql,
                const __nv_bfloat16* __restrict__ Kh,
                const __nv_bfloat16* __restrict__ Kl,
                const __nv_bfloat16* __restrict__ Vh,
                const __nv_bfloat16* __restrict__ Vl,
                __nv_bfloat16* __restrict__ Ch,
                __nv_bfloat16* __restrict__ Cl) {
    extern __shared__ char dynsm[];
    const uint32_t sb = smem_u32(dynsm);

    const int bh = blockIdx.y;
    const int b = bh / NHEAD, h = bh % NHEAD;
    const int q0 = blockIdx.x * 128;

    const __nv_bfloat16* Qhp = Qh + (size_t)(b * SEQ) * HID + h * HDIM;
    const __nv_bfloat16* Qlp = Ql + (size_t)(b * SEQ) * HID + h * HDIM;
    const __nv_bfloat16* Khp = Kh + (size_t)(b * SEQ) * HID + h * HDIM;
    const __nv_bfloat16* Klp = Kl + (size_t)(b * SEQ) * HID + h * HDIM;
    const __nv_bfloat16* Vhp = Vh + (size_t)(b * SEQ) * HID + h * HDIM;
    const __nv_bfloat16* Vlp = Vl + (size_t)(b * SEQ) * HID + h * HDIM;
    __nv_bfloat16* Chp = Ch + (size_t)(b * SEQ) * HID + h * HDIM;
    __nv_bfloat16* Clp = Cl + (size_t)(b * SEQ) * HID + h * HDIM;

    const int tid = threadIdx.x;
    const int wid = tid >> 5;
    const int lane = tid & 31;
    const int wrow = wid * 16;

    const int qrow = tid >> 1;
    const int kvrow = tid >> 2;

    {
#pragma unroll
        for (int j = 0; j < 4; j++) {
            const int seg = (tid & 1) * 4 + j;
            const size_t g = (size_t)(q0 + qrow) * HID + seg * 8;
            const uint32_t d = (uint32_t)(qrow * 144 + seg * 16);
            CP_ASYNC16(sb + AT_QH + d, Qhp + g);
            CP_ASYNC16(sb + AT_QL + d, Qlp + g);
        }
#pragma unroll
        for (int j = 0; j < 2; j++) {
            const int seg = (tid & 3) * 2 + j;
            const size_t g = (size_t)kvrow * HID + seg * 8;
            const uint32_t d = (uint32_t)(kvrow * 144 + seg * 16);
            CP_ASYNC16(sb + AT_KH(0) + d, Khp + g);
            CP_ASYNC16(sb + AT_KL(0) + d, Klp + g);
            CP_ASYNC16(sb + AT_VH(0) + d, Vhp + g);
            CP_ASYNC16(sb + AT_VL(0) + d, Vlp + g);
        }
        CP_COMMIT();
    }

    float oacc[8][4];
#pragma unroll
    for (int i = 0; i < 8; i++)
#pragma unroll
        for (int j = 0; j < 4; j++) oacc[i][j] = 0.0f;
    float rs0 = 0.f, rs1 = 0.f;

    const uint32_t qoff = (uint32_t)((wrow + (lane & 15)) * 144 + (lane >> 4) * 16);
    const uint32_t koff = (uint32_t)((lane & 15) * 144 + (lane >> 4) * 16);
    const uint32_t voff = (uint32_t)(((lane & 7) + ((lane >> 3) & 1) * 8) * 144
                                     + ((lane >> 4) * 8) * 2);

    const int NT = SEQ / 64;

    for (int ts = 0; ts < NT; ts++) {
        const int st = ts & 1;
        CP_WAIT(0);
        __syncthreads();
        if (ts + 1 < NT) {
            const int ns = st ^ 1;
#pragma unroll
            for (int j = 0; j < 2; j++) {
                const int seg = (tid & 3) * 2 + j;
                const size_t g = (size_t)((ts + 1) * 64 + kvrow) * HID + seg * 8;
                const uint32_t d = (uint32_t)(kvrow * 144 + seg * 16);
                CP_ASYNC16(sb + AT_KH(ns) + d, Khp + g);
                CP_ASYNC16(sb + AT_KL(ns) + d, Klp + g);
                CP_ASYNC16(sb + AT_VH(ns) + d, Vhp + g);
                CP_ASYNC16(sb + AT_VL(ns) + d, Vlp + g);
            }
            CP_COMMIT();
        }

        float sacc[8][4];
#pragma unroll
        for (int i = 0; i < 8; i++)
#pragma unroll
            for (int j = 0; j < 4; j++) sacc[i][j] = 0.0f;

        const uint32_t kbh = sb + AT_KH(st);
        const uint32_t kbl = sb + AT_KL(st);
#pragma unroll
        for (int ks = 0; ks < 4; ks++) {
            uint32_t qfh[4], qfl[4];
            LDSM_X4(qfh, sb + AT_QH + qoff + ks * 32);
            LDSM_X4(qfl, sb + AT_QL + qoff + ks * 32);
            uint32_t kfh[4][4], kfl[4][4];
#pragma unroll
            for (int g = 0; g < 4; g++) {
                LDSM_X4(kfh[g], kbh + koff + g * 16 * 144 + ks * 32);
                LDSM_X4(kfl[g], kbl + koff + g * 16 * 144 + ks * 32);
            }
#pragma unroll
            for (int nt = 0; nt < 8; nt++) {
                const int g = nt >> 1;
                const int sel = nt & 1;
                MMA_BF16(sacc[nt], qfh, kfh[g][sel], kfh[g][sel + 2]);
            }
#pragma unroll
            for (int nt = 0; nt < 8; nt++) {
                const int g = nt >> 1;
                const int sel = nt & 1;
                MMA_BF16(sacc[nt], qfh, kfl[g][sel], kfl[g][sel + 2]);
            }
#pragma unroll
            for (int nt = 0; nt < 8; nt++) {
                const int g = nt >> 1;
                const int sel = nt & 1;
                MMA_BF16(sacc[nt], qfl, kfh[g][sel], kfh[g][sel + 2]);
            }
        }

#pragma unroll
        for (int nt = 0; nt < 8; nt++) {
            const float e0 = ex2_approx(sacc[nt][0] * EXP_SCL);
            const float e1 = ex2_approx(sacc[nt][1] * EXP_SCL);
            const float e2 = ex2_approx(sacc[nt][2] * EXP_SCL);
            const float e3 = ex2_approx(sacc[nt][3] * EXP_SCL);
            sacc[nt][0] = e0; sacc[nt][1] = e1;
            sacc[nt][2] = e2; sacc[nt][3] = e3;
            rs0 += e0 + e1;
            rs1 += e2 + e3;
        }

        uint32_t pf[4][4];
#pragma unroll
        for (int j = 0; j < 4; j++) {
            pf[j][0] = pack_bf2(sacc[2 * j][0],     sacc[2 * j][1]);
            pf[j][1] = pack_bf2(sacc[2 * j][2],     sacc[2 * j][3]);
            pf[j][2] = pack_bf2(sacc[2 * j + 1][0], sacc[2 * j + 1][1]);
            pf[j][3] = pack_bf2(sacc[2 * j + 1][2], sacc[2 * j + 1][3]);
        }

        const uint32_t vbh = sb + AT_VH(st);
        const uint32_t vbl = sb + AT_VL(st);
#pragma unroll
        for (int ks = 0; ks < 4; ks++) {
            uint32_t vfh[4][4], vfl[4][4];
#pragma unroll
            for (int ni = 0; ni < 4; ni++) {
                LDSM_X4_T(vfh[ni], vbh + voff + ks * 16 * 144 + ni * 32);
                LDSM_X4_T(vfl[ni], vbl + voff + ks * 16 * 144 + ni * 32);
            }
#pragma unroll
            for (int nt = 0; nt < 8; nt++) {
                const int ni = nt >> 1;
                const int sel = (nt & 1) * 2;
                MMA_BF16(oacc[nt], pf[ks], vfh[ni][sel], vfh[ni][sel + 1]);
            }
#pragma unroll
            for (int nt = 0; nt < 8; nt++) {
                const int ni = nt >> 1;
                const int sel = (nt & 1) * 2;
                MMA_BF16(oacc[nt], pf[ks], vfl[ni][sel], vfl[ni][sel + 1]);
            }
        }
    }

    rs0 += __shfl_xor_sync(0xffffffffu, rs0, 1);
    rs0 += __shfl_xor_sync(0xffffffffu, rs0, 2);
    rs1 += __shfl_xor_sync(0xffffffffu, rs1, 1);
    rs1 += __shfl_xor_sync(0xffffffffu, rs1, 2);
    const float inv0 = 1.0f / rs0;
    const float inv1 = 1.0f / rs1;

    const int r0 = q0 + wrow + (lane >> 2);
#pragma unroll
    for (int nt = 0; nt < 8; nt++) {
        const int col = nt * 8 + (lane & 3) * 2;
        __nv_bfloat16 h0, h1, l0, l1;
        split_hl(oacc[nt][0] * inv0, h0, l0);
        split_hl(oacc[nt][1] * inv0, h1, l1);
        *reinterpret_cast<__nv_bfloat162*>(Chp + (size_t)r0 * HID + col) = __halves2bfloat162(h0, h1);
        *reinterpret_cast<__nv_bfloat162*>(Clp + (size_t)r0 * HID + col) = __halves2bfloat162(l0, l1);
        split_hl(oacc[nt][2] * inv1, h0, l0);
        split_hl(oacc[nt][3] * inv1, h1, l1);
        *reinterpret_cast<__nv_bfloat162*>(Chp + (size_t)(r0 + 8) * HID + col) = __halves2bfloat162(h0, h1);
        *reinterpret_cast<__nv_bfloat162*>(Clp + (size_t)(r0 + 8) * HID + col) = __halves2bfloat162(l0, l1);
    }
}

// ---------------------------------------------------------------------------
// Add + LayerNorm -> fp32 out (+ optional bf16 hi/lo out)
// ---------------------------------------------------------------------------
template <bool OUTHL>
__global__ __launch_bounds__(256)
void add_ln_kernel(const float* __restrict__ X,
                   const float* __restrict__ Y,
                   const float* __restrict__ g,
                   const float* __restrict__ b,
                   float* __restrict__ O,
                   __nv_bfloat16* __restrict__ Oh,
                   __nv_bfloat16* __restrict__ Ol) {
    const int row = blockIdx.x;
    const float* xr = X + (size_t)row * HID;
    const float* yr = Y + (size_t)row * HID;
    float* orow = O + (size_t)row * HID;
    __nv_bfloat16* ohr = Oh + (size_t)row * HID;
    __nv_bfloat16* olr = Ol + (size_t)row * HID;
    const int tid = threadIdx.x;

    float vals[3];
    float s = 0.f, ss = 0.f;
#pragma unroll
    for (int t = 0; t < 3; t++) {
        const int c = tid + t * 256;
        float v = xr[c] + yr[c];
        vals[t] = v;
        s += v;
        ss += v * v;
    }

    __shared__ float rs[256];
    __shared__ float rss[256];
    rs[tid] = s;
    rss[tid] = ss;
    __syncthreads();
#pragma unroll
    for (int st = 128; st > 0; st >>= 1) {
        if (tid < st) {
            rs[tid] += rs[tid + st];
            rss[tid] += rss[tid + st];
        }
        __syncthreads();
    }
    const float mean = rs[0] * (1.0f / HID);
    const float var = rss[0] * (1.0f / HID) - mean * mean;
    const float inv = rsqrtf(var + 1e-12f);

#pragma unroll
    for (int t = 0; t < 3; t++) {
        const int c = tid + t * 256;
        const float o = (vals[t] - mean) * inv * g[c] + b[c];
        orow[c] = o;
        if (OUTHL) {
            __nv_bfloat16 h, l;
            split_hl(o, h, l);
            ohr[c] = h;
            olr[c] = l;
        }
    }
}

// ---------------------------------------------------------------------------
// Launch
// ---------------------------------------------------------------------------
extern "C" void kernel_launch(void* const* d_in, const int* in_sizes, int n_in,
                              void* d_out, int out_size) {
    const float* x    = (const float*)d_in[0];
    const float* Wq   = (const float*)d_in[1];
    const float* bq   = (const float*)d_in[2];
    const float* Wk   = (const float*)d_in[3];
    const float* bk   = (const float*)d_in[4];
    const float* Wv   = (const float*)d_in[5];
    const float* bv   = (const float*)d_in[6];
    const float* Wo   = (const float*)d_in[7];
    const float* bo   = (const float*)d_in[8];
    const float* g1   = (const float*)d_in[9];
    const float* be1  = (const float*)d_in[10];
    const float* W2   = (const float*)d_in[11];
    const float* b2   = (const float*)d_in[12];
    const float* g2   = (const float*)d_in[13];
    const float* be2  = (const float*)d_in[14];

    float *X, *T1, *T2;
    cudaGetSymbolAddress((void**)&X,  g_X);
    cudaGetSymbolAddress((void**)&T1, g_T1);
    cudaGetSymbolAddress((void**)&T2, g_T2);

    __nv_bfloat16 *XH, *XL, *QH, *QL, *KH, *KL, *VH, *VL, *CH, *CL, *TH, *TL, *UH, *UL;
    cudaGetSymbolAddress((void**)&XH, g_XH); cudaGetSymbolAddress((void**)&XL, g_XL);
    cudaGetSymbolAddress((void**)&QH, g_QH); cudaGetSymbolAddress((void**)&QL, g_QL);
    cudaGetSymbolAddress((void**)&KH, g_KH); cudaGetSymbolAddress((void**)&KL, g_KL);
    cudaGetSymbolAddress((void**)&VH, g_VH); cudaGetSymbolAddress((void**)&VL, g_VL);
    cudaGetSymbolAddress((void**)&CH, g_CH); cudaGetSymbolAddress((void**)&CL, g_CL);
    cudaGetSymbolAddress((void**)&TH, g_TH); cudaGetSymbolAddress((void**)&TL, g_TL);
    cudaGetSymbolAddress((void**)&UH, g_UH); cudaGetSymbolAddress((void**)&UL, g_UL);

    __nv_bfloat16 *WqH, *WqL, *WkH, *WkL, *WvH, *WvL, *WoH, *WoL, *W2H, *W2L;
    cudaGetSymbolAddress((void**)&WqH, g_WqH); cudaGetSymbolAddress((void**)&WqL, g_WqL);
    cudaGetSymbolAddress((void**)&WkH, g_WkH); cudaGetSymbolAddress((void**)&WkL, g_WkL);
    cudaGetSymbolAddress((void**)&WvH, g_WvH); cudaGetSymbolAddress((void**)&WvL, g_WvL);
    cudaGetSymbolAddress((void**)&WoH, g_WoH); cudaGetSymbolAddress((void**)&WoL, g_WoL);
    cudaGetSymbolAddress((void**)&W2H, g_W2H); cudaGetSymbolAddress((void**)&W2L, g_W2L);

    cudaFuncSetAttribute(gemm_mma<false, true, false>, cudaFuncAttributeMaxDynamicSharedMemorySize, GEMM_SMEM);
    cudaFuncSetAttribute(gemm_mma<true, false, true>,  cudaFuncAttributeMaxDynamicSharedMemorySize, GEMM_SMEM);
    cudaFuncSetAttribute(gemm_mma<true, true, false>,  cudaFuncAttributeMaxDynamicSharedMemorySize, GEMM_SMEM);
    cudaFuncSetAttribute(gemm_qkv, cudaFuncAttributeMaxDynamicSharedMemorySize, GEMM_SMEM);
    cudaFuncSetAttribute(attn_fused, cudaFuncAttributeMaxDynamicSharedMemorySize, ATT_SMEM);

    // weight conversion (2 float4 per thread)
    const int wN4 = WELEMS / 4;
    const int wGrid = (wN4 / 2 + 255) / 256;
    conv_hl<<<wGrid, 256>>>(Wq, WqH, WqL, wN4);
    conv_hl<<<wGrid, 256>>>(Wk, WkH, WkL, wN4);
    conv_hl<<<wGrid, 256>>>(Wv, WvH, WvL, wN4);
    conv_hl<<<wGrid, 256>>>(Wo, WoH, WoL, wN4);
    conv_hl<<<wGrid, 256>>>(W2, W2H, W2L, wN4);

    // initial activation conversion straight from harness input (no X copy)
    const int aN4 = MH / 4;
    const int aGrid = (aN4 / 2 + 255) / 256;
    conv_hl<<<aGrid, 256>>>(x, XH, XL, aN4);

    const dim3 gemmGrid(HID / 64, MROWS / 128);        // (12, 32)
    const dim3 qkvGrid(HID / 64, MROWS / 128, 3);      // (12, 32, 3)
    const dim3 atGrid(SEQ / 128, BATCH * NHEAD);       // (4, 96)

    for (int l = 0; l < NLAYERS; l++) {
        const size_t wo = (size_t)l * HID * HID;
        const size_t vo = (size_t)l * HID;
        const float* Xres = (l == 0) ? x : X;

        gemm_qkv<<<qkvGrid, 256, GEMM_SMEM>>>(XH, XL,
            WqH + wo, WqL + wo, bq + vo, QH, QL,
            WkH + wo, WkL + wo, bk + vo, KH, KL,
            WvH + wo, WvL + wo, bv + vo, VH, VL);

        attn_fused<<<atGrid, 256, ATT_SMEM>>>(QH, QL, KH, KL, VH, VL, CH, CL);

        gemm_mma<false, true, false><<<gemmGrid, 256, GEMM_SMEM>>>(CH, CL, WoH + wo, WoL + wo, bo + vo, T1, nullptr, nullptr);
        add_ln_kernel<true><<<MROWS, 256>>>(Xres, T1, g1 + vo, be1 + vo, T2, TH, TL);

        gemm_mma<true, false, true><<<gemmGrid, 256, GEMM_SMEM>>>(TH, TL, W2H + wo, W2L + wo, b2 + vo, nullptr, UH, UL);
        gemm_mma<true, true, false><<<gemmGrid, 256, GEMM_SMEM>>>(UH, UL, W2H + wo, W2L + wo, b2 + vo, T1, nullptr, nullptr);

        if (l < NLAYERS - 1) {
            add_ln_kernel<true><<<MROWS, 256>>>(T2, T1, g2 + vo, be2 + vo, X, XH, XL);
        } else {
            // last layer: write final output directly to d_out, skip hi/lo
            add_ln_kernel<false><<<MROWS, 256>>>(T2, T1, g2 + vo, be2 + vo,
                                                 (float*)d_out, XH, XL);
        }
    }
}